// round 1
// baseline (speedup 1.0000x reference)
#include <cuda_runtime.h>
#include <cuda_bf16.h>
#include <cstdint>

#define GCN_N     100000
#define GCN_NNZ   3200000
#define GCN_SLOPE 0.25f

// ---------------- device scratch (static, allocation-free) ----------------
__device__ int   g_rowptr[GCN_N + 1];
__device__ int   g_cursor[GCN_N];          // also used as counts
__device__ int   g_scol[GCN_NNZ];
__device__ float g_sval[GCN_NNZ];
__device__ float g_sup [GCN_N * 256];
__device__ float g_hbuf[GCN_N * 256];

// ---------------- CSR build ----------------
__global__ void zero_kernel(int* p, int n) {
    int i = blockIdx.x * blockDim.x + threadIdx.x;
    if (i < n) p[i] = 0;
}

__global__ void hist_kernel(const int* __restrict__ rows, int* __restrict__ counts, int nnz) {
    int i = blockIdx.x * blockDim.x + threadIdx.x;
    if (i < nnz) atomicAdd(&counts[rows[i]], 1);
}

// single-block sequential chunked exclusive scan: rowptr[0]=0, rowptr[i+1]=incl(counts[0..i])
__global__ void scan_kernel(const int* __restrict__ counts, int* __restrict__ rowptr, int n) {
    __shared__ int wsum[32];
    int lane = threadIdx.x & 31;
    int wid  = threadIdx.x >> 5;
    int offset = 0;
    if (threadIdx.x == 0) rowptr[0] = 0;
    for (int base = 0; base < n; base += 1024) {
        int i = base + threadIdx.x;
        int v = (i < n) ? counts[i] : 0;
        int x = v;
        #pragma unroll
        for (int d = 1; d < 32; d <<= 1) {
            int y = __shfl_up_sync(0xffffffffu, x, d);
            if (lane >= d) x += y;
        }
        if (lane == 31) wsum[wid] = x;
        __syncthreads();
        if (wid == 0) {
            int t = wsum[lane];
            #pragma unroll
            for (int d = 1; d < 32; d <<= 1) {
                int y = __shfl_up_sync(0xffffffffu, t, d);
                if (lane >= d) t += y;
            }
            wsum[lane] = t;
        }
        __syncthreads();
        int incl = x + (wid > 0 ? wsum[wid - 1] : 0);
        if (i < n) rowptr[i + 1] = offset + incl;
        offset += wsum[31];
        __syncthreads();
    }
}

__global__ void copy_kernel(const int* __restrict__ src, int* __restrict__ dst, int n) {
    int i = blockIdx.x * blockDim.x + threadIdx.x;
    if (i < n) dst[i] = src[i];
}

__global__ void scatter_kernel(const int* __restrict__ rows, const int* __restrict__ cols,
                               const float* __restrict__ vals, int* __restrict__ cursor,
                               int* __restrict__ scol, float* __restrict__ sval, int nnz) {
    int i = blockIdx.x * blockDim.x + threadIdx.x;
    if (i < nnz) {
        int r = rows[i];
        int pos = atomicAdd(&cursor[r], 1);
        scol[pos] = cols[i];
        sval[pos] = vals[i];
    }
}

// ---------------- dense GEMM: C[M,N] = A[M,K] @ B[K,N], fp32 ----------------
// 128x128 block tile, BK=16, 256 threads, 8x8 micro-tile per thread.
#define BM 128
#define BN 128
#define BK 16

__global__ __launch_bounds__(256) void gemm_kernel(const float* __restrict__ A,
                                                   const float* __restrict__ B,
                                                   float* __restrict__ C,
                                                   int M, int N, int K) {
    __shared__ float As[BK][BM];
    __shared__ float Bs[BK][BN];
    int tid = threadIdx.x;
    int m0 = blockIdx.y * BM;
    int n0 = blockIdx.x * BN;

    int tx = tid & 15;   // n dir
    int ty = tid >> 4;   // m dir
    float acc[8][8];
    #pragma unroll
    for (int i = 0; i < 8; i++)
        #pragma unroll
        for (int j = 0; j < 8; j++) acc[i][j] = 0.f;

    // A load mapping: float4 along K
    int a_kq = (tid & 3) * 4;    // k offset (0,4,8,12)
    int a_r  = tid >> 2;         // 0..63 ; rows a_r, a_r+64
    // B load mapping: float4 along N
    int b_nq = (tid & 31) * 4;   // 0..124
    int b_r  = tid >> 5;         // 0..7  ; k rows b_r, b_r+8

    for (int k0 = 0; k0 < K; k0 += BK) {
        #pragma unroll
        for (int it = 0; it < 2; it++) {
            int row = m0 + a_r + it * 64;
            float4 va = make_float4(0.f, 0.f, 0.f, 0.f);
            if (row < M) va = *(const float4*)(A + (size_t)row * K + k0 + a_kq);
            As[a_kq + 0][a_r + it * 64] = va.x;
            As[a_kq + 1][a_r + it * 64] = va.y;
            As[a_kq + 2][a_r + it * 64] = va.z;
            As[a_kq + 3][a_r + it * 64] = va.w;
        }
        #pragma unroll
        for (int it = 0; it < 2; it++) {
            int krow = b_r + it * 8;
            *(float4*)&Bs[krow][b_nq] = *(const float4*)(B + (size_t)(k0 + krow) * N + n0 + b_nq);
        }
        __syncthreads();
        #pragma unroll
        for (int k = 0; k < BK; k++) {
            float a[8], b[8];
            #pragma unroll
            for (int i = 0; i < 8; i++) a[i] = As[k][ty * 8 + i];
            #pragma unroll
            for (int j = 0; j < 8; j++) b[j] = Bs[k][tx * 8 + j];
            #pragma unroll
            for (int i = 0; i < 8; i++)
                #pragma unroll
                for (int j = 0; j < 8; j++) acc[i][j] += a[i] * b[j];
        }
        __syncthreads();
    }

    #pragma unroll
    for (int i = 0; i < 8; i++) {
        int row = m0 + ty * 8 + i;
        if (row < M) {
            #pragma unroll
            for (int j = 0; j < 8; j += 4) {
                *(float4*)(C + (size_t)row * N + n0 + tx * 8 + j) =
                    make_float4(acc[i][j], acc[i][j + 1], acc[i][j + 2], acc[i][j + 3]);
            }
        }
    }
}

// ---------------- SpMM + bias + leaky_relu (warp per row) ----------------
template <int D>
__global__ __launch_bounds__(256) void spmm_kernel(const float* __restrict__ sup,
                                                   const int* __restrict__ scol,
                                                   const float* __restrict__ sval,
                                                   const int* __restrict__ rowptr,
                                                   const float* __restrict__ bias,
                                                   float* __restrict__ out, int n) {
    int warp = (blockIdx.x * blockDim.x + threadIdx.x) >> 5;
    int lane = threadIdx.x & 31;
    if (warp >= n) return;
    int s = rowptr[warp];
    int e = rowptr[warp + 1];
    constexpr int J = D / 32;
    float acc[J];
    #pragma unroll
    for (int j = 0; j < J; j++) acc[j] = 0.f;

    int p = s;
    for (; p + 1 < e; p += 2) {
        int   c0 = __ldg(&scol[p]);
        int   c1 = __ldg(&scol[p + 1]);
        float v0 = __ldg(&sval[p]);
        float v1 = __ldg(&sval[p + 1]);
        const float* base0 = sup + (size_t)c0 * D;
        const float* base1 = sup + (size_t)c1 * D;
        #pragma unroll
        for (int j = 0; j < J; j++) {
            acc[j] += v0 * __ldg(&base0[j * 32 + lane]);
            acc[j] += v1 * __ldg(&base1[j * 32 + lane]);
        }
    }
    if (p < e) {
        int   c = __ldg(&scol[p]);
        float v = __ldg(&sval[p]);
        const float* base = sup + (size_t)c * D;
        #pragma unroll
        for (int j = 0; j < J; j++) acc[j] += v * __ldg(&base[j * 32 + lane]);
    }

    float* o = out + (size_t)warp * D;
    #pragma unroll
    for (int j = 0; j < J; j++) {
        float r = acc[j] + __ldg(&bias[j * 32 + lane]);
        o[j * 32 + lane] = (r > 0.f) ? r : GCN_SLOPE * r;
    }
}

// ---------------- launch ----------------
extern "C" void kernel_launch(void* const* d_in, const int* in_sizes, int n_in,
                              void* d_out, int out_size) {
    const float* x    = (const float*)d_in[0];
    const int*   rows = (const int*)  d_in[1];
    const int*   cols = (const int*)  d_in[2];
    const float* vals = (const float*)d_in[3];
    const float* W1   = (const float*)d_in[4];
    const float* b1   = (const float*)d_in[5];
    const float* W2   = (const float*)d_in[6];
    const float* b2   = (const float*)d_in[7];
    const float* W3   = (const float*)d_in[8];
    const float* b3   = (const float*)d_in[9];
    float* out = (float*)d_out;

    const int N = GCN_N;
    const int NNZ = GCN_NNZ;

    int *rowptr, *cursor, *scol;
    float *sval, *sup, *hbuf;
    cudaGetSymbolAddress((void**)&rowptr, g_rowptr);
    cudaGetSymbolAddress((void**)&cursor, g_cursor);
    cudaGetSymbolAddress((void**)&scol,   g_scol);
    cudaGetSymbolAddress((void**)&sval,   g_sval);
    cudaGetSymbolAddress((void**)&sup,    g_sup);
    cudaGetSymbolAddress((void**)&hbuf,   g_hbuf);

    // CSR build (rebuilt every call: deterministic work, graph-capturable)
    zero_kernel<<<(N + 255) / 256, 256>>>(cursor, N);
    hist_kernel<<<(NNZ + 255) / 256, 256>>>(rows, cursor, NNZ);
    scan_kernel<<<1, 1024>>>(cursor, rowptr, N);
    copy_kernel<<<(N + 255) / 256, 256>>>(rowptr, cursor, N);
    scatter_kernel<<<(NNZ + 255) / 256, 256>>>(rows, cols, vals, cursor, scol, sval, NNZ);

    dim3 g2(256 / BN, (N + BM - 1) / BM);
    dim3 g1(128 / BN, (N + BM - 1) / BM);
    int spmm_grid = (N + 7) / 8;  // 8 warps per 256-thread block

    // layer 1: x[100k,512] @ W1[512,256] ; spmm ; +b1 ; leaky
    gemm_kernel<<<g2, 256>>>(x, W1, sup, N, 256, 512);
    spmm_kernel<256><<<spmm_grid, 256>>>(sup, scol, sval, rowptr, b1, hbuf, N);
    // layer 2
    gemm_kernel<<<g2, 256>>>(hbuf, W2, sup, N, 256, 256);
    spmm_kernel<256><<<spmm_grid, 256>>>(sup, scol, sval, rowptr, b2, hbuf, N);
    // layer 3: -> d_out [100k,128]
    gemm_kernel<<<g1, 256>>>(hbuf, W3, sup, N, 128, 256);
    spmm_kernel<128><<<spmm_grid, 256>>>(sup, scol, sval, rowptr, b3, out, N);
}

// round 2
// speedup vs baseline: 1.0969x; 1.0969x over previous
#include <cuda_runtime.h>
#include <cuda_bf16.h>
#include <cstdint>

#define GCN_N     100000
#define GCN_NNZ   3200000
#define GCN_SLOPE 0.25f

// ---------------- device scratch (static, allocation-free) ----------------
__device__ int   g_rowptr[GCN_N + 1];
__device__ int   g_cursor[GCN_N];          // also used as counts
__device__ int   g_scol[GCN_NNZ];
__device__ float g_sval[GCN_NNZ];
__device__ float g_sup [GCN_N * 256];
__device__ float g_hbuf[GCN_N * 256];

// ---------------- f32x2 packed-FMA helpers (Blackwell FFMA2) ----------------
__device__ __forceinline__ unsigned long long pack_f32x2(float x, float y) {
    unsigned long long r;
    asm("mov.b64 %0, {%1, %2};" : "=l"(r) : "f"(x), "f"(y));
    return r;
}
__device__ __forceinline__ void fma_f32x2(unsigned long long& d,
                                          unsigned long long a,
                                          unsigned long long b) {
    asm("fma.rn.f32x2 %0, %1, %2, %0;" : "+l"(d) : "l"(a), "l"(b));
}
__device__ __forceinline__ float2 unpack_f32x2(unsigned long long v) {
    float2 r;
    asm("mov.b64 {%0, %1}, %2;" : "=f"(r.x), "=f"(r.y) : "l"(v));
    return r;
}

// ---------------- CSR build ----------------
__global__ void zero_kernel(int* p, int n) {
    int i = blockIdx.x * blockDim.x + threadIdx.x;
    if (i < n) p[i] = 0;
}

__global__ void hist_kernel(const int* __restrict__ rows, int* __restrict__ counts, int nnz) {
    int i = blockIdx.x * blockDim.x + threadIdx.x;
    if (i < nnz) atomicAdd(&counts[rows[i]], 1);
}

// single-block chunked exclusive scan: rowptr[0]=0, rowptr[i+1]=incl(counts[0..i])
__global__ void scan_kernel(const int* __restrict__ counts, int* __restrict__ rowptr, int n) {
    __shared__ int wsum[32];
    int lane = threadIdx.x & 31;
    int wid  = threadIdx.x >> 5;
    int offset = 0;
    if (threadIdx.x == 0) rowptr[0] = 0;
    for (int base = 0; base < n; base += 1024) {
        int i = base + threadIdx.x;
        int v = (i < n) ? counts[i] : 0;
        int x = v;
        #pragma unroll
        for (int d = 1; d < 32; d <<= 1) {
            int y = __shfl_up_sync(0xffffffffu, x, d);
            if (lane >= d) x += y;
        }
        if (lane == 31) wsum[wid] = x;
        __syncthreads();
        if (wid == 0) {
            int t = wsum[lane];
            #pragma unroll
            for (int d = 1; d < 32; d <<= 1) {
                int y = __shfl_up_sync(0xffffffffu, t, d);
                if (lane >= d) t += y;
            }
            wsum[lane] = t;
        }
        __syncthreads();
        int incl = x + (wid > 0 ? wsum[wid - 1] : 0);
        if (i < n) rowptr[i + 1] = offset + incl;
        offset += wsum[31];
        __syncthreads();
    }
}

__global__ void copy_kernel(const int* __restrict__ src, int* __restrict__ dst, int n) {
    int i = blockIdx.x * blockDim.x + threadIdx.x;
    if (i < n) dst[i] = src[i];
}

__global__ void scatter_kernel(const int* __restrict__ rows, const int* __restrict__ cols,
                               const float* __restrict__ vals, int* __restrict__ cursor,
                               int* __restrict__ scol, float* __restrict__ sval, int nnz) {
    int i = blockIdx.x * blockDim.x + threadIdx.x;
    if (i < nnz) {
        int r = rows[i];
        int pos = atomicAdd(&cursor[r], 1);
        scol[pos] = cols[i];
        sval[pos] = vals[i];
    }
}

// ---------------- dense GEMM: C[M,N] = A[M,K] @ B[K,N], fp32 via FFMA2 -------
// 128x128 block tile, BK=16, 256 threads, 8x8 micro-tile per thread.
#define BM 128
#define BN 128
#define BK 16

__global__ __launch_bounds__(256) void gemm_kernel(const float* __restrict__ A,
                                                   const float* __restrict__ B,
                                                   float* __restrict__ C,
                                                   int M, int N, int K) {
    __shared__ float As[BK][BM];
    __shared__ float Bs[BK][BN];
    int tid = threadIdx.x;
    int m0 = blockIdx.y * BM;
    int n0 = blockIdx.x * BN;

    int tx = tid & 15;   // n dir
    int ty = tid >> 4;   // m dir

    // acc[i][jp] holds C pair (n = 2*jp, 2*jp+1) for row i of the 8x8 micro-tile
    unsigned long long acc[8][4];
    #pragma unroll
    for (int i = 0; i < 8; i++)
        #pragma unroll
        for (int j = 0; j < 4; j++) acc[i][j] = 0ull;

    // A load mapping: float4 along K
    int a_kq = (tid & 3) * 4;    // k offset (0,4,8,12)
    int a_r  = tid >> 2;         // 0..63 ; rows a_r, a_r+64
    // B load mapping: float4 along N
    int b_nq = (tid & 31) * 4;   // 0..124
    int b_r  = tid >> 5;         // 0..7  ; k rows b_r, b_r+8

    for (int k0 = 0; k0 < K; k0 += BK) {
        #pragma unroll
        for (int it = 0; it < 2; it++) {
            int row = m0 + a_r + it * 64;
            float4 va = make_float4(0.f, 0.f, 0.f, 0.f);
            if (row < M) va = *(const float4*)(A + (size_t)row * K + k0 + a_kq);
            As[a_kq + 0][a_r + it * 64] = va.x;
            As[a_kq + 1][a_r + it * 64] = va.y;
            As[a_kq + 2][a_r + it * 64] = va.z;
            As[a_kq + 3][a_r + it * 64] = va.w;
        }
        #pragma unroll
        for (int it = 0; it < 2; it++) {
            int krow = b_r + it * 8;
            *(float4*)&Bs[krow][b_nq] = *(const float4*)(B + (size_t)(k0 + krow) * N + n0 + b_nq);
        }
        __syncthreads();
        #pragma unroll
        for (int k = 0; k < BK; k++) {
            float4 a0 = *(const float4*)&As[k][ty * 8];
            float4 a1 = *(const float4*)&As[k][ty * 8 + 4];
            unsigned long long b2[4];
            #pragma unroll
            for (int jp = 0; jp < 4; jp++)
                b2[jp] = *(const unsigned long long*)&Bs[k][tx * 8 + 2 * jp];
            float a[8] = {a0.x, a0.y, a0.z, a0.w, a1.x, a1.y, a1.z, a1.w};
            #pragma unroll
            for (int i = 0; i < 8; i++) {
                unsigned long long a2 = pack_f32x2(a[i], a[i]);
                #pragma unroll
                for (int jp = 0; jp < 4; jp++)
                    fma_f32x2(acc[i][jp], a2, b2[jp]);
            }
        }
        __syncthreads();
    }

    #pragma unroll
    for (int i = 0; i < 8; i++) {
        int row = m0 + ty * 8 + i;
        if (row < M) {
            #pragma unroll
            for (int h = 0; h < 2; h++) {
                float2 p0 = unpack_f32x2(acc[i][2 * h + 0]);
                float2 p1 = unpack_f32x2(acc[i][2 * h + 1]);
                *(float4*)(C + (size_t)row * N + n0 + tx * 8 + 4 * h) =
                    make_float4(p0.x, p0.y, p1.x, p1.y);
            }
        }
    }
}

// ---------------- SpMM + bias + leaky_relu (warp per row, float4 lanes) -----
template <int D>
__global__ __launch_bounds__(256) void spmm_kernel(const float* __restrict__ sup,
                                                   const int* __restrict__ scol,
                                                   const float* __restrict__ sval,
                                                   const int* __restrict__ rowptr,
                                                   const float* __restrict__ bias,
                                                   float* __restrict__ out, int n) {
    int warp = (blockIdx.x * blockDim.x + threadIdx.x) >> 5;
    int lane = threadIdx.x & 31;
    if (warp >= n) return;
    int s = rowptr[warp];
    int e = rowptr[warp + 1];
    constexpr int J = D / 128;   // float4 chunks per lane
    float4 acc[J];
    #pragma unroll
    for (int j = 0; j < J; j++) acc[j] = make_float4(0.f, 0.f, 0.f, 0.f);

    int p = s;
    for (; p + 1 < e; p += 2) {
        int   c0 = __ldg(&scol[p]);
        int   c1 = __ldg(&scol[p + 1]);
        float v0 = __ldg(&sval[p]);
        float v1 = __ldg(&sval[p + 1]);
        const float4* base0 = (const float4*)(sup + (size_t)c0 * D);
        const float4* base1 = (const float4*)(sup + (size_t)c1 * D);
        #pragma unroll
        for (int j = 0; j < J; j++) {
            float4 g0 = __ldg(&base0[j * 32 + lane]);
            float4 g1 = __ldg(&base1[j * 32 + lane]);
            acc[j].x += v0 * g0.x + v1 * g1.x;
            acc[j].y += v0 * g0.y + v1 * g1.y;
            acc[j].z += v0 * g0.z + v1 * g1.z;
            acc[j].w += v0 * g0.w + v1 * g1.w;
        }
    }
    if (p < e) {
        int   c = __ldg(&scol[p]);
        float v = __ldg(&sval[p]);
        const float4* base = (const float4*)(sup + (size_t)c * D);
        #pragma unroll
        for (int j = 0; j < J; j++) {
            float4 g = __ldg(&base[j * 32 + lane]);
            acc[j].x += v * g.x;
            acc[j].y += v * g.y;
            acc[j].z += v * g.z;
            acc[j].w += v * g.w;
        }
    }

    float4* o = (float4*)(out + (size_t)warp * D);
    const float4* bp = (const float4*)bias;
    #pragma unroll
    for (int j = 0; j < J; j++) {
        float4 b = __ldg(&bp[j * 32 + lane]);
        float rx = acc[j].x + b.x;
        float ry = acc[j].y + b.y;
        float rz = acc[j].z + b.z;
        float rw = acc[j].w + b.w;
        rx = (rx > 0.f) ? rx : GCN_SLOPE * rx;
        ry = (ry > 0.f) ? ry : GCN_SLOPE * ry;
        rz = (rz > 0.f) ? rz : GCN_SLOPE * rz;
        rw = (rw > 0.f) ? rw : GCN_SLOPE * rw;
        o[j * 32 + lane] = make_float4(rx, ry, rz, rw);
    }
}

// ---------------- launch ----------------
extern "C" void kernel_launch(void* const* d_in, const int* in_sizes, int n_in,
                              void* d_out, int out_size) {
    const float* x    = (const float*)d_in[0];
    const int*   rows = (const int*)  d_in[1];
    const int*   cols = (const int*)  d_in[2];
    const float* vals = (const float*)d_in[3];
    const float* W1   = (const float*)d_in[4];
    const float* b1   = (const float*)d_in[5];
    const float* W2   = (const float*)d_in[6];
    const float* b2   = (const float*)d_in[7];
    const float* W3   = (const float*)d_in[8];
    const float* b3   = (const float*)d_in[9];
    float* out = (float*)d_out;

    const int N = GCN_N;
    const int NNZ = GCN_NNZ;

    int *rowptr, *cursor, *scol;
    float *sval, *sup, *hbuf;
    cudaGetSymbolAddress((void**)&rowptr, g_rowptr);
    cudaGetSymbolAddress((void**)&cursor, g_cursor);
    cudaGetSymbolAddress((void**)&scol,   g_scol);
    cudaGetSymbolAddress((void**)&sval,   g_sval);
    cudaGetSymbolAddress((void**)&sup,    g_sup);
    cudaGetSymbolAddress((void**)&hbuf,   g_hbuf);

    // CSR build (deterministic, graph-capturable)
    zero_kernel<<<(N + 255) / 256, 256>>>(cursor, N);
    hist_kernel<<<(NNZ + 255) / 256, 256>>>(rows, cursor, NNZ);
    scan_kernel<<<1, 1024>>>(cursor, rowptr, N);
    copy_kernel<<<(N + 255) / 256, 256>>>(rowptr, cursor, N);
    scatter_kernel<<<(NNZ + 255) / 256, 256>>>(rows, cols, vals, cursor, scol, sval, NNZ);

    dim3 g2(256 / BN, (N + BM - 1) / BM);
    dim3 g1(128 / BN, (N + BM - 1) / BM);
    int spmm_grid = (N + 7) / 8;  // 8 warps per 256-thread block

    // layer 1: x[100k,512] @ W1[512,256] ; spmm ; +b1 ; leaky
    gemm_kernel<<<g2, 256>>>(x, W1, sup, N, 256, 512);
    spmm_kernel<256><<<spmm_grid, 256>>>(sup, scol, sval, rowptr, b1, hbuf, N);
    // layer 2
    gemm_kernel<<<g2, 256>>>(hbuf, W2, sup, N, 256, 256);
    spmm_kernel<256><<<spmm_grid, 256>>>(sup, scol, sval, rowptr, b2, hbuf, N);
    // layer 3: -> d_out [100k,128]
    gemm_kernel<<<g1, 256>>>(hbuf, W3, sup, N, 128, 256);
    spmm_kernel<128><<<spmm_grid, 256>>>(sup, scol, sval, rowptr, b3, out, N);
}

// round 4
// speedup vs baseline: 1.1881x; 1.0832x over previous
#include <cuda_runtime.h>
#include <cuda_bf16.h>
#include <cstdint>

#define GCN_N     100000
#define GCN_NNZ   3200000
#define GCN_SLOPE 0.25f

// ---------------- device scratch (static, allocation-free) ----------------
__device__ __align__(16) int   g_rowptr[GCN_N + 1];
__device__ __align__(16) int   g_cursor[GCN_N];
__device__ __align__(16) int   g_scol[GCN_NNZ];
__device__ __align__(16) float g_sval[GCN_NNZ];
__device__ __align__(16) float g_sup [GCN_N * 256];           // GEMM output fp32
__device__ __align__(16) __nv_bfloat16 g_a[(size_t)GCN_N * 1536];  // A' concat splits
__device__ __align__(16) __nv_bfloat16 g_b[256 * 1536];            // B' concat splits

// ---------------- CSR build ----------------
__global__ void zero_kernel(int* p, int n) {
    int i = blockIdx.x * blockDim.x + threadIdx.x;
    if (i < n) p[i] = 0;
}
__global__ void hist_kernel(const int* __restrict__ rows, int* __restrict__ counts, int nnz) {
    int i = blockIdx.x * blockDim.x + threadIdx.x;
    if (i < nnz) atomicAdd(&counts[rows[i]], 1);
}
__global__ void scan_kernel(const int* __restrict__ counts, int* __restrict__ rowptr, int n) {
    __shared__ int wsum[32];
    int lane = threadIdx.x & 31;
    int wid  = threadIdx.x >> 5;
    int offset = 0;
    if (threadIdx.x == 0) rowptr[0] = 0;
    for (int base = 0; base < n; base += 1024) {
        int i = base + threadIdx.x;
        int v = (i < n) ? counts[i] : 0;
        int x = v;
        #pragma unroll
        for (int d = 1; d < 32; d <<= 1) {
            int y = __shfl_up_sync(0xffffffffu, x, d);
            if (lane >= d) x += y;
        }
        if (lane == 31) wsum[wid] = x;
        __syncthreads();
        if (wid == 0) {
            int t = wsum[lane];
            #pragma unroll
            for (int d = 1; d < 32; d <<= 1) {
                int y = __shfl_up_sync(0xffffffffu, t, d);
                if (lane >= d) t += y;
            }
            wsum[lane] = t;
        }
        __syncthreads();
        int incl = x + (wid > 0 ? wsum[wid - 1] : 0);
        if (i < n) rowptr[i + 1] = offset + incl;
        offset += wsum[31];
        __syncthreads();
    }
}
__global__ void copy_kernel(const int* __restrict__ src, int* __restrict__ dst, int n) {
    int i = blockIdx.x * blockDim.x + threadIdx.x;
    if (i < n) dst[i] = src[i];
}
__global__ void scatter_kernel(const int* __restrict__ rows, const int* __restrict__ cols,
                               const float* __restrict__ vals, int* __restrict__ cursor,
                               int* __restrict__ scol, float* __restrict__ sval, int nnz) {
    int i = blockIdx.x * blockDim.x + threadIdx.x;
    if (i < nnz) {
        int r = rows[i];
        int pos = atomicAdd(&cursor[r], 1);
        scol[pos] = cols[i];
        sval[pos] = vals[i];
    }
}

// ---------------- x -> A' concat split  [hi(512) | lo(512) | hi(512)] ------
__global__ void split_x_kernel(const float* __restrict__ in, __nv_bfloat16* __restrict__ ap, int n4) {
    int i = blockIdx.x * blockDim.x + threadIdx.x;
    if (i >= n4) return;
    float4 v = __ldg((const float4*)in + i);
    int row = i >> 7;                  // 512/4 groups per row
    int col = (i & 127) * 4;
    __nv_bfloat16 h0 = __float2bfloat16(v.x), h1 = __float2bfloat16(v.y);
    __nv_bfloat16 h2 = __float2bfloat16(v.z), h3 = __float2bfloat16(v.w);
    __nv_bfloat162 hA(h0, h1), hB(h2, h3);
    __nv_bfloat162 lA(__float2bfloat16(v.x - __bfloat162float(h0)),
                      __float2bfloat16(v.y - __bfloat162float(h1)));
    __nv_bfloat162 lB(__float2bfloat16(v.z - __bfloat162float(h2)),
                      __float2bfloat16(v.w - __bfloat162float(h3)));
    __nv_bfloat16* rp = ap + (size_t)row * 1536;
    *(__nv_bfloat162*)(rp + col)            = hA;
    *(__nv_bfloat162*)(rp + col + 2)        = hB;
    *(__nv_bfloat162*)(rp + col + 512)      = lA;
    *(__nv_bfloat162*)(rp + col + 514)      = lB;
    *(__nv_bfloat162*)(rp + col + 1024)     = hA;
    *(__nv_bfloat162*)(rp + col + 1026)     = hB;
}

// W[K,N] -> B'[n][0:K]=Wh, [K:2K]=Wh, [2K:3K]=Wl   (row stride 3K)
__global__ void wsplit_kernel(const float* __restrict__ W, __nv_bfloat16* __restrict__ bp,
                              int K, int N) {
    int idx = blockIdx.x * blockDim.x + threadIdx.x;
    if (idx >= K * N) return;
    int k = idx / N, n = idx % N;
    float v = W[idx];
    __nv_bfloat16 h = __float2bfloat16(v);
    __nv_bfloat16 l = __float2bfloat16(v - __bfloat162float(h));
    __nv_bfloat16* rp = bp + (size_t)n * (3 * K);
    rp[k] = h;
    rp[K + k] = h;
    rp[2 * K + k] = l;
}

// ---------------- bf16 GEMM via mma.sync (HMMA), cp.async pipeline ---------
// C[M,N] = A[M,K] @ B[N,K]^T ; A,B row-major bf16 (K-major); C fp32.
// BM=128, BN=128, BK=64, 3 stages, 256 threads, warp tile 32x64.
__global__ __launch_bounds__(256) void gemm_mma(const __nv_bfloat16* __restrict__ A,
                                                const __nv_bfloat16* __restrict__ B,
                                                float* __restrict__ C,
                                                int M, int N, int K) {
    extern __shared__ char smem[];
    constexpr int STAGES = 3;
    constexpr int ABYTES = 128 * 64 * 2;   // 16KB
    constexpr int BBYTES = 128 * 64 * 2;
    uint32_t sa_base;
    asm("{ .reg .u64 t; cvta.to.shared.u64 t, %1; cvt.u32.u64 %0, t; }" : "=r"(sa_base) : "l"(smem));
    uint32_t sb_base = sa_base + STAGES * ABYTES;

    int tid = threadIdx.x;
    int wid = tid >> 5, lane = tid & 31;
    int wm = wid & 3, wn = wid >> 2;
    int m0 = blockIdx.y * 128, n0 = blockIdx.x * 128;
    int NC = K / 64;

    float d[2][8][4];
    #pragma unroll
    for (int mi = 0; mi < 2; mi++)
        #pragma unroll
        for (int nj = 0; nj < 8; nj++)
            #pragma unroll
            for (int q = 0; q < 4; q++) d[mi][nj][q] = 0.f;

    const __nv_bfloat16* Abase = A + (size_t)m0 * K;
    const __nv_bfloat16* Bbase = B + (size_t)n0 * K;

#define LOAD_STAGE(st, ch) do {                                                   \
        uint32_t _da = sa_base + (st) * ABYTES;                                   \
        uint32_t _db = sb_base + (st) * BBYTES;                                   \
        int _k0 = (ch) * 64;                                                      \
        _Pragma("unroll")                                                         \
        for (int _i = 0; _i < 4; _i++) {                                          \
            int _u = tid + _i * 256;                                              \
            int _r = _u >> 3, _c = _u & 7;                                        \
            uint32_t _off = (uint32_t)(_r * 128 + _c * 16);                       \
            _off ^= ((_off >> 3) & 0x70);                                         \
            const __nv_bfloat16* _src = Abase + (size_t)_r * K + _k0 + _c * 8;    \
            uint32_t _sz = (m0 + _r < M) ? 16u : 0u;                              \
            if (m0 + _r >= M) _src = Abase + _k0;                                 \
            asm volatile("cp.async.cg.shared.global [%0], [%1], 16, %2;"          \
                :: "r"(_da + _off), "l"(_src), "r"(_sz));                         \
        }                                                                         \
        _Pragma("unroll")                                                         \
        for (int _i = 0; _i < 4; _i++) {                                          \
            int _u = tid + _i * 256;                                              \
            int _r = _u >> 3, _c = _u & 7;                                        \
            uint32_t _off = (uint32_t)(_r * 128 + _c * 16);                       \
            _off ^= ((_off >> 3) & 0x70);                                         \
            const __nv_bfloat16* _src = Bbase + (size_t)_r * K + _k0 + _c * 8;    \
            asm volatile("cp.async.cg.shared.global [%0], [%1], 16;"              \
                :: "r"(_db + _off), "l"(_src));                                   \
        }                                                                         \
    } while (0)

    // prefetch
    LOAD_STAGE(0, 0);
    asm volatile("cp.async.commit_group;");
    LOAD_STAGE(1, 1);
    asm volatile("cp.async.commit_group;");

    for (int c = 0; c < NC; c++) {
        asm volatile("cp.async.wait_group 1;");
        __syncthreads();
        if (c + 2 < NC) LOAD_STAGE((c + 2) % STAGES, c + 2);
        asm volatile("cp.async.commit_group;");

        uint32_t da = sa_base + (c % STAGES) * ABYTES;
        uint32_t db = sb_base + (c % STAGES) * BBYTES;
        #pragma unroll
        for (int kk = 0; kk < 4; kk++) {
            int k16 = kk * 16;
            uint32_t a[2][4];
            #pragma unroll
            for (int mi = 0; mi < 2; mi++) {
                int row = wm * 32 + mi * 16 + (lane & 15);
                int colB = (k16 + ((lane >> 4) << 3)) * 2;
                uint32_t off = (uint32_t)(row * 128 + colB);
                off ^= ((off >> 3) & 0x70);
                asm volatile("ldmatrix.sync.aligned.m8n8.x4.shared.b16 {%0,%1,%2,%3}, [%4];"
                    : "=r"(a[mi][0]), "=r"(a[mi][1]), "=r"(a[mi][2]), "=r"(a[mi][3])
                    : "r"(da + off));
            }
            uint32_t b[8][2];
            #pragma unroll
            for (int nj = 0; nj < 4; nj++) {
                int nrow = wn * 64 + nj * 16 + (lane & 7) + ((lane >> 4) << 3);
                int colB = (k16 + (((lane >> 3) & 1) << 3)) * 2;
                uint32_t off = (uint32_t)(nrow * 128 + colB);
                off ^= ((off >> 3) & 0x70);
                uint32_t r0, r1, r2, r3;
                asm volatile("ldmatrix.sync.aligned.m8n8.x4.shared.b16 {%0,%1,%2,%3}, [%4];"
                    : "=r"(r0), "=r"(r1), "=r"(r2), "=r"(r3) : "r"(db + off));
                b[nj * 2][0] = r0; b[nj * 2][1] = r1;
                b[nj * 2 + 1][0] = r2; b[nj * 2 + 1][1] = r3;
            }
            #pragma unroll
            for (int mi = 0; mi < 2; mi++)
                #pragma unroll
                for (int nj = 0; nj < 8; nj++)
                    asm volatile("mma.sync.aligned.m16n8k16.row.col.f32.bf16.bf16.f32 "
                        "{%0,%1,%2,%3}, {%4,%5,%6,%7}, {%8,%9}, {%0,%1,%2,%3};"
                        : "+f"(d[mi][nj][0]), "+f"(d[mi][nj][1]),
                          "+f"(d[mi][nj][2]), "+f"(d[mi][nj][3])
                        : "r"(a[mi][0]), "r"(a[mi][1]), "r"(a[mi][2]), "r"(a[mi][3]),
                          "r"(b[nj][0]), "r"(b[nj][1]));
        }
        __syncthreads();
    }
#undef LOAD_STAGE

    // epilogue: direct fp32 stores
    #pragma unroll
    for (int mi = 0; mi < 2; mi++) {
        int r0 = m0 + wm * 32 + mi * 16 + (lane >> 2);
        #pragma unroll
        for (int nj = 0; nj < 8; nj++) {
            int col = n0 + wn * 64 + nj * 8 + 2 * (lane & 3);
            if (r0 < M)
                *(float2*)(C + (size_t)r0 * N + col) = make_float2(d[mi][nj][0], d[mi][nj][1]);
            if (r0 + 8 < M)
                *(float2*)(C + (size_t)(r0 + 8) * N + col) = make_float2(d[mi][nj][2], d[mi][nj][3]);
        }
    }
}

// ---------------- SpMM + bias + leaky_relu (warp per row) ----------------
// SPLIT=true: writes concat-split bf16 A' rows [hi(256)|lo(256)|hi(256)], stride 768.
template <int D, bool SPLIT>
__global__ __launch_bounds__(256) void spmm_kernel(const float* __restrict__ sup,
                                                   const int* __restrict__ scol,
                                                   const float* __restrict__ sval,
                                                   const int* __restrict__ rowptr,
                                                   const float* __restrict__ bias,
                                                   float* __restrict__ outf,
                                                   __nv_bfloat16* __restrict__ outa,
                                                   int n) {
    int warp = (blockIdx.x * blockDim.x + threadIdx.x) >> 5;
    int lane = threadIdx.x & 31;
    if (warp >= n) return;
    int s = rowptr[warp];
    int e = rowptr[warp + 1];
    constexpr int J = D / 128;
    float4 acc[J];
    #pragma unroll
    for (int j = 0; j < J; j++) acc[j] = make_float4(0.f, 0.f, 0.f, 0.f);

    int p = s;
    for (; p + 1 < e; p += 2) {
        int   c0 = __ldg(&scol[p]);
        int   c1 = __ldg(&scol[p + 1]);
        float v0 = __ldg(&sval[p]);
        float v1 = __ldg(&sval[p + 1]);
        const float4* b0 = (const float4*)(sup + (size_t)c0 * D);
        const float4* b1 = (const float4*)(sup + (size_t)c1 * D);
        #pragma unroll
        for (int j = 0; j < J; j++) {
            float4 g0 = __ldg(&b0[j * 32 + lane]);
            float4 g1 = __ldg(&b1[j * 32 + lane]);
            acc[j].x += v0 * g0.x + v1 * g1.x;
            acc[j].y += v0 * g0.y + v1 * g1.y;
            acc[j].z += v0 * g0.z + v1 * g1.z;
            acc[j].w += v0 * g0.w + v1 * g1.w;
        }
    }
    if (p < e) {
        int   c = __ldg(&scol[p]);
        float v = __ldg(&sval[p]);
        const float4* b = (const float4*)(sup + (size_t)c * D);
        #pragma unroll
        for (int j = 0; j < J; j++) {
            float4 g = __ldg(&b[j * 32 + lane]);
            acc[j].x += v * g.x;
            acc[j].y += v * g.y;
            acc[j].z += v * g.z;
            acc[j].w += v * g.w;
        }
    }

    const float4* bp = (const float4*)bias;
    #pragma unroll
    for (int j = 0; j < J; j++) {
        float4 b = __ldg(&bp[j * 32 + lane]);
        float rx = acc[j].x + b.x, ry = acc[j].y + b.y;
        float rz = acc[j].z + b.z, rw = acc[j].w + b.w;
        rx = (rx > 0.f) ? rx : GCN_SLOPE * rx;
        ry = (ry > 0.f) ? ry : GCN_SLOPE * ry;
        rz = (rz > 0.f) ? rz : GCN_SLOPE * rz;
        rw = (rw > 0.f) ? rw : GCN_SLOPE * rw;
        if (SPLIT) {
            __nv_bfloat16 hx = __float2bfloat16(rx), hy = __float2bfloat16(ry);
            __nv_bfloat16 hz = __float2bfloat16(rz), hw = __float2bfloat16(rw);
            __nv_bfloat162 hA(hx, hy), hB(hz, hw);
            __nv_bfloat162 lA(__float2bfloat16(rx - __bfloat162float(hx)),
                              __float2bfloat16(ry - __bfloat162float(hy)));
            __nv_bfloat162 lB(__float2bfloat16(rz - __bfloat162float(hz)),
                              __float2bfloat16(rw - __bfloat162float(hw)));
            __nv_bfloat16* rp = outa + (size_t)warp * 768;
            int col = (j * 32 + lane) * 4;
            *(__nv_bfloat162*)(rp + col)           = hA;
            *(__nv_bfloat162*)(rp + col + 2)       = hB;
            *(__nv_bfloat162*)(rp + col + 256)     = lA;
            *(__nv_bfloat162*)(rp + col + 258)     = lB;
            *(__nv_bfloat162*)(rp + col + 512)     = hA;
            *(__nv_bfloat162*)(rp + col + 514)     = hB;
        } else {
            float4* o = (float4*)(outf + (size_t)warp * D);
            o[j * 32 + lane] = make_float4(rx, ry, rz, rw);
        }
    }
}

// ---------------- launch ----------------
extern "C" void kernel_launch(void* const* d_in, const int* in_sizes, int n_in,
                              void* d_out, int out_size) {
    const float* x    = (const float*)d_in[0];
    const int*   rows = (const int*)  d_in[1];
    const int*   cols = (const int*)  d_in[2];
    const float* vals = (const float*)d_in[3];
    const float* W1   = (const float*)d_in[4];
    const float* b1   = (const float*)d_in[5];
    const float* W2   = (const float*)d_in[6];
    const float* b2   = (const float*)d_in[7];
    const float* W3   = (const float*)d_in[8];
    const float* b3   = (const float*)d_in[9];
    float* out = (float*)d_out;

    const int N = GCN_N;
    const int NNZ = GCN_NNZ;

    int *rowptr, *cursor, *scol;
    float *sval, *sup;
    __nv_bfloat16 *ap, *bp;
    cudaGetSymbolAddress((void**)&rowptr, g_rowptr);
    cudaGetSymbolAddress((void**)&cursor, g_cursor);
    cudaGetSymbolAddress((void**)&scol,   g_scol);
    cudaGetSymbolAddress((void**)&sval,   g_sval);
    cudaGetSymbolAddress((void**)&sup,    g_sup);
    cudaGetSymbolAddress((void**)&ap,     g_a);
    cudaGetSymbolAddress((void**)&bp,     g_b);

    const int SMEM_GEMM = 3 * (128 * 64 * 2) * 2;   // 96KB
    cudaFuncSetAttribute(gemm_mma, cudaFuncAttributeMaxDynamicSharedMemorySize, SMEM_GEMM);

    // CSR build
    zero_kernel<<<(N + 255) / 256, 256>>>(cursor, N);
    hist_kernel<<<(NNZ + 255) / 256, 256>>>(rows, cursor, NNZ);
    scan_kernel<<<1, 1024>>>(cursor, rowptr, N);
    copy_kernel<<<(N + 255) / 256, 256>>>(rowptr, cursor, N);
    scatter_kernel<<<(NNZ + 255) / 256, 256>>>(rows, cols, vals, cursor, scol, sval, NNZ);

    const int MTILES = (N + 127) / 128;   // 782
    int spmm_grid = (N + 7) / 8;

    // x -> A' (K'=1536)
    split_x_kernel<<<(N * 512 / 4 + 255) / 256, 256>>>(x, ap, N * 512 / 4);

    // layer 1: K'=1536, N=256
    wsplit_kernel<<<(512 * 256 + 255) / 256, 256>>>(W1, bp, 512, 256);
    gemm_mma<<<dim3(2, MTILES), 256, SMEM_GEMM>>>(ap, bp, sup, N, 256, 1536);
    spmm_kernel<256, true><<<spmm_grid, 256>>>(sup, scol, sval, rowptr, b1, nullptr, ap, N);

    // layer 2: K'=768, N=256
    wsplit_kernel<<<(256 * 256 + 255) / 256, 256>>>(W2, bp, 256, 256);
    gemm_mma<<<dim3(2, MTILES), 256, SMEM_GEMM>>>(ap, bp, sup, N, 256, 768);
    spmm_kernel<256, true><<<spmm_grid, 256>>>(sup, scol, sval, rowptr, b2, nullptr, ap, N);

    // layer 3: K'=768, N=128 -> out
    wsplit_kernel<<<(256 * 128 + 255) / 256, 256>>>(W3, bp, 256, 128);
    gemm_mma<<<dim3(1, MTILES), 256, SMEM_GEMM>>>(ap, bp, sup, N, 128, 768);
    spmm_kernel<128, false><<<spmm_grid, 256>>>(sup, scol, sval, rowptr, b3, out, nullptr, N);
}

// round 5
// speedup vs baseline: 1.7934x; 1.5094x over previous
#include <cuda_runtime.h>
#include <cuda_fp16.h>
#include <cstdint>

#define GCN_N     100000
#define GCN_NNZ   3200000
#define GCN_SLOPE 0.25f

// ---------------- device scratch (static, allocation-free) ----------------
__device__ __align__(16) int   g_rowptr[GCN_N + 1];
__device__ __align__(16) int   g_cursor[GCN_N];
__device__ __align__(16) int   g_scol[GCN_NNZ];
__device__ __align__(16) float g_sval[GCN_NNZ];
__device__ __align__(16) float g_sup [GCN_N * 256];            // GEMM output fp32
__device__ __align__(16) __half g_a[(size_t)GCN_N * 1024];     // A' = [hi | lo] fp16
__device__ __align__(16) __half g_b[256 * 1024];               // B' = [hi | hi] fp16

// ---------------- CSR build ----------------
__global__ void zero_kernel(int* p, int n) {
    int i = blockIdx.x * blockDim.x + threadIdx.x;
    if (i < n) p[i] = 0;
}
__global__ void hist_kernel(const int* __restrict__ rows, int* __restrict__ counts, int nnz) {
    int i = blockIdx.x * blockDim.x + threadIdx.x;
    if (i < nnz) atomicAdd(&counts[rows[i]], 1);
}
// exclusive scan; writes rowptr[0..n] and cursor[i] = rowptr[i]
__global__ void scan_kernel(const int* __restrict__ counts, int* __restrict__ rowptr,
                            int* __restrict__ cursor, int n) {
    __shared__ int wsum[32];
    int lane = threadIdx.x & 31;
    int wid  = threadIdx.x >> 5;
    int offset = 0;
    if (threadIdx.x == 0) rowptr[0] = 0;
    for (int base = 0; base < n; base += 1024) {
        int i = base + threadIdx.x;
        int v = (i < n) ? counts[i] : 0;
        int x = v;
        #pragma unroll
        for (int d = 1; d < 32; d <<= 1) {
            int y = __shfl_up_sync(0xffffffffu, x, d);
            if (lane >= d) x += y;
        }
        if (lane == 31) wsum[wid] = x;
        __syncthreads();
        if (wid == 0) {
            int t = wsum[lane];
            #pragma unroll
            for (int d = 1; d < 32; d <<= 1) {
                int y = __shfl_up_sync(0xffffffffu, t, d);
                if (lane >= d) t += y;
            }
            wsum[lane] = t;
        }
        __syncthreads();
        int incl = x + (wid > 0 ? wsum[wid - 1] : 0);
        if (i < n) {
            rowptr[i + 1] = offset + incl;
            cursor[i] = offset + incl - v;
        }
        offset += wsum[31];
        __syncthreads();
    }
}
__global__ void scatter_kernel(const int* __restrict__ rows, const int* __restrict__ cols,
                               const float* __restrict__ vals, int* __restrict__ cursor,
                               int* __restrict__ scol, float* __restrict__ sval, int nnz) {
    int i = blockIdx.x * blockDim.x + threadIdx.x;
    if (i < nnz) {
        int r = rows[i];
        int pos = atomicAdd(&cursor[r], 1);
        scol[pos] = cols[i];
        sval[pos] = vals[i];
    }
}

// ---------------- x -> A' fp16 split [hi(512) | lo(512)], stride 1024 ------
__global__ void split_x_kernel(const float* __restrict__ in, __half* __restrict__ ap, int n4) {
    int i = blockIdx.x * blockDim.x + threadIdx.x;
    if (i >= n4) return;
    float4 v = __ldg((const float4*)in + i);
    int row = i >> 7;                  // 128 float4-groups per 512-row
    int col = (i & 127) * 4;
    __half h0 = __float2half_rn(v.x), h1 = __float2half_rn(v.y);
    __half h2 = __float2half_rn(v.z), h3 = __float2half_rn(v.w);
    __half2 hA = __halves2half2(h0, h1), hB = __halves2half2(h2, h3);
    __half2 lA = __halves2half2(__float2half_rn(v.x - __half2float(h0)),
                                __float2half_rn(v.y - __half2float(h1)));
    __half2 lB = __halves2half2(__float2half_rn(v.z - __half2float(h2)),
                                __float2half_rn(v.w - __half2float(h3)));
    __half* rp = ap + (size_t)row * 1024;
    *(__half2*)(rp + col)         = hA;
    *(__half2*)(rp + col + 2)     = hB;
    *(__half2*)(rp + col + 512)   = lA;
    *(__half2*)(rp + col + 514)   = lB;
}

// W[K,N] -> B'[n] = [Wh(K) | Wh(K)], row stride 2K
__global__ void wsplit_kernel(const float* __restrict__ W, __half* __restrict__ bp,
                              int K, int N) {
    int idx = blockIdx.x * blockDim.x + threadIdx.x;
    if (idx >= K * N) return;
    int k = idx / N, n = idx % N;
    __half h = __float2half_rn(W[idx]);
    __half* rp = bp + (size_t)n * (2 * K);
    rp[k] = h;
    rp[K + k] = h;
}

// ---------------- fp16 GEMM via mma.sync (HMMA), cp.async pipeline ---------
// C[M,N] = A[M,K] @ B[N,K]^T ; A,B row-major fp16 (K-major); C fp32.
// BM=128, BN=128, BK=64, 3 stages, 256 threads, warp tile 32x64.
__global__ __launch_bounds__(256) void gemm_mma(const __half* __restrict__ A,
                                                const __half* __restrict__ B,
                                                float* __restrict__ C,
                                                int M, int N, int K) {
    extern __shared__ char smem[];
    constexpr int STAGES = 3;
    constexpr int ABYTES = 128 * 64 * 2;   // 16KB
    constexpr int BBYTES = 128 * 64 * 2;
    uint32_t sa_base;
    asm("{ .reg .u64 t; cvta.to.shared.u64 t, %1; cvt.u32.u64 %0, t; }" : "=r"(sa_base) : "l"(smem));
    uint32_t sb_base = sa_base + STAGES * ABYTES;

    int tid = threadIdx.x;
    int wid = tid >> 5, lane = tid & 31;
    int wm = wid & 3, wn = wid >> 2;
    int m0 = blockIdx.y * 128, n0 = blockIdx.x * 128;
    int NC = K / 64;

    float d[2][8][4];
    #pragma unroll
    for (int mi = 0; mi < 2; mi++)
        #pragma unroll
        for (int nj = 0; nj < 8; nj++)
            #pragma unroll
            for (int q = 0; q < 4; q++) d[mi][nj][q] = 0.f;

    const __half* Abase = A + (size_t)m0 * K;
    const __half* Bbase = B + (size_t)n0 * K;

#define LOAD_STAGE(st, ch) do {                                                   \
        uint32_t _da = sa_base + (st) * ABYTES;                                   \
        uint32_t _db = sb_base + (st) * BBYTES;                                   \
        int _k0 = (ch) * 64;                                                      \
        _Pragma("unroll")                                                         \
        for (int _i = 0; _i < 4; _i++) {                                          \
            int _u = tid + _i * 256;                                              \
            int _r = _u >> 3, _c = _u & 7;                                        \
            uint32_t _off = (uint32_t)(_r * 128 + _c * 16);                       \
            _off ^= ((_off >> 3) & 0x70);                                         \
            const __half* _src = Abase + (size_t)_r * K + _k0 + _c * 8;           \
            uint32_t _sz = (m0 + _r < M) ? 16u : 0u;                              \
            if (m0 + _r >= M) _src = Abase + _k0;                                 \
            asm volatile("cp.async.cg.shared.global [%0], [%1], 16, %2;"          \
                :: "r"(_da + _off), "l"(_src), "r"(_sz));                         \
        }                                                                         \
        _Pragma("unroll")                                                         \
        for (int _i = 0; _i < 4; _i++) {                                          \
            int _u = tid + _i * 256;                                              \
            int _r = _u >> 3, _c = _u & 7;                                        \
            uint32_t _off = (uint32_t)(_r * 128 + _c * 16);                       \
            _off ^= ((_off >> 3) & 0x70);                                         \
            const __half* _src = Bbase + (size_t)_r * K + _k0 + _c * 8;           \
            asm volatile("cp.async.cg.shared.global [%0], [%1], 16;"              \
                :: "r"(_db + _off), "l"(_src));                                   \
        }                                                                         \
    } while (0)

    // prefetch
    LOAD_STAGE(0, 0);
    asm volatile("cp.async.commit_group;");
    LOAD_STAGE(1, 1);
    asm volatile("cp.async.commit_group;");

    for (int c = 0; c < NC; c++) {
        asm volatile("cp.async.wait_group 1;");
        __syncthreads();
        if (c + 2 < NC) LOAD_STAGE((c + 2) % STAGES, c + 2);
        asm volatile("cp.async.commit_group;");

        uint32_t da = sa_base + (c % STAGES) * ABYTES;
        uint32_t db = sb_base + (c % STAGES) * BBYTES;
        #pragma unroll
        for (int kk = 0; kk < 4; kk++) {
            int k16 = kk * 16;
            uint32_t a[2][4];
            #pragma unroll
            for (int mi = 0; mi < 2; mi++) {
                int row = wm * 32 + mi * 16 + (lane & 15);
                int colB = (k16 + ((lane >> 4) << 3)) * 2;
                uint32_t off = (uint32_t)(row * 128 + colB);
                off ^= ((off >> 3) & 0x70);
                asm volatile("ldmatrix.sync.aligned.m8n8.x4.shared.b16 {%0,%1,%2,%3}, [%4];"
                    : "=r"(a[mi][0]), "=r"(a[mi][1]), "=r"(a[mi][2]), "=r"(a[mi][3])
                    : "r"(da + off));
            }
            uint32_t b[8][2];
            #pragma unroll
            for (int nj = 0; nj < 4; nj++) {
                int nrow = wn * 64 + nj * 16 + (lane & 7) + ((lane >> 4) << 3);
                int colB = (k16 + (((lane >> 3) & 1) << 3)) * 2;
                uint32_t off = (uint32_t)(nrow * 128 + colB);
                off ^= ((off >> 3) & 0x70);
                uint32_t r0, r1, r2, r3;
                asm volatile("ldmatrix.sync.aligned.m8n8.x4.shared.b16 {%0,%1,%2,%3}, [%4];"
                    : "=r"(r0), "=r"(r1), "=r"(r2), "=r"(r3) : "r"(db + off));
                b[nj * 2][0] = r0; b[nj * 2][1] = r1;
                b[nj * 2 + 1][0] = r2; b[nj * 2 + 1][1] = r3;
            }
            #pragma unroll
            for (int mi = 0; mi < 2; mi++)
                #pragma unroll
                for (int nj = 0; nj < 8; nj++)
                    asm volatile("mma.sync.aligned.m16n8k16.row.col.f32.f16.f16.f32 "
                        "{%0,%1,%2,%3}, {%4,%5,%6,%7}, {%8,%9}, {%0,%1,%2,%3};"
                        : "+f"(d[mi][nj][0]), "+f"(d[mi][nj][1]),
                          "+f"(d[mi][nj][2]), "+f"(d[mi][nj][3])
                        : "r"(a[mi][0]), "r"(a[mi][1]), "r"(a[mi][2]), "r"(a[mi][3]),
                          "r"(b[nj][0]), "r"(b[nj][1]));
        }
        __syncthreads();
    }
#undef LOAD_STAGE

    // epilogue: direct fp32 stores
    #pragma unroll
    for (int mi = 0; mi < 2; mi++) {
        int r0 = m0 + wm * 32 + mi * 16 + (lane >> 2);
        #pragma unroll
        for (int nj = 0; nj < 8; nj++) {
            int col = n0 + wn * 64 + nj * 8 + 2 * (lane & 3);
            if (r0 < M)
                *(float2*)(C + (size_t)r0 * N + col) = make_float2(d[mi][nj][0], d[mi][nj][1]);
            if (r0 + 8 < M)
                *(float2*)(C + (size_t)(r0 + 8) * N + col) = make_float2(d[mi][nj][2], d[mi][nj][3]);
        }
    }
}

// ---------------- SpMM + bias + leaky_relu (warp per row, unroll 4) --------
// SPLIT=true: writes fp16 A' rows [hi(256)|lo(256)], stride 512.
template <int D, bool SPLIT>
__global__ __launch_bounds__(256) void spmm_kernel(const float* __restrict__ sup,
                                                   const int* __restrict__ scol,
                                                   const float* __restrict__ sval,
                                                   const int* __restrict__ rowptr,
                                                   const float* __restrict__ bias,
                                                   float* __restrict__ outf,
                                                   __half* __restrict__ outa,
                                                   int n) {
    int warp = (blockIdx.x * blockDim.x + threadIdx.x) >> 5;
    int lane = threadIdx.x & 31;
    if (warp >= n) return;
    int s = rowptr[warp];
    int e = rowptr[warp + 1];
    constexpr int J = D / 128;
    float4 acc[J];
    #pragma unroll
    for (int j = 0; j < J; j++) acc[j] = make_float4(0.f, 0.f, 0.f, 0.f);

    int p = s;
    for (; p + 3 < e; p += 4) {
        int   c0 = __ldg(&scol[p]),     c1 = __ldg(&scol[p + 1]);
        int   c2 = __ldg(&scol[p + 2]), c3 = __ldg(&scol[p + 3]);
        float v0 = __ldg(&sval[p]),     v1 = __ldg(&sval[p + 1]);
        float v2 = __ldg(&sval[p + 2]), v3 = __ldg(&sval[p + 3]);
        const float4* b0 = (const float4*)(sup + (size_t)c0 * D);
        const float4* b1 = (const float4*)(sup + (size_t)c1 * D);
        const float4* b2 = (const float4*)(sup + (size_t)c2 * D);
        const float4* b3 = (const float4*)(sup + (size_t)c3 * D);
        #pragma unroll
        for (int j = 0; j < J; j++) {
            float4 g0 = __ldg(&b0[j * 32 + lane]);
            float4 g1 = __ldg(&b1[j * 32 + lane]);
            float4 g2 = __ldg(&b2[j * 32 + lane]);
            float4 g3 = __ldg(&b3[j * 32 + lane]);
            acc[j].x += v0 * g0.x + v1 * g1.x + v2 * g2.x + v3 * g3.x;
            acc[j].y += v0 * g0.y + v1 * g1.y + v2 * g2.y + v3 * g3.y;
            acc[j].z += v0 * g0.z + v1 * g1.z + v2 * g2.z + v3 * g3.z;
            acc[j].w += v0 * g0.w + v1 * g1.w + v2 * g2.w + v3 * g3.w;
        }
    }
    for (; p < e; p++) {
        int   c = __ldg(&scol[p]);
        float v = __ldg(&sval[p]);
        const float4* b = (const float4*)(sup + (size_t)c * D);
        #pragma unroll
        for (int j = 0; j < J; j++) {
            float4 g = __ldg(&b[j * 32 + lane]);
            acc[j].x += v * g.x;
            acc[j].y += v * g.y;
            acc[j].z += v * g.z;
            acc[j].w += v * g.w;
        }
    }

    const float4* bp = (const float4*)bias;
    #pragma unroll
    for (int j = 0; j < J; j++) {
        float4 b = __ldg(&bp[j * 32 + lane]);
        float rx = acc[j].x + b.x, ry = acc[j].y + b.y;
        float rz = acc[j].z + b.z, rw = acc[j].w + b.w;
        rx = (rx > 0.f) ? rx : GCN_SLOPE * rx;
        ry = (ry > 0.f) ? ry : GCN_SLOPE * ry;
        rz = (rz > 0.f) ? rz : GCN_SLOPE * rz;
        rw = (rw > 0.f) ? rw : GCN_SLOPE * rw;
        if (SPLIT) {
            __half hx = __float2half_rn(rx), hy = __float2half_rn(ry);
            __half hz = __float2half_rn(rz), hw = __float2half_rn(rw);
            __half2 hA = __halves2half2(hx, hy), hB = __halves2half2(hz, hw);
            __half2 lA = __halves2half2(__float2half_rn(rx - __half2float(hx)),
                                        __float2half_rn(ry - __half2float(hy)));
            __half2 lB = __halves2half2(__float2half_rn(rz - __half2float(hz)),
                                        __float2half_rn(rw - __half2float(hw)));
            __half* rp = outa + (size_t)warp * 512;
            int col = (j * 32 + lane) * 4;
            *(__half2*)(rp + col)         = hA;
            *(__half2*)(rp + col + 2)     = hB;
            *(__half2*)(rp + col + 256)   = lA;
            *(__half2*)(rp + col + 258)   = lB;
        } else {
            float4* o = (float4*)(outf + (size_t)warp * D);
            o[j * 32 + lane] = make_float4(rx, ry, rz, rw);
        }
    }
}

// ---------------- launch ----------------
extern "C" void kernel_launch(void* const* d_in, const int* in_sizes, int n_in,
                              void* d_out, int out_size) {
    const float* x    = (const float*)d_in[0];
    const int*   rows = (const int*)  d_in[1];
    const int*   cols = (const int*)  d_in[2];
    const float* vals = (const float*)d_in[3];
    const float* W1   = (const float*)d_in[4];
    const float* b1   = (const float*)d_in[5];
    const float* W2   = (const float*)d_in[6];
    const float* b2   = (const float*)d_in[7];
    const float* W3   = (const float*)d_in[8];
    const float* b3   = (const float*)d_in[9];
    float* out = (float*)d_out;

    const int N = GCN_N;
    const int NNZ = GCN_NNZ;

    int *rowptr, *cursor, *scol;
    float *sval, *sup;
    __half *ap, *bp;
    cudaGetSymbolAddress((void**)&rowptr, g_rowptr);
    cudaGetSymbolAddress((void**)&cursor, g_cursor);
    cudaGetSymbolAddress((void**)&scol,   g_scol);
    cudaGetSymbolAddress((void**)&sval,   g_sval);
    cudaGetSymbolAddress((void**)&sup,    g_sup);
    cudaGetSymbolAddress((void**)&ap,     g_a);
    cudaGetSymbolAddress((void**)&bp,     g_b);

    const int SMEM_GEMM = 3 * (128 * 64 * 2) * 2;   // 96KB
    cudaFuncSetAttribute(gemm_mma, cudaFuncAttributeMaxDynamicSharedMemorySize, SMEM_GEMM);

    const int MTILES = (N + 127) / 128;   // 782
    int spmm_grid = (N + 7) / 8;

    // launches 1-3: conversions + CSR zero (gemm1 must be 4th for ncu capture)
    split_x_kernel<<<(N * 512 / 4 + 255) / 256, 256>>>(x, ap, N * 512 / 4);
    wsplit_kernel<<<(512 * 256 + 255) / 256, 256>>>(W1, bp, 512, 256);
    zero_kernel<<<(N + 255) / 256, 256>>>(cursor, N);

    // launch 4: layer-1 GEMM (K'=1024, N=256)  <- ncu capture slot
    gemm_mma<<<dim3(2, MTILES), 256, SMEM_GEMM>>>(ap, bp, sup, N, 256, 1024);

    // CSR build
    hist_kernel<<<(NNZ + 255) / 256, 256>>>(rows, cursor, NNZ);
    scan_kernel<<<1, 1024>>>(cursor, rowptr, cursor, N);
    scatter_kernel<<<(NNZ + 255) / 256, 256>>>(rows, cols, vals, cursor, scol, sval, NNZ);

    // layer 1 SpMM
    spmm_kernel<256, true><<<spmm_grid, 256>>>(sup, scol, sval, rowptr, b1, nullptr, ap, N);

    // layer 2: K'=512, N=256
    wsplit_kernel<<<(256 * 256 + 255) / 256, 256>>>(W2, bp, 256, 256);
    gemm_mma<<<dim3(2, MTILES), 256, SMEM_GEMM>>>(ap, bp, sup, N, 256, 512);
    spmm_kernel<256, true><<<spmm_grid, 256>>>(sup, scol, sval, rowptr, b2, nullptr, ap, N);

    // layer 3: K'=512, N=128 -> out
    wsplit_kernel<<<(256 * 128 + 255) / 256, 256>>>(W3, bp, 256, 128);
    gemm_mma<<<dim3(1, MTILES), 256, SMEM_GEMM>>>(ap, bp, sup, N, 128, 512);
    spmm_kernel<128, false><<<spmm_grid, 256>>>(sup, scol, sval, rowptr, b3, out, nullptr, N);
}

// round 6
// speedup vs baseline: 2.4694x; 1.3770x over previous
#include <cuda_runtime.h>
#include <cuda_fp16.h>
#include <cstdint>

#define GCN_N     100000
#define GCN_NNZ   3200000
#define GCN_SLOPE 0.25f

// ---------------- device scratch (static, allocation-free) ----------------
__device__ __align__(16) int    g_rowptr[GCN_N + 1];
__device__ __align__(16) int    g_cursor[GCN_N];
__device__ __align__(16) int    g_scol[GCN_NNZ];
__device__ __align__(16) float  g_sval[GCN_NNZ];
__device__ __align__(16) __half g_sup [(size_t)GCN_N * 256];   // GEMM output fp16
__device__ __align__(16) __half g_a[(size_t)GCN_N * 1024];     // A' = [hi | lo] fp16
__device__ __align__(16) __half g_b[256 * 1024];               // B' = [hi | hi] fp16

// ---------------- CSR build ----------------
__global__ void zero_kernel(int* p, int n) {
    int i = blockIdx.x * blockDim.x + threadIdx.x;
    if (i < n) p[i] = 0;
}
__global__ void hist_kernel(const int* __restrict__ rows, int* __restrict__ counts, int nnz) {
    int i = blockIdx.x * blockDim.x + threadIdx.x;
    if (i < nnz) atomicAdd(&counts[rows[i]], 1);
}
// exclusive scan; writes rowptr[0..n] and cursor[i] = rowptr[i]
__global__ void scan_kernel(const int* __restrict__ counts, int* __restrict__ rowptr,
                            int* __restrict__ cursor, int n) {
    __shared__ int wsum[32];
    int lane = threadIdx.x & 31;
    int wid  = threadIdx.x >> 5;
    int offset = 0;
    if (threadIdx.x == 0) rowptr[0] = 0;
    for (int base = 0; base < n; base += 1024) {
        int i = base + threadIdx.x;
        int v = (i < n) ? counts[i] : 0;
        int x = v;
        #pragma unroll
        for (int d = 1; d < 32; d <<= 1) {
            int y = __shfl_up_sync(0xffffffffu, x, d);
            if (lane >= d) x += y;
        }
        if (lane == 31) wsum[wid] = x;
        __syncthreads();
        if (wid == 0) {
            int t = wsum[lane];
            #pragma unroll
            for (int d = 1; d < 32; d <<= 1) {
                int y = __shfl_up_sync(0xffffffffu, t, d);
                if (lane >= d) t += y;
            }
            wsum[lane] = t;
        }
        __syncthreads();
        int incl = x + (wid > 0 ? wsum[wid - 1] : 0);
        if (i < n) {
            rowptr[i + 1] = offset + incl;
            cursor[i] = offset + incl - v;
        }
        offset += wsum[31];
        __syncthreads();
    }
}
__global__ void scatter_kernel(const int* __restrict__ rows, const int* __restrict__ cols,
                               const float* __restrict__ vals, int* __restrict__ cursor,
                               int* __restrict__ scol, float* __restrict__ sval, int nnz) {
    int i = blockIdx.x * blockDim.x + threadIdx.x;
    if (i < nnz) {
        int r = rows[i];
        int pos = atomicAdd(&cursor[r], 1);
        scol[pos] = cols[i];
        sval[pos] = vals[i];
    }
}

// ---------------- x -> A' fp16 split [hi(512) | lo(512)], stride 1024 ------
__global__ void split_x_kernel(const float* __restrict__ in, __half* __restrict__ ap, int n4) {
    int i = blockIdx.x * blockDim.x + threadIdx.x;
    if (i >= n4) return;
    float4 v = __ldg((const float4*)in + i);
    int row = i >> 7;
    int col = (i & 127) * 4;
    __half h0 = __float2half_rn(v.x), h1 = __float2half_rn(v.y);
    __half h2 = __float2half_rn(v.z), h3 = __float2half_rn(v.w);
    __half2 hA = __halves2half2(h0, h1), hB = __halves2half2(h2, h3);
    __half2 lA = __halves2half2(__float2half_rn(v.x - __half2float(h0)),
                                __float2half_rn(v.y - __half2float(h1)));
    __half2 lB = __halves2half2(__float2half_rn(v.z - __half2float(h2)),
                                __float2half_rn(v.w - __half2float(h3)));
    __half* rp = ap + (size_t)row * 1024;
    *(__half2*)(rp + col)         = hA;
    *(__half2*)(rp + col + 2)     = hB;
    *(__half2*)(rp + col + 512)   = lA;
    *(__half2*)(rp + col + 514)   = lB;
}

// W[K,N] -> B'[n] = [Wh(K) | Wh(K)], row stride 2K
__global__ void wsplit_kernel(const float* __restrict__ W, __half* __restrict__ bp,
                              int K, int N) {
    int idx = blockIdx.x * blockDim.x + threadIdx.x;
    if (idx >= K * N) return;
    int k = idx / N, n = idx % N;
    __half h = __float2half_rn(W[idx]);
    __half* rp = bp + (size_t)n * (2 * K);
    rp[k] = h;
    rp[K + k] = h;
}

// ---------------- fp16 GEMM via mma.sync (HMMA), cp.async pipeline ---------
// C[M,N] = A[M,K] @ B[N,K]^T ; fp16 out.
__global__ __launch_bounds__(256) void gemm_mma(const __half* __restrict__ A,
                                                const __half* __restrict__ B,
                                                __half* __restrict__ C,
                                                int M, int N, int K) {
    extern __shared__ char smem[];
    constexpr int STAGES = 3;
    constexpr int ABYTES = 128 * 64 * 2;
    constexpr int BBYTES = 128 * 64 * 2;
    uint32_t sa_base;
    asm("{ .reg .u64 t; cvta.to.shared.u64 t, %1; cvt.u32.u64 %0, t; }" : "=r"(sa_base) : "l"(smem));
    uint32_t sb_base = sa_base + STAGES * ABYTES;

    int tid = threadIdx.x;
    int wid = tid >> 5, lane = tid & 31;
    int wm = wid & 3, wn = wid >> 2;
    int m0 = blockIdx.y * 128, n0 = blockIdx.x * 128;
    int NC = K / 64;

    float d[2][8][4];
    #pragma unroll
    for (int mi = 0; mi < 2; mi++)
        #pragma unroll
        for (int nj = 0; nj < 8; nj++)
            #pragma unroll
            for (int q = 0; q < 4; q++) d[mi][nj][q] = 0.f;

    const __half* Abase = A + (size_t)m0 * K;
    const __half* Bbase = B + (size_t)n0 * K;

#define LOAD_STAGE(st, ch) do {                                                   \
        uint32_t _da = sa_base + (st) * ABYTES;                                   \
        uint32_t _db = sb_base + (st) * BBYTES;                                   \
        int _k0 = (ch) * 64;                                                      \
        _Pragma("unroll")                                                         \
        for (int _i = 0; _i < 4; _i++) {                                          \
            int _u = tid + _i * 256;                                              \
            int _r = _u >> 3, _c = _u & 7;                                        \
            uint32_t _off = (uint32_t)(_r * 128 + _c * 16);                       \
            _off ^= ((_off >> 3) & 0x70);                                         \
            const __half* _src = Abase + (size_t)_r * K + _k0 + _c * 8;           \
            uint32_t _sz = (m0 + _r < M) ? 16u : 0u;                              \
            if (m0 + _r >= M) _src = Abase + _k0;                                 \
            asm volatile("cp.async.cg.shared.global [%0], [%1], 16, %2;"          \
                :: "r"(_da + _off), "l"(_src), "r"(_sz));                         \
        }                                                                         \
        _Pragma("unroll")                                                         \
        for (int _i = 0; _i < 4; _i++) {                                          \
            int _u = tid + _i * 256;                                              \
            int _r = _u >> 3, _c = _u & 7;                                        \
            uint32_t _off = (uint32_t)(_r * 128 + _c * 16);                       \
            _off ^= ((_off >> 3) & 0x70);                                         \
            const __half* _src = Bbase + (size_t)_r * K + _k0 + _c * 8;           \
            asm volatile("cp.async.cg.shared.global [%0], [%1], 16;"              \
                :: "r"(_db + _off), "l"(_src));                                   \
        }                                                                         \
    } while (0)

    LOAD_STAGE(0, 0);
    asm volatile("cp.async.commit_group;");
    LOAD_STAGE(1, 1);
    asm volatile("cp.async.commit_group;");

    for (int c = 0; c < NC; c++) {
        asm volatile("cp.async.wait_group 1;");
        __syncthreads();
        if (c + 2 < NC) LOAD_STAGE((c + 2) % STAGES, c + 2);
        asm volatile("cp.async.commit_group;");

        uint32_t da = sa_base + (c % STAGES) * ABYTES;
        uint32_t db = sb_base + (c % STAGES) * BBYTES;
        #pragma unroll
        for (int kk = 0; kk < 4; kk++) {
            int k16 = kk * 16;
            uint32_t a[2][4];
            #pragma unroll
            for (int mi = 0; mi < 2; mi++) {
                int row = wm * 32 + mi * 16 + (lane & 15);
                int colB = (k16 + ((lane >> 4) << 3)) * 2;
                uint32_t off = (uint32_t)(row * 128 + colB);
                off ^= ((off >> 3) & 0x70);
                asm volatile("ldmatrix.sync.aligned.m8n8.x4.shared.b16 {%0,%1,%2,%3}, [%4];"
                    : "=r"(a[mi][0]), "=r"(a[mi][1]), "=r"(a[mi][2]), "=r"(a[mi][3])
                    : "r"(da + off));
            }
            uint32_t b[8][2];
            #pragma unroll
            for (int nj = 0; nj < 4; nj++) {
                int nrow = wn * 64 + nj * 16 + (lane & 7) + ((lane >> 4) << 3);
                int colB = (k16 + (((lane >> 3) & 1) << 3)) * 2;
                uint32_t off = (uint32_t)(nrow * 128 + colB);
                off ^= ((off >> 3) & 0x70);
                uint32_t r0, r1, r2, r3;
                asm volatile("ldmatrix.sync.aligned.m8n8.x4.shared.b16 {%0,%1,%2,%3}, [%4];"
                    : "=r"(r0), "=r"(r1), "=r"(r2), "=r"(r3) : "r"(db + off));
                b[nj * 2][0] = r0; b[nj * 2][1] = r1;
                b[nj * 2 + 1][0] = r2; b[nj * 2 + 1][1] = r3;
            }
            #pragma unroll
            for (int mi = 0; mi < 2; mi++)
                #pragma unroll
                for (int nj = 0; nj < 8; nj++)
                    asm volatile("mma.sync.aligned.m16n8k16.row.col.f32.f16.f16.f32 "
                        "{%0,%1,%2,%3}, {%4,%5,%6,%7}, {%8,%9}, {%0,%1,%2,%3};"
                        : "+f"(d[mi][nj][0]), "+f"(d[mi][nj][1]),
                          "+f"(d[mi][nj][2]), "+f"(d[mi][nj][3])
                        : "r"(a[mi][0]), "r"(a[mi][1]), "r"(a[mi][2]), "r"(a[mi][3]),
                          "r"(b[nj][0]), "r"(b[nj][1]));
        }
        __syncthreads();
    }
#undef LOAD_STAGE

    // epilogue: fp16 stores
    #pragma unroll
    for (int mi = 0; mi < 2; mi++) {
        int r0 = m0 + wm * 32 + mi * 16 + (lane >> 2);
        #pragma unroll
        for (int nj = 0; nj < 8; nj++) {
            int col = n0 + wn * 64 + nj * 8 + 2 * (lane & 3);
            if (r0 < M)
                *(__half2*)(C + (size_t)r0 * N + col) =
                    __floats2half2_rn(d[mi][nj][0], d[mi][nj][1]);
            if (r0 + 8 < M)
                *(__half2*)(C + (size_t)(r0 + 8) * N + col) =
                    __floats2half2_rn(d[mi][nj][2], d[mi][nj][3]);
        }
    }
}

// ---------------- SpMM (fp16 gather) + bias + leaky_relu -------------------
// warp per row; lane handles VEC = D/32 contiguous columns (one 16B or 8B load).
// SPLIT=true: writes fp16 A' rows [hi(256)|lo(256)], stride 512.
template <int D, bool SPLIT>
__global__ __launch_bounds__(256) void spmm_kernel(const __half* __restrict__ sup,
                                                   const int* __restrict__ scol,
                                                   const float* __restrict__ sval,
                                                   const int* __restrict__ rowptr,
                                                   const float* __restrict__ bias,
                                                   float* __restrict__ outf,
                                                   __half* __restrict__ outa,
                                                   int n) {
    int warp = (blockIdx.x * blockDim.x + threadIdx.x) >> 5;
    int lane = threadIdx.x & 31;
    if (warp >= n) return;
    int s = rowptr[warp];
    int e = rowptr[warp + 1];
    constexpr int VEC = D / 32;              // 8 (D=256) or 4 (D=128)
    float acc[VEC];
    #pragma unroll
    for (int q = 0; q < VEC; q++) acc[q] = 0.f;

    const int lanecol = lane * VEC;

#define GATHER(cc, vv) do {                                                        \
        const __half* _b = sup + (size_t)(cc) * D + lanecol;                       \
        if (VEC == 8) {                                                            \
            uint4 _r = __ldg((const uint4*)_b);                                    \
            const __half2* _h = (const __half2*)&_r;                               \
            _Pragma("unroll")                                                      \
            for (int _q = 0; _q < 4; _q++) {                                       \
                float2 _f = __half22float2(_h[_q]);                                \
                acc[2 * _q]     += (vv) * _f.x;                                    \
                acc[2 * _q + 1] += (vv) * _f.y;                                    \
            }                                                                      \
        } else {                                                                   \
            uint2 _r = __ldg((const uint2*)_b);                                    \
            const __half2* _h = (const __half2*)&_r;                               \
            _Pragma("unroll")                                                      \
            for (int _q = 0; _q < 2; _q++) {                                       \
                float2 _f = __half22float2(_h[_q]);                                \
                acc[2 * _q]     += (vv) * _f.x;                                    \
                acc[2 * _q + 1] += (vv) * _f.y;                                    \
            }                                                                      \
        }                                                                          \
    } while (0)

    int p = s;
    for (; p + 3 < e; p += 4) {
        int   c0 = __ldg(&scol[p]),     c1 = __ldg(&scol[p + 1]);
        int   c2 = __ldg(&scol[p + 2]), c3 = __ldg(&scol[p + 3]);
        float v0 = __ldg(&sval[p]),     v1 = __ldg(&sval[p + 1]);
        float v2 = __ldg(&sval[p + 2]), v3 = __ldg(&sval[p + 3]);
        GATHER(c0, v0); GATHER(c1, v1); GATHER(c2, v2); GATHER(c3, v3);
    }
    for (; p < e; p++) {
        int   c = __ldg(&scol[p]);
        float v = __ldg(&sval[p]);
        GATHER(c, v);
    }
#undef GATHER

    // bias + leaky
    float r[VEC];
    #pragma unroll
    for (int q = 0; q < VEC; q += 4) {
        float4 b = __ldg((const float4*)(bias + lanecol + q));
        r[q]     = acc[q]     + b.x;
        r[q + 1] = acc[q + 1] + b.y;
        r[q + 2] = acc[q + 2] + b.z;
        r[q + 3] = acc[q + 3] + b.w;
    }
    #pragma unroll
    for (int q = 0; q < VEC; q++) r[q] = (r[q] > 0.f) ? r[q] : GCN_SLOPE * r[q];

    if (SPLIT) {
        __half* rp = outa + (size_t)warp * 512;
        #pragma unroll
        for (int q = 0; q < VEC; q += 2) {
            __half h0 = __float2half_rn(r[q]), h1 = __float2half_rn(r[q + 1]);
            *(__half2*)(rp + lanecol + q)       = __halves2half2(h0, h1);
            *(__half2*)(rp + 256 + lanecol + q) = __halves2half2(
                __float2half_rn(r[q]     - __half2float(h0)),
                __float2half_rn(r[q + 1] - __half2float(h1)));
        }
    } else {
        float* o = outf + (size_t)warp * D + lanecol;
        #pragma unroll
        for (int q = 0; q < VEC; q += 4)
            *(float4*)(o + q) = make_float4(r[q], r[q + 1], r[q + 2], r[q + 3]);
    }
}

// ---------------- launch ----------------
extern "C" void kernel_launch(void* const* d_in, const int* in_sizes, int n_in,
                              void* d_out, int out_size) {
    const float* x    = (const float*)d_in[0];
    const int*   rows = (const int*)  d_in[1];
    const int*   cols = (const int*)  d_in[2];
    const float* vals = (const float*)d_in[3];
    const float* W1   = (const float*)d_in[4];
    const float* b1   = (const float*)d_in[5];
    const float* W2   = (const float*)d_in[6];
    const float* b2   = (const float*)d_in[7];
    const float* W3   = (const float*)d_in[8];
    const float* b3   = (const float*)d_in[9];
    float* out = (float*)d_out;

    const int N = GCN_N;
    const int NNZ = GCN_NNZ;

    int *rowptr, *cursor, *scol;
    float *sval;
    __half *sup, *ap, *bp;
    cudaGetSymbolAddress((void**)&rowptr, g_rowptr);
    cudaGetSymbolAddress((void**)&cursor, g_cursor);
    cudaGetSymbolAddress((void**)&scol,   g_scol);
    cudaGetSymbolAddress((void**)&sval,   g_sval);
    cudaGetSymbolAddress((void**)&sup,    g_sup);
    cudaGetSymbolAddress((void**)&ap,     g_a);
    cudaGetSymbolAddress((void**)&bp,     g_b);

    const int SMEM_GEMM = 3 * (128 * 64 * 2) * 2;   // 96KB
    cudaFuncSetAttribute(gemm_mma, cudaFuncAttributeMaxDynamicSharedMemorySize, SMEM_GEMM);

    const int MTILES = (N + 127) / 128;   // 782
    int spmm_grid = (N + 7) / 8;

    // launches 1-3 (gemm1 must be 4th for the ncu capture slot)
    split_x_kernel<<<(N * 512 / 4 + 255) / 256, 256>>>(x, ap, N * 512 / 4);
    wsplit_kernel<<<(512 * 256 + 255) / 256, 256>>>(W1, bp, 512, 256);
    zero_kernel<<<(N + 255) / 256, 256>>>(cursor, N);

    // launch 4: layer-1 GEMM (K'=1024, N=256)  <- ncu capture slot
    gemm_mma<<<dim3(2, MTILES), 256, SMEM_GEMM>>>(ap, bp, sup, N, 256, 1024);

    // CSR build
    hist_kernel<<<(NNZ + 255) / 256, 256>>>(rows, cursor, NNZ);
    scan_kernel<<<1, 1024>>>(cursor, rowptr, cursor, N);
    scatter_kernel<<<(NNZ + 255) / 256, 256>>>(rows, cols, vals, cursor, scol, sval, NNZ);

    // layer 1 SpMM
    spmm_kernel<256, true><<<spmm_grid, 256>>>(sup, scol, sval, rowptr, b1, nullptr, ap, N);

    // layer 2: K'=512, N=256
    wsplit_kernel<<<(256 * 256 + 255) / 256, 256>>>(W2, bp, 256, 256);
    gemm_mma<<<dim3(2, MTILES), 256, SMEM_GEMM>>>(ap, bp, sup, N, 256, 512);
    spmm_kernel<256, true><<<spmm_grid, 256>>>(sup, scol, sval, rowptr, b2, nullptr, ap, N);

    // layer 3: K'=512, N=128 -> out (fp32)
    wsplit_kernel<<<(256 * 128 + 255) / 256, 256>>>(W3, bp, 256, 128);
    gemm_mma<<<dim3(1, MTILES), 256, SMEM_GEMM>>>(ap, bp, sup, N, 128, 512);
    spmm_kernel<128, false><<<spmm_grid, 256>>>(sup, scol, sval, rowptr, b3, out, nullptr, N);
}

// round 7
// speedup vs baseline: 2.5502x; 1.0327x over previous
#include <cuda_runtime.h>
#include <cuda_fp16.h>
#include <cstdint>

#define GCN_N     100000
#define GCN_NNZ   3200000
#define GCN_SLOPE 0.25f

// ---------------- device scratch (static, allocation-free) ----------------
__device__ __align__(16) int    g_rowptr[GCN_N + 1];
__device__ __align__(16) int    g_cursor[GCN_N];
__device__ __align__(16) uint2  g_scv[GCN_NNZ];                // packed (col, val)
__device__ __align__(16) __half g_sup [(size_t)GCN_N * 256];   // GEMM output fp16
__device__ __align__(16) __half g_a[(size_t)GCN_N * 512];      // A' = [hi | lo] fp16 (layers 2/3)
__device__ __align__(16) __half g_b[256 * 1024];               // B' weights fp16

// ---------------- CSR build ----------------
__global__ void zero_kernel(int* p, int n) {
    int i = blockIdx.x * blockDim.x + threadIdx.x;
    if (i < n) p[i] = 0;
}
__global__ void hist_kernel(const int* __restrict__ rows, int* __restrict__ counts, int nnz) {
    int i = blockIdx.x * blockDim.x + threadIdx.x;
    if (i < nnz) atomicAdd(&counts[rows[i]], 1);
}
// exclusive scan; writes rowptr[0..n] and cursor[i] = rowptr[i]
__global__ void scan_kernel(const int* __restrict__ counts, int* __restrict__ rowptr,
                            int* __restrict__ cursor, int n) {
    __shared__ int wsum[32];
    int lane = threadIdx.x & 31;
    int wid  = threadIdx.x >> 5;
    int offset = 0;
    if (threadIdx.x == 0) rowptr[0] = 0;
    for (int base = 0; base < n; base += 1024) {
        int i = base + threadIdx.x;
        int v = (i < n) ? counts[i] : 0;
        int x = v;
        #pragma unroll
        for (int d = 1; d < 32; d <<= 1) {
            int y = __shfl_up_sync(0xffffffffu, x, d);
            if (lane >= d) x += y;
        }
        if (lane == 31) wsum[wid] = x;
        __syncthreads();
        if (wid == 0) {
            int t = wsum[lane];
            #pragma unroll
            for (int d = 1; d < 32; d <<= 1) {
                int y = __shfl_up_sync(0xffffffffu, t, d);
                if (lane >= d) t += y;
            }
            wsum[lane] = t;
        }
        __syncthreads();
        int incl = x + (wid > 0 ? wsum[wid - 1] : 0);
        if (i < n) {
            rowptr[i + 1] = offset + incl;
            cursor[i] = offset + incl - v;
        }
        offset += wsum[31];
        __syncthreads();
    }
}
__global__ void scatter_kernel(const int* __restrict__ rows, const int* __restrict__ cols,
                               const float* __restrict__ vals, int* __restrict__ cursor,
                               uint2* __restrict__ scv, int nnz) {
    int i = blockIdx.x * blockDim.x + threadIdx.x;
    if (i < nnz) {
        int r = rows[i];
        int pos = atomicAdd(&cursor[r], 1);
        scv[pos] = make_uint2((unsigned)cols[i], __float_as_uint(vals[i]));
    }
}

// W[K,N] -> B'[n] = [Wh(K)] row stride K (layer 1, fused gemm reads single copy)
__global__ void wsplit_single(const float* __restrict__ W, __half* __restrict__ bp,
                              int K, int N) {
    int idx = blockIdx.x * blockDim.x + threadIdx.x;
    if (idx >= K * N) return;
    int k = idx / N, n = idx % N;
    bp[(size_t)n * K + k] = __float2half_rn(W[idx]);
}
// W[K,N] -> B'[n] = [Wh(K) | Wh(K)], row stride 2K (layers 2/3, concat-K GEMM)
__global__ void wsplit_dup(const float* __restrict__ W, __half* __restrict__ bp,
                           int K, int N) {
    int idx = blockIdx.x * blockDim.x + threadIdx.x;
    if (idx >= K * N) return;
    int k = idx / N, n = idx % N;
    __half h = __float2half_rn(W[idx]);
    __half* rp = bp + (size_t)n * (2 * K);
    rp[k] = h;
    rp[K + k] = h;
}

// ---------------- layer-1 fused GEMM: C = (hi(x)+lo(x)) @ Wh^T -------------
// x fp32 [M,512], B fp16 [256,512] K-major, C fp16 [M,256].
// BM=64, BN=128, chunk = 64 fp32 cols (8 chunks), 2-stage cp.async,
// in-kernel fp32 -> fp16 hi/lo conversion, 256 threads, warp tile 32x32.
__global__ __launch_bounds__(256, 2) void gemm1_fused(const float* __restrict__ X,
                                                      const __half* __restrict__ B,
                                                      __half* __restrict__ C, int M) {
    extern __shared__ char smem[];
    constexpr int XROW = 272;                 // 256B row + 16B pad
    constexpr int XST  = 64 * XROW;           // 17408
    constexpr int OFF_HI = 2 * XST;           // 34816
    constexpr int OFF_LO = OFF_HI + 8192;     // 43008
    constexpr int OFF_B  = OFF_LO + 8192;     // 51200
    constexpr int BST = 128 * 128;            // 16384
    // total = 51200 + 2*16384 = 83968

    uint32_t sbase;
    asm("{ .reg .u64 t; cvta.to.shared.u64 t, %1; cvt.u32.u64 %0, t; }" : "=r"(sbase) : "l"(smem));

    int tid = threadIdx.x;
    int wid = tid >> 5, lane = tid & 31;
    int wm = wid & 1, wn = wid >> 1;          // 2 x 4 warp grid, warp tile 32x32
    int m0 = blockIdx.y * 64, n0 = blockIdx.x * 128;

    float d[2][4][4];
    #pragma unroll
    for (int mi = 0; mi < 2; mi++)
        #pragma unroll
        for (int nj = 0; nj < 4; nj++)
            #pragma unroll
            for (int q = 0; q < 4; q++) d[mi][nj][q] = 0.f;

    const float*  Xbase = X + (size_t)m0 * 512;
    const __half* Bbase = B + (size_t)n0 * 512;

#define LOAD_X(st, ch) do {                                                        \
        uint32_t _dx = sbase + (st) * XST;                                         \
        _Pragma("unroll")                                                          \
        for (int _i = 0; _i < 4; _i++) {                                           \
            int _u = tid + _i * 256;                                               \
            int _r = _u >> 4, _c = _u & 15;                                        \
            const float* _src = Xbase + (size_t)_r * 512 + (ch) * 64 + _c * 4;     \
            uint32_t _sz = (m0 + _r < M) ? 16u : 0u;                               \
            if (m0 + _r >= M) _src = Xbase + (ch) * 64;                            \
            asm volatile("cp.async.cg.shared.global [%0], [%1], 16, %2;"           \
                :: "r"(_dx + (uint32_t)(_r * XROW + _c * 16)), "l"(_src), "r"(_sz)); \
        }                                                                          \
    } while (0)
#define LOAD_B(st, ch) do {                                                        \
        uint32_t _db = sbase + OFF_B + (st) * BST;                                 \
        _Pragma("unroll")                                                          \
        for (int _i = 0; _i < 4; _i++) {                                           \
            int _u = tid + _i * 256;                                               \
            int _r = _u >> 3, _c = _u & 7;                                         \
            uint32_t _off = (uint32_t)(_r * 128 + _c * 16);                        \
            _off ^= ((_off >> 3) & 0x70);                                          \
            const __half* _src = Bbase + (size_t)_r * 512 + (ch) * 64 + _c * 8;    \
            asm volatile("cp.async.cg.shared.global [%0], [%1], 16;"               \
                :: "r"(_db + _off), "l"(_src));                                    \
        }                                                                          \
    } while (0)

    LOAD_X(0, 0); LOAD_B(0, 0);
    asm volatile("cp.async.commit_group;");

    for (int c = 0; c < 8; c++) {
        asm volatile("cp.async.wait_group 0;");
        __syncthreads();                       // load(c) visible; all warps done with mma(c-1)
        if (c + 1 < 8) {
            LOAD_X((c + 1) & 1, c + 1);
            LOAD_B((c + 1) & 1, c + 1);
            asm volatile("cp.async.commit_group;");
        }

        // convert xstage[c&1] -> hi/lo tiles (64 rows x 64 halves, SW128)
        {
            uint32_t xs = sbase + (c & 1) * XST;
            #pragma unroll
            for (int i = 0; i < 2; i++) {
                int u = tid + i * 256;         // 0..511 : 64 rows x 8 groups
                int r = u >> 3, g = u & 7;
                float4 fa = *(const float4*)(smem + (c & 1) * XST + r * XROW + g * 32);
                float4 fb = *(const float4*)(smem + (c & 1) * XST + r * XROW + g * 32 + 16);
                (void)xs;
                __half h0 = __float2half_rn(fa.x), h1 = __float2half_rn(fa.y);
                __half h2 = __float2half_rn(fa.z), h3 = __float2half_rn(fa.w);
                __half h4 = __float2half_rn(fb.x), h5 = __float2half_rn(fb.y);
                __half h6 = __float2half_rn(fb.z), h7 = __float2half_rn(fb.w);
                __half2 hv[4] = {__halves2half2(h0, h1), __halves2half2(h2, h3),
                                 __halves2half2(h4, h5), __halves2half2(h6, h7)};
                __half2 lv[4] = {
                    __halves2half2(__float2half_rn(fa.x - __half2float(h0)),
                                   __float2half_rn(fa.y - __half2float(h1))),
                    __halves2half2(__float2half_rn(fa.z - __half2float(h2)),
                                   __float2half_rn(fa.w - __half2float(h3))),
                    __halves2half2(__float2half_rn(fb.x - __half2float(h4)),
                                   __float2half_rn(fb.y - __half2float(h5))),
                    __halves2half2(__float2half_rn(fb.z - __half2float(h6)),
                                   __float2half_rn(fb.w - __half2float(h7)))};
                uint32_t off = (uint32_t)(r * 128 + g * 16);
                off ^= ((off >> 3) & 0x70);
                *(uint4*)(smem + OFF_HI + off) = *(uint4*)hv;
                *(uint4*)(smem + OFF_LO + off) = *(uint4*)lv;
            }
        }
        __syncthreads();

        uint32_t db = sbase + OFF_B + (c & 1) * BST;
        #pragma unroll
        for (int half = 0; half < 2; half++) {
            uint32_t da = sbase + (half == 0 ? OFF_HI : OFF_LO);
            #pragma unroll
            for (int kk = 0; kk < 4; kk++) {
                int k16 = kk * 16;
                uint32_t a[2][4];
                #pragma unroll
                for (int mi = 0; mi < 2; mi++) {
                    int row = wm * 32 + mi * 16 + (lane & 15);
                    int colB = (k16 + ((lane >> 4) << 3)) * 2;
                    uint32_t off = (uint32_t)(row * 128 + colB);
                    off ^= ((off >> 3) & 0x70);
                    asm volatile("ldmatrix.sync.aligned.m8n8.x4.shared.b16 {%0,%1,%2,%3}, [%4];"
                        : "=r"(a[mi][0]), "=r"(a[mi][1]), "=r"(a[mi][2]), "=r"(a[mi][3])
                        : "r"(da + off));
                }
                uint32_t b[4][2];
                #pragma unroll
                for (int nj = 0; nj < 2; nj++) {
                    int nrow = wn * 32 + nj * 16 + (lane & 7) + ((lane >> 4) << 3);
                    int colB = (k16 + (((lane >> 3) & 1) << 3)) * 2;
                    uint32_t off = (uint32_t)(nrow * 128 + colB);
                    off ^= ((off >> 3) & 0x70);
                    uint32_t r0, r1, r2, r3;
                    asm volatile("ldmatrix.sync.aligned.m8n8.x4.shared.b16 {%0,%1,%2,%3}, [%4];"
                        : "=r"(r0), "=r"(r1), "=r"(r2), "=r"(r3) : "r"(db + off));
                    b[nj * 2][0] = r0; b[nj * 2][1] = r1;
                    b[nj * 2 + 1][0] = r2; b[nj * 2 + 1][1] = r3;
                }
                #pragma unroll
                for (int mi = 0; mi < 2; mi++)
                    #pragma unroll
                    for (int nj = 0; nj < 4; nj++)
                        asm volatile("mma.sync.aligned.m16n8k16.row.col.f32.f16.f16.f32 "
                            "{%0,%1,%2,%3}, {%4,%5,%6,%7}, {%8,%9}, {%0,%1,%2,%3};"
                            : "+f"(d[mi][nj][0]), "+f"(d[mi][nj][1]),
                              "+f"(d[mi][nj][2]), "+f"(d[mi][nj][3])
                            : "r"(a[mi][0]), "r"(a[mi][1]), "r"(a[mi][2]), "r"(a[mi][3]),
                              "r"(b[nj][0]), "r"(b[nj][1]));
            }
        }
        __syncthreads();
    }
#undef LOAD_X
#undef LOAD_B

    #pragma unroll
    for (int mi = 0; mi < 2; mi++) {
        int r0 = m0 + wm * 32 + mi * 16 + (lane >> 2);
        #pragma unroll
        for (int nj = 0; nj < 4; nj++) {
            int col = n0 + wn * 32 + nj * 8 + 2 * (lane & 3);
            if (r0 < M)
                *(__half2*)(C + (size_t)r0 * 256 + col) =
                    __floats2half2_rn(d[mi][nj][0], d[mi][nj][1]);
            if (r0 + 8 < M)
                *(__half2*)(C + (size_t)(r0 + 8) * 256 + col) =
                    __floats2half2_rn(d[mi][nj][2], d[mi][nj][3]);
        }
    }
}

// ---------------- fp16 GEMM via mma.sync, cp.async (layers 2/3) ------------
// C[M,N] = A[M,K] @ B[N,K]^T ; fp16 out. BM=128, BN=128, BK=64, 3 stages.
__global__ __launch_bounds__(256) void gemm_mma(const __half* __restrict__ A,
                                                const __half* __restrict__ B,
                                                __half* __restrict__ C,
                                                int M, int N, int K) {
    extern __shared__ char smem[];
    constexpr int STAGES = 3;
    constexpr int ABYTES = 128 * 64 * 2;
    constexpr int BBYTES = 128 * 64 * 2;
    uint32_t sa_base;
    asm("{ .reg .u64 t; cvta.to.shared.u64 t, %1; cvt.u32.u64 %0, t; }" : "=r"(sa_base) : "l"(smem));
    uint32_t sb_base = sa_base + STAGES * ABYTES;

    int tid = threadIdx.x;
    int wid = tid >> 5, lane = tid & 31;
    int wm = wid & 3, wn = wid >> 2;
    int m0 = blockIdx.y * 128, n0 = blockIdx.x * 128;
    int NC = K / 64;

    float d[2][8][4];
    #pragma unroll
    for (int mi = 0; mi < 2; mi++)
        #pragma unroll
        for (int nj = 0; nj < 8; nj++)
            #pragma unroll
            for (int q = 0; q < 4; q++) d[mi][nj][q] = 0.f;

    const __half* Abase = A + (size_t)m0 * K;
    const __half* Bbase = B + (size_t)n0 * K;

#define LOAD_STAGE(st, ch) do {                                                   \
        uint32_t _da = sa_base + (st) * ABYTES;                                   \
        uint32_t _db = sb_base + (st) * BBYTES;                                   \
        int _k0 = (ch) * 64;                                                      \
        _Pragma("unroll")                                                         \
        for (int _i = 0; _i < 4; _i++) {                                          \
            int _u = tid + _i * 256;                                              \
            int _r = _u >> 3, _c = _u & 7;                                        \
            uint32_t _off = (uint32_t)(_r * 128 + _c * 16);                       \
            _off ^= ((_off >> 3) & 0x70);                                         \
            const __half* _src = Abase + (size_t)_r * K + _k0 + _c * 8;           \
            uint32_t _sz = (m0 + _r < M) ? 16u : 0u;                              \
            if (m0 + _r >= M) _src = Abase + _k0;                                 \
            asm volatile("cp.async.cg.shared.global [%0], [%1], 16, %2;"          \
                :: "r"(_da + _off), "l"(_src), "r"(_sz));                         \
        }                                                                         \
        _Pragma("unroll")                                                         \
        for (int _i = 0; _i < 4; _i++) {                                          \
            int _u = tid + _i * 256;                                              \
            int _r = _u >> 3, _c = _u & 7;                                        \
            uint32_t _off = (uint32_t)(_r * 128 + _c * 16);                       \
            _off ^= ((_off >> 3) & 0x70);                                         \
            const __half* _src = Bbase + (size_t)_r * K + _k0 + _c * 8;           \
            asm volatile("cp.async.cg.shared.global [%0], [%1], 16;"              \
                :: "r"(_db + _off), "l"(_src));                                   \
        }                                                                         \
    } while (0)

    LOAD_STAGE(0, 0);
    asm volatile("cp.async.commit_group;");
    LOAD_STAGE(1, 1);
    asm volatile("cp.async.commit_group;");

    for (int c = 0; c < NC; c++) {
        asm volatile("cp.async.wait_group 1;");
        __syncthreads();
        if (c + 2 < NC) LOAD_STAGE((c + 2) % STAGES, c + 2);
        asm volatile("cp.async.commit_group;");

        uint32_t da = sa_base + (c % STAGES) * ABYTES;
        uint32_t db = sb_base + (c % STAGES) * BBYTES;
        #pragma unroll
        for (int kk = 0; kk < 4; kk++) {
            int k16 = kk * 16;
            uint32_t a[2][4];
            #pragma unroll
            for (int mi = 0; mi < 2; mi++) {
                int row = wm * 32 + mi * 16 + (lane & 15);
                int colB = (k16 + ((lane >> 4) << 3)) * 2;
                uint32_t off = (uint32_t)(row * 128 + colB);
                off ^= ((off >> 3) & 0x70);
                asm volatile("ldmatrix.sync.aligned.m8n8.x4.shared.b16 {%0,%1,%2,%3}, [%4];"
                    : "=r"(a[mi][0]), "=r"(a[mi][1]), "=r"(a[mi][2]), "=r"(a[mi][3])
                    : "r"(da + off));
            }
            uint32_t b[8][2];
            #pragma unroll
            for (int nj = 0; nj < 4; nj++) {
                int nrow = wn * 64 + nj * 16 + (lane & 7) + ((lane >> 4) << 3);
                int colB = (k16 + (((lane >> 3) & 1) << 3)) * 2;
                uint32_t off = (uint32_t)(nrow * 128 + colB);
                off ^= ((off >> 3) & 0x70);
                uint32_t r0, r1, r2, r3;
                asm volatile("ldmatrix.sync.aligned.m8n8.x4.shared.b16 {%0,%1,%2,%3}, [%4];"
                    : "=r"(r0), "=r"(r1), "=r"(r2), "=r"(r3) : "r"(db + off));
                b[nj * 2][0] = r0; b[nj * 2][1] = r1;
                b[nj * 2 + 1][0] = r2; b[nj * 2 + 1][1] = r3;
            }
            #pragma unroll
            for (int mi = 0; mi < 2; mi++)
                #pragma unroll
                for (int nj = 0; nj < 8; nj++)
                    asm volatile("mma.sync.aligned.m16n8k16.row.col.f32.f16.f16.f32 "
                        "{%0,%1,%2,%3}, {%4,%5,%6,%7}, {%8,%9}, {%0,%1,%2,%3};"
                        : "+f"(d[mi][nj][0]), "+f"(d[mi][nj][1]),
                          "+f"(d[mi][nj][2]), "+f"(d[mi][nj][3])
                        : "r"(a[mi][0]), "r"(a[mi][1]), "r"(a[mi][2]), "r"(a[mi][3]),
                          "r"(b[nj][0]), "r"(b[nj][1]));
        }
        __syncthreads();
    }
#undef LOAD_STAGE

    #pragma unroll
    for (int mi = 0; mi < 2; mi++) {
        int r0 = m0 + wm * 32 + mi * 16 + (lane >> 2);
        #pragma unroll
        for (int nj = 0; nj < 8; nj++) {
            int col = n0 + wn * 64 + nj * 8 + 2 * (lane & 3);
            if (r0 < M)
                *(__half2*)(C + (size_t)r0 * N + col) =
                    __floats2half2_rn(d[mi][nj][0], d[mi][nj][1]);
            if (r0 + 8 < M)
                *(__half2*)(C + (size_t)(r0 + 8) * N + col) =
                    __floats2half2_rn(d[mi][nj][2], d[mi][nj][3]);
        }
    }
}

// ---------------- SpMM (fp16 gather, packed edges) + bias + leaky ----------
template <int D, bool SPLIT>
__global__ __launch_bounds__(256) void spmm_kernel(const __half* __restrict__ sup,
                                                   const uint2* __restrict__ scv,
                                                   const int* __restrict__ rowptr,
                                                   const float* __restrict__ bias,
                                                   float* __restrict__ outf,
                                                   __half* __restrict__ outa,
                                                   int n) {
    int warp = (blockIdx.x * blockDim.x + threadIdx.x) >> 5;
    int lane = threadIdx.x & 31;
    if (warp >= n) return;
    int s = rowptr[warp];
    int e = rowptr[warp + 1];
    constexpr int VEC = D / 32;
    float acc[VEC];
    #pragma unroll
    for (int q = 0; q < VEC; q++) acc[q] = 0.f;

    const int lanecol = lane * VEC;

#define GATHER(cc, vv) do {                                                        \
        const __half* _b = sup + (size_t)(cc) * D + lanecol;                       \
        if (VEC == 8) {                                                            \
            uint4 _r = __ldg((const uint4*)_b);                                    \
            const __half2* _h = (const __half2*)&_r;                               \
            _Pragma("unroll")                                                      \
            for (int _q = 0; _q < 4; _q++) {                                       \
                float2 _f = __half22float2(_h[_q]);                                \
                acc[2 * _q]     += (vv) * _f.x;                                    \
                acc[2 * _q + 1] += (vv) * _f.y;                                    \
            }                                                                      \
        } else {                                                                   \
            uint2 _r = __ldg((const uint2*)_b);                                    \
            const __half2* _h = (const __half2*)&_r;                               \
            _Pragma("unroll")                                                      \
            for (int _q = 0; _q < 2; _q++) {                                       \
                float2 _f = __half22float2(_h[_q]);                                \
                acc[2 * _q]     += (vv) * _f.x;                                    \
                acc[2 * _q + 1] += (vv) * _f.y;                                    \
            }                                                                      \
        }                                                                          \
    } while (0)

    int p = s;
    for (; p + 3 < e; p += 4) {
        uint2 e0 = __ldg(&scv[p]),     e1 = __ldg(&scv[p + 1]);
        uint2 e2 = __ldg(&scv[p + 2]), e3 = __ldg(&scv[p + 3]);
        GATHER(e0.x, __uint_as_float(e0.y));
        GATHER(e1.x, __uint_as_float(e1.y));
        GATHER(e2.x, __uint_as_float(e2.y));
        GATHER(e3.x, __uint_as_float(e3.y));
    }
    for (; p < e; p++) {
        uint2 ee = __ldg(&scv[p]);
        GATHER(ee.x, __uint_as_float(ee.y));
    }
#undef GATHER

    float r[VEC];
    #pragma unroll
    for (int q = 0; q < VEC; q += 4) {
        float4 b = __ldg((const float4*)(bias + lanecol + q));
        r[q]     = acc[q]     + b.x;
        r[q + 1] = acc[q + 1] + b.y;
        r[q + 2] = acc[q + 2] + b.z;
        r[q + 3] = acc[q + 3] + b.w;
    }
    #pragma unroll
    for (int q = 0; q < VEC; q++) r[q] = (r[q] > 0.f) ? r[q] : GCN_SLOPE * r[q];

    if (SPLIT) {
        __half* rp = outa + (size_t)warp * 512;
        #pragma unroll
        for (int q = 0; q < VEC; q += 2) {
            __half h0 = __float2half_rn(r[q]), h1 = __float2half_rn(r[q + 1]);
            *(__half2*)(rp + lanecol + q)       = __halves2half2(h0, h1);
            *(__half2*)(rp + 256 + lanecol + q) = __halves2half2(
                __float2half_rn(r[q]     - __half2float(h0)),
                __float2half_rn(r[q + 1] - __half2float(h1)));
        }
    } else {
        float* o = outf + (size_t)warp * D + lanecol;
        #pragma unroll
        for (int q = 0; q < VEC; q += 4)
            *(float4*)(o + q) = make_float4(r[q], r[q + 1], r[q + 2], r[q + 3]);
    }
}

// ---------------- launch ----------------
extern "C" void kernel_launch(void* const* d_in, const int* in_sizes, int n_in,
                              void* d_out, int out_size) {
    const float* x    = (const float*)d_in[0];
    const int*   rows = (const int*)  d_in[1];
    const int*   cols = (const int*)  d_in[2];
    const float* vals = (const float*)d_in[3];
    const float* W1   = (const float*)d_in[4];
    const float* b1   = (const float*)d_in[5];
    const float* W2   = (const float*)d_in[6];
    const float* b2   = (const float*)d_in[7];
    const float* W3   = (const float*)d_in[8];
    const float* b3   = (const float*)d_in[9];
    float* out = (float*)d_out;

    const int N = GCN_N;
    const int NNZ = GCN_NNZ;

    int *rowptr, *cursor;
    uint2* scv;
    __half *sup, *ap, *bp;
    cudaGetSymbolAddress((void**)&rowptr, g_rowptr);
    cudaGetSymbolAddress((void**)&cursor, g_cursor);
    cudaGetSymbolAddress((void**)&scv,    g_scv);
    cudaGetSymbolAddress((void**)&sup,    g_sup);
    cudaGetSymbolAddress((void**)&ap,     g_a);
    cudaGetSymbolAddress((void**)&bp,     g_b);

    const int SMEM_GEMM  = 3 * (128 * 64 * 2) * 2;   // 96KB (gemm_mma)
    const int SMEM_FUSED = 83968;                    // gemm1_fused
    cudaFuncSetAttribute(gemm_mma,   cudaFuncAttributeMaxDynamicSharedMemorySize, SMEM_GEMM);
    cudaFuncSetAttribute(gemm1_fused, cudaFuncAttributeMaxDynamicSharedMemorySize, SMEM_FUSED);

    const int MT128 = (N + 127) / 128;   // 782
    const int MT64  = (N + 63) / 64;     // 1563
    int spmm_grid = (N + 7) / 8;

    // launches 1-3 (gemm1_fused must be 4th for the ncu capture slot)
    wsplit_single<<<(512 * 256 + 255) / 256, 256>>>(W1, bp, 512, 256);
    zero_kernel<<<(N + 255) / 256, 256>>>(cursor, N);
    hist_kernel<<<(NNZ + 255) / 256, 256>>>(rows, cursor, NNZ);

    // launch 4: fused layer-1 GEMM (reads fp32 x directly)  <- ncu capture slot
    gemm1_fused<<<dim3(2, MT64), 256, SMEM_FUSED>>>(x, bp, sup, N);

    // CSR finish
    scan_kernel<<<1, 1024>>>(cursor, rowptr, cursor, N);
    scatter_kernel<<<(NNZ + 255) / 256, 256>>>(rows, cols, vals, cursor, scv, NNZ);

    // layer 1 SpMM -> A'
    spmm_kernel<256, true><<<spmm_grid, 256>>>(sup, scv, rowptr, b1, nullptr, ap, N);

    // layer 2: K'=512, N=256
    wsplit_dup<<<(256 * 256 + 255) / 256, 256>>>(W2, bp, 256, 256);
    gemm_mma<<<dim3(2, MT128), 256, SMEM_GEMM>>>(ap, bp, sup, N, 256, 512);
    spmm_kernel<256, true><<<spmm_grid, 256>>>(sup, scv, rowptr, b2, nullptr, ap, N);

    // layer 3: K'=512, N=128 -> out (fp32)
    wsplit_dup<<<(256 * 128 + 255) / 256, 256>>>(W3, bp, 256, 128);
    gemm_mma<<<dim3(1, MT128), 256, SMEM_GEMM>>>(ap, bp, sup, N, 128, 512);
    spmm_kernel<128, false><<<spmm_grid, 256>>>(sup, scv, rowptr, b3, out, nullptr, N);
}

// round 8
// speedup vs baseline: 2.9695x; 1.1645x over previous
#include <cuda_runtime.h>
#include <cuda_fp16.h>
#include <cstdint>

#define GCN_N     100000
#define GCN_NNZ   3200000
#define GCN_SLOPE 0.25f

// ---------------- device scratch (static, allocation-free) ----------------
__device__ __align__(16) int    g_rowptr[GCN_N + 1];
__device__ __align__(16) int    g_cursor[GCN_N];
__device__ __align__(16) uint2  g_scv[GCN_NNZ];                // packed (col, val)
__device__ __align__(16) __half g_sup [(size_t)GCN_N * 256];   // GEMM output fp16
__device__ __align__(16) __half g_a[(size_t)GCN_N * 256];      // activations fp16
__device__ __align__(16) __half g_b[256 * 512];                // weights fp16 [N,K]

// ---------------- CSR build ----------------
__global__ void zero_kernel(int* p, int n) {
    int i = blockIdx.x * blockDim.x + threadIdx.x;
    if (i < n) p[i] = 0;
}
__global__ void hist_kernel(const int* __restrict__ rows, int* __restrict__ counts, int nnz) {
    int i = blockIdx.x * blockDim.x + threadIdx.x;
    if (i < nnz) atomicAdd(&counts[rows[i]], 1);
}
// exclusive scan; writes rowptr[0..n] and cursor[i] = rowptr[i]
__global__ void scan_kernel(const int* __restrict__ counts, int* __restrict__ rowptr,
                            int* __restrict__ cursor, int n) {
    __shared__ int wsum[32];
    int lane = threadIdx.x & 31;
    int wid  = threadIdx.x >> 5;
    int offset = 0;
    if (threadIdx.x == 0) rowptr[0] = 0;
    for (int base = 0; base < n; base += 1024) {
        int i = base + threadIdx.x;
        int v = (i < n) ? counts[i] : 0;
        int x = v;
        #pragma unroll
        for (int d = 1; d < 32; d <<= 1) {
            int y = __shfl_up_sync(0xffffffffu, x, d);
            if (lane >= d) x += y;
        }
        if (lane == 31) wsum[wid] = x;
        __syncthreads();
        if (wid == 0) {
            int t = wsum[lane];
            #pragma unroll
            for (int d = 1; d < 32; d <<= 1) {
                int y = __shfl_up_sync(0xffffffffu, t, d);
                if (lane >= d) t += y;
            }
            wsum[lane] = t;
        }
        __syncthreads();
        int incl = x + (wid > 0 ? wsum[wid - 1] : 0);
        if (i < n) {
            rowptr[i + 1] = offset + incl;
            cursor[i] = offset + incl - v;
        }
        offset += wsum[31];
        __syncthreads();
    }
}
__global__ void scatter_kernel(const int* __restrict__ rows, const int* __restrict__ cols,
                               const float* __restrict__ vals, int* __restrict__ cursor,
                               uint2* __restrict__ scv, int nnz) {
    int i = blockIdx.x * blockDim.x + threadIdx.x;
    if (i < nnz) {
        int r = rows[i];
        int pos = atomicAdd(&cursor[r], 1);
        scv[pos] = make_uint2((unsigned)cols[i], __float_as_uint(vals[i]));
    }
}

// W[K,N] -> B[n,k] fp16 (transpose)
__global__ void wsplit_single(const float* __restrict__ W, __half* __restrict__ bp,
                              int K, int N) {
    int idx = blockIdx.x * blockDim.x + threadIdx.x;
    if (idx >= K * N) return;
    int k = idx / N, n = idx % N;
    bp[(size_t)n * K + k] = __float2half_rn(W[idx]);
}

// ---------------- layer-1 fused GEMM: C = fp16(x) @ Wh^T -------------------
// x fp32 [M,512], B fp16 [256,512] K-major, C fp16 [M,256].
// BM=64, BN=128, chunk=64 fp32 cols (8 chunks), 2-stage cp.async,
// in-kernel fp32 -> fp16 conversion, 256 threads, warp tile 32x32.
__global__ __launch_bounds__(256, 2) void gemm1_fused(const float* __restrict__ X,
                                                      const __half* __restrict__ B,
                                                      __half* __restrict__ C, int M) {
    extern __shared__ char smem[];
    constexpr int XROW = 272;                 // 256B row + 16B pad
    constexpr int XST  = 64 * XROW;           // 17408
    constexpr int OFF_HI = 2 * XST;           // 34816
    constexpr int OFF_B  = OFF_HI + 8192;     // 43008
    constexpr int BST = 128 * 128;            // 16384
    // total = 43008 + 2*16384 = 75776

    uint32_t sbase;
    asm("{ .reg .u64 t; cvta.to.shared.u64 t, %1; cvt.u32.u64 %0, t; }" : "=r"(sbase) : "l"(smem));

    int tid = threadIdx.x;
    int wid = tid >> 5, lane = tid & 31;
    int wm = wid & 1, wn = wid >> 1;          // 2 x 4 warp grid, warp tile 32x32
    int m0 = blockIdx.y * 64, n0 = blockIdx.x * 128;

    float d[2][4][4];
    #pragma unroll
    for (int mi = 0; mi < 2; mi++)
        #pragma unroll
        for (int nj = 0; nj < 4; nj++)
            #pragma unroll
            for (int q = 0; q < 4; q++) d[mi][nj][q] = 0.f;

    const float*  Xbase = X + (size_t)m0 * 512;
    const __half* Bbase = B + (size_t)n0 * 512;

#define LOAD_X(st, ch) do {                                                        \
        uint32_t _dx = sbase + (st) * XST;                                         \
        _Pragma("unroll")                                                          \
        for (int _i = 0; _i < 4; _i++) {                                           \
            int _u = tid + _i * 256;                                               \
            int _r = _u >> 4, _c = _u & 15;                                        \
            const float* _src = Xbase + (size_t)_r * 512 + (ch) * 64 + _c * 4;     \
            uint32_t _sz = (m0 + _r < M) ? 16u : 0u;                               \
            if (m0 + _r >= M) _src = Xbase + (ch) * 64;                            \
            asm volatile("cp.async.cg.shared.global [%0], [%1], 16, %2;"           \
                :: "r"(_dx + (uint32_t)(_r * XROW + _c * 16)), "l"(_src), "r"(_sz)); \
        }                                                                          \
    } while (0)
#define LOAD_B(st, ch) do {                                                        \
        uint32_t _db = sbase + OFF_B + (st) * BST;                                 \
        _Pragma("unroll")                                                          \
        for (int _i = 0; _i < 4; _i++) {                                           \
            int _u = tid + _i * 256;                                               \
            int _r = _u >> 3, _c = _u & 7;                                         \
            uint32_t _off = (uint32_t)(_r * 128 + _c * 16);                        \
            _off ^= ((_off >> 3) & 0x70);                                          \
            const __half* _src = Bbase + (size_t)_r * 512 + (ch) * 64 + _c * 8;    \
            asm volatile("cp.async.cg.shared.global [%0], [%1], 16;"               \
                :: "r"(_db + _off), "l"(_src));                                    \
        }                                                                          \
    } while (0)

    LOAD_X(0, 0); LOAD_B(0, 0);
    asm volatile("cp.async.commit_group;");

    for (int c = 0; c < 8; c++) {
        asm volatile("cp.async.wait_group 0;");
        __syncthreads();
        if (c + 1 < 8) {
            LOAD_X((c + 1) & 1, c + 1);
            LOAD_B((c + 1) & 1, c + 1);
            asm volatile("cp.async.commit_group;");
        }

        // convert xstage[c&1] -> fp16 tile (64 rows x 64 halves, SW128)
        #pragma unroll
        for (int i = 0; i < 2; i++) {
            int u = tid + i * 256;             // 0..511 : 64 rows x 8 groups
            int r = u >> 3, g = u & 7;
            float4 fa = *(const float4*)(smem + (c & 1) * XST + r * XROW + g * 32);
            float4 fb = *(const float4*)(smem + (c & 1) * XST + r * XROW + g * 32 + 16);
            __half2 hv[4] = {__floats2half2_rn(fa.x, fa.y), __floats2half2_rn(fa.z, fa.w),
                             __floats2half2_rn(fb.x, fb.y), __floats2half2_rn(fb.z, fb.w)};
            uint32_t off = (uint32_t)(r * 128 + g * 16);
            off ^= ((off >> 3) & 0x70);
            *(uint4*)(smem + OFF_HI + off) = *(uint4*)hv;
        }
        __syncthreads();

        uint32_t da = sbase + OFF_HI;
        uint32_t db = sbase + OFF_B + (c & 1) * BST;
        #pragma unroll
        for (int kk = 0; kk < 4; kk++) {
            int k16 = kk * 16;
            uint32_t a[2][4];
            #pragma unroll
            for (int mi = 0; mi < 2; mi++) {
                int row = wm * 32 + mi * 16 + (lane & 15);
                int colB = (k16 + ((lane >> 4) << 3)) * 2;
                uint32_t off = (uint32_t)(row * 128 + colB);
                off ^= ((off >> 3) & 0x70);
                asm volatile("ldmatrix.sync.aligned.m8n8.x4.shared.b16 {%0,%1,%2,%3}, [%4];"
                    : "=r"(a[mi][0]), "=r"(a[mi][1]), "=r"(a[mi][2]), "=r"(a[mi][3])
                    : "r"(da + off));
            }
            uint32_t b[4][2];
            #pragma unroll
            for (int nj = 0; nj < 2; nj++) {
                int nrow = wn * 32 + nj * 16 + (lane & 7) + ((lane >> 4) << 3);
                int colB = (k16 + (((lane >> 3) & 1) << 3)) * 2;
                uint32_t off = (uint32_t)(nrow * 128 + colB);
                off ^= ((off >> 3) & 0x70);
                uint32_t r0, r1, r2, r3;
                asm volatile("ldmatrix.sync.aligned.m8n8.x4.shared.b16 {%0,%1,%2,%3}, [%4];"
                    : "=r"(r0), "=r"(r1), "=r"(r2), "=r"(r3) : "r"(db + off));
                b[nj * 2][0] = r0; b[nj * 2][1] = r1;
                b[nj * 2 + 1][0] = r2; b[nj * 2 + 1][1] = r3;
            }
            #pragma unroll
            for (int mi = 0; mi < 2; mi++)
                #pragma unroll
                for (int nj = 0; nj < 4; nj++)
                    asm volatile("mma.sync.aligned.m16n8k16.row.col.f32.f16.f16.f32 "
                        "{%0,%1,%2,%3}, {%4,%5,%6,%7}, {%8,%9}, {%0,%1,%2,%3};"
                        : "+f"(d[mi][nj][0]), "+f"(d[mi][nj][1]),
                          "+f"(d[mi][nj][2]), "+f"(d[mi][nj][3])
                        : "r"(a[mi][0]), "r"(a[mi][1]), "r"(a[mi][2]), "r"(a[mi][3]),
                          "r"(b[nj][0]), "r"(b[nj][1]));
        }
        __syncthreads();
    }
#undef LOAD_X
#undef LOAD_B

    #pragma unroll
    for (int mi = 0; mi < 2; mi++) {
        int r0 = m0 + wm * 32 + mi * 16 + (lane >> 2);
        #pragma unroll
        for (int nj = 0; nj < 4; nj++) {
            int col = n0 + wn * 32 + nj * 8 + 2 * (lane & 3);
            if (r0 < M)
                *(__half2*)(C + (size_t)r0 * 256 + col) =
                    __floats2half2_rn(d[mi][nj][0], d[mi][nj][1]);
            if (r0 + 8 < M)
                *(__half2*)(C + (size_t)(r0 + 8) * 256 + col) =
                    __floats2half2_rn(d[mi][nj][2], d[mi][nj][3]);
        }
    }
}

// ---------------- fp16 GEMM via mma.sync, cp.async (layers 2/3) ------------
// C[M,N] = A[M,K] @ B[N,K]^T ; fp16 out. BM=128, BN=128, BK=64, 3 stages.
__global__ __launch_bounds__(256) void gemm_mma(const __half* __restrict__ A,
                                                const __half* __restrict__ B,
                                                __half* __restrict__ C,
                                                int M, int N, int K) {
    extern __shared__ char smem[];
    constexpr int STAGES = 3;
    constexpr int ABYTES = 128 * 64 * 2;
    constexpr int BBYTES = 128 * 64 * 2;
    uint32_t sa_base;
    asm("{ .reg .u64 t; cvta.to.shared.u64 t, %1; cvt.u32.u64 %0, t; }" : "=r"(sa_base) : "l"(smem));
    uint32_t sb_base = sa_base + STAGES * ABYTES;

    int tid = threadIdx.x;
    int wid = tid >> 5, lane = tid & 31;
    int wm = wid & 3, wn = wid >> 2;
    int m0 = blockIdx.y * 128, n0 = blockIdx.x * 128;
    int NC = K / 64;

    float d[2][8][4];
    #pragma unroll
    for (int mi = 0; mi < 2; mi++)
        #pragma unroll
        for (int nj = 0; nj < 8; nj++)
            #pragma unroll
            for (int q = 0; q < 4; q++) d[mi][nj][q] = 0.f;

    const __half* Abase = A + (size_t)m0 * K;
    const __half* Bbase = B + (size_t)n0 * K;

#define LOAD_STAGE(st, ch) do {                                                   \
        uint32_t _da = sa_base + (st) * ABYTES;                                   \
        uint32_t _db = sb_base + (st) * BBYTES;                                   \
        int _k0 = (ch) * 64;                                                      \
        _Pragma("unroll")                                                         \
        for (int _i = 0; _i < 4; _i++) {                                          \
            int _u = tid + _i * 256;                                              \
            int _r = _u >> 3, _c = _u & 7;                                        \
            uint32_t _off = (uint32_t)(_r * 128 + _c * 16);                       \
            _off ^= ((_off >> 3) & 0x70);                                         \
            const __half* _src = Abase + (size_t)_r * K + _k0 + _c * 8;           \
            uint32_t _sz = (m0 + _r < M) ? 16u : 0u;                              \
            if (m0 + _r >= M) _src = Abase + _k0;                                 \
            asm volatile("cp.async.cg.shared.global [%0], [%1], 16, %2;"          \
                :: "r"(_da + _off), "l"(_src), "r"(_sz));                         \
        }                                                                         \
        _Pragma("unroll")                                                         \
        for (int _i = 0; _i < 4; _i++) {                                          \
            int _u = tid + _i * 256;                                              \
            int _r = _u >> 3, _c = _u & 7;                                        \
            uint32_t _off = (uint32_t)(_r * 128 + _c * 16);                       \
            _off ^= ((_off >> 3) & 0x70);                                         \
            const __half* _src = Bbase + (size_t)_r * K + _k0 + _c * 8;           \
            asm volatile("cp.async.cg.shared.global [%0], [%1], 16;"              \
                :: "r"(_db + _off), "l"(_src));                                   \
        }                                                                         \
    } while (0)

    LOAD_STAGE(0, 0);
    asm volatile("cp.async.commit_group;");
    if (NC > 1) LOAD_STAGE(1, 1);
    asm volatile("cp.async.commit_group;");

    for (int c = 0; c < NC; c++) {
        asm volatile("cp.async.wait_group 1;");
        __syncthreads();
        if (c + 2 < NC) LOAD_STAGE((c + 2) % STAGES, c + 2);
        asm volatile("cp.async.commit_group;");

        uint32_t da = sa_base + (c % STAGES) * ABYTES;
        uint32_t db = sb_base + (c % STAGES) * BBYTES;
        #pragma unroll
        for (int kk = 0; kk < 4; kk++) {
            int k16 = kk * 16;
            uint32_t a[2][4];
            #pragma unroll
            for (int mi = 0; mi < 2; mi++) {
                int row = wm * 32 + mi * 16 + (lane & 15);
                int colB = (k16 + ((lane >> 4) << 3)) * 2;
                uint32_t off = (uint32_t)(row * 128 + colB);
                off ^= ((off >> 3) & 0x70);
                asm volatile("ldmatrix.sync.aligned.m8n8.x4.shared.b16 {%0,%1,%2,%3}, [%4];"
                    : "=r"(a[mi][0]), "=r"(a[mi][1]), "=r"(a[mi][2]), "=r"(a[mi][3])
                    : "r"(da + off));
            }
            uint32_t b[8][2];
            #pragma unroll
            for (int nj = 0; nj < 4; nj++) {
                int nrow = wn * 64 + nj * 16 + (lane & 7) + ((lane >> 4) << 3);
                int colB = (k16 + (((lane >> 3) & 1) << 3)) * 2;
                uint32_t off = (uint32_t)(nrow * 128 + colB);
                off ^= ((off >> 3) & 0x70);
                uint32_t r0, r1, r2, r3;
                asm volatile("ldmatrix.sync.aligned.m8n8.x4.shared.b16 {%0,%1,%2,%3}, [%4];"
                    : "=r"(r0), "=r"(r1), "=r"(r2), "=r"(r3) : "r"(db + off));
                b[nj * 2][0] = r0; b[nj * 2][1] = r1;
                b[nj * 2 + 1][0] = r2; b[nj * 2 + 1][1] = r3;
            }
            #pragma unroll
            for (int mi = 0; mi < 2; mi++)
                #pragma unroll
                for (int nj = 0; nj < 8; nj++)
                    asm volatile("mma.sync.aligned.m16n8k16.row.col.f32.f16.f16.f32 "
                        "{%0,%1,%2,%3}, {%4,%5,%6,%7}, {%8,%9}, {%0,%1,%2,%3};"
                        : "+f"(d[mi][nj][0]), "+f"(d[mi][nj][1]),
                          "+f"(d[mi][nj][2]), "+f"(d[mi][nj][3])
                        : "r"(a[mi][0]), "r"(a[mi][1]), "r"(a[mi][2]), "r"(a[mi][3]),
                          "r"(b[nj][0]), "r"(b[nj][1]));
        }
        __syncthreads();
    }
#undef LOAD_STAGE

    #pragma unroll
    for (int mi = 0; mi < 2; mi++) {
        int r0 = m0 + wm * 32 + mi * 16 + (lane >> 2);
        #pragma unroll
        for (int nj = 0; nj < 8; nj++) {
            int col = n0 + wn * 64 + nj * 8 + 2 * (lane & 3);
            if (r0 < M)
                *(__half2*)(C + (size_t)r0 * N + col) =
                    __floats2half2_rn(d[mi][nj][0], d[mi][nj][1]);
            if (r0 + 8 < M)
                *(__half2*)(C + (size_t)(r0 + 8) * N + col) =
                    __floats2half2_rn(d[mi][nj][2], d[mi][nj][3]);
        }
    }
}

// ---------------- SpMM (fp16 gather, packed edges) + bias + leaky ----------
// HALF_OUT=true: writes fp16 activations (stride D). false: fp32 out.
template <int D, bool HALF_OUT>
__global__ __launch_bounds__(256) void spmm_kernel(const __half* __restrict__ sup,
                                                   const uint2* __restrict__ scv,
                                                   const int* __restrict__ rowptr,
                                                   const float* __restrict__ bias,
                                                   float* __restrict__ outf,
                                                   __half* __restrict__ outa,
                                                   int n) {
    int warp = (blockIdx.x * blockDim.x + threadIdx.x) >> 5;
    int lane = threadIdx.x & 31;
    if (warp >= n) return;
    int s = rowptr[warp];
    int e = rowptr[warp + 1];
    constexpr int VEC = D / 32;
    float acc[VEC];
    #pragma unroll
    for (int q = 0; q < VEC; q++) acc[q] = 0.f;

    const int lanecol = lane * VEC;

#define GATHER(cc, vv) do {                                                        \
        const __half* _b = sup + (size_t)(cc) * D + lanecol;                       \
        if (VEC == 8) {                                                            \
            uint4 _r = __ldg((const uint4*)_b);                                    \
            const __half2* _h = (const __half2*)&_r;                               \
            _Pragma("unroll")                                                      \
            for (int _q = 0; _q < 4; _q++) {                                       \
                float2 _f = __half22float2(_h[_q]);                                \
                acc[2 * _q]     += (vv) * _f.x;                                    \
                acc[2 * _q + 1] += (vv) * _f.y;                                    \
            }                                                                      \
        } else {                                                                   \
            uint2 _r = __ldg((const uint2*)_b);                                    \
            const __half2* _h = (const __half2*)&_r;                               \
            _Pragma("unroll")                                                      \
            for (int _q = 0; _q < 2; _q++) {                                       \
                float2 _f = __half22float2(_h[_q]);                                \
                acc[2 * _q]     += (vv) * _f.x;                                    \
                acc[2 * _q + 1] += (vv) * _f.y;                                    \
            }                                                                      \
        }                                                                          \
    } while (0)

    int p = s;
    for (; p + 3 < e; p += 4) {
        uint2 e0 = __ldg(&scv[p]),     e1 = __ldg(&scv[p + 1]);
        uint2 e2 = __ldg(&scv[p + 2]), e3 = __ldg(&scv[p + 3]);
        GATHER(e0.x, __uint_as_float(e0.y));
        GATHER(e1.x, __uint_as_float(e1.y));
        GATHER(e2.x, __uint_as_float(e2.y));
        GATHER(e3.x, __uint_as_float(e3.y));
    }
    for (; p < e; p++) {
        uint2 ee = __ldg(&scv[p]);
        GATHER(ee.x, __uint_as_float(ee.y));
    }
#undef GATHER

    float r[VEC];
    #pragma unroll
    for (int q = 0; q < VEC; q += 4) {
        float4 b = __ldg((const float4*)(bias + lanecol + q));
        r[q]     = acc[q]     + b.x;
        r[q + 1] = acc[q + 1] + b.y;
        r[q + 2] = acc[q + 2] + b.z;
        r[q + 3] = acc[q + 3] + b.w;
    }
    #pragma unroll
    for (int q = 0; q < VEC; q++) r[q] = (r[q] > 0.f) ? r[q] : GCN_SLOPE * r[q];

    if (HALF_OUT) {
        __half* rp = outa + (size_t)warp * D;
        #pragma unroll
        for (int q = 0; q < VEC; q += 2)
            *(__half2*)(rp + lanecol + q) = __floats2half2_rn(r[q], r[q + 1]);
    } else {
        float* o = outf + (size_t)warp * D + lanecol;
        #pragma unroll
        for (int q = 0; q < VEC; q += 4)
            *(float4*)(o + q) = make_float4(r[q], r[q + 1], r[q + 2], r[q + 3]);
    }
}

// ---------------- launch ----------------
extern "C" void kernel_launch(void* const* d_in, const int* in_sizes, int n_in,
                              void* d_out, int out_size) {
    const float* x    = (const float*)d_in[0];
    const int*   rows = (const int*)  d_in[1];
    const int*   cols = (const int*)  d_in[2];
    const float* vals = (const float*)d_in[3];
    const float* W1   = (const float*)d_in[4];
    const float* b1   = (const float*)d_in[5];
    const float* W2   = (const float*)d_in[6];
    const float* b2   = (const float*)d_in[7];
    const float* W3   = (const float*)d_in[8];
    const float* b3   = (const float*)d_in[9];
    float* out = (float*)d_out;

    const int N = GCN_N;
    const int NNZ = GCN_NNZ;

    int *rowptr, *cursor;
    uint2* scv;
    __half *sup, *ap, *bp;
    cudaGetSymbolAddress((void**)&rowptr, g_rowptr);
    cudaGetSymbolAddress((void**)&cursor, g_cursor);
    cudaGetSymbolAddress((void**)&scv,    g_scv);
    cudaGetSymbolAddress((void**)&sup,    g_sup);
    cudaGetSymbolAddress((void**)&ap,     g_a);
    cudaGetSymbolAddress((void**)&bp,     g_b);

    const int SMEM_GEMM  = 3 * (128 * 64 * 2) * 2;   // 96KB (gemm_mma)
    const int SMEM_FUSED = 75776;                    // gemm1_fused
    cudaFuncSetAttribute(gemm_mma,    cudaFuncAttributeMaxDynamicSharedMemorySize, SMEM_GEMM);
    cudaFuncSetAttribute(gemm1_fused, cudaFuncAttributeMaxDynamicSharedMemorySize, SMEM_FUSED);

    const int MT128 = (N + 127) / 128;   // 782
    const int MT64  = (N + 63) / 64;     // 1563
    int spmm_grid = (N + 7) / 8;

    // launches 1-3 (gemm1_fused must be 4th for the ncu capture slot)
    wsplit_single<<<(512 * 256 + 255) / 256, 256>>>(W1, bp, 512, 256);
    zero_kernel<<<(N + 255) / 256, 256>>>(cursor, N);
    hist_kernel<<<(NNZ + 255) / 256, 256>>>(rows, cursor, NNZ);

    // launch 4: fused layer-1 GEMM (fp32 x -> fp16 in-kernel)  <- ncu slot
    gemm1_fused<<<dim3(2, MT64), 256, SMEM_FUSED>>>(x, bp, sup, N);

    // CSR finish
    scan_kernel<<<1, 1024>>>(cursor, rowptr, cursor, N);
    scatter_kernel<<<(NNZ + 255) / 256, 256>>>(rows, cols, vals, cursor, scv, NNZ);

    // layer 1 SpMM -> h1 (fp16)
    spmm_kernel<256, true><<<spmm_grid, 256>>>(sup, scv, rowptr, b1, nullptr, ap, N);

    // layer 2: K=256, N=256
    wsplit_single<<<(256 * 256 + 255) / 256, 256>>>(W2, bp, 256, 256);
    gemm_mma<<<dim3(2, MT128), 256, SMEM_GEMM>>>(ap, bp, sup, N, 256, 256);
    spmm_kernel<256, true><<<spmm_grid, 256>>>(sup, scv, rowptr, b2, nullptr, ap, N);

    // layer 3: K=256, N=128 -> out (fp32)
    wsplit_single<<<(256 * 128 + 255) / 256, 256>>>(W3, bp, 256, 128);
    gemm_mma<<<dim3(1, MT128), 256, SMEM_GEMM>>>(ap, bp, sup, N, 128, 256);
    spmm_kernel<128, false><<<spmm_grid, 256>>>(sup, scv, rowptr, b3, out, nullptr, N);
}

// round 9
// speedup vs baseline: 3.3687x; 1.1344x over previous
#include <cuda_runtime.h>
#include <cuda_fp16.h>
#include <cstdint>

#define GCN_N     100000
#define GCN_NNZ   3200000
#define GCN_SLOPE 0.25f

// ---------------- device scratch (static, allocation-free) ----------------
__device__ __align__(16) int    g_rowptr[GCN_N + 1];
__device__ __align__(16) int    g_cursor[GCN_N];
__device__ __align__(16) int    g_cnt[GCN_N];
__device__ __align__(16) int    g_bsum[512];
__device__ __align__(16) uint2  g_scv[GCN_NNZ];                // packed (col, val)
__device__ __align__(16) __half g_sup [(size_t)GCN_N * 256];   // GEMM output fp16
__device__ __align__(16) __half g_a[(size_t)GCN_N * 256];      // activations fp16
__device__ __align__(16) __half g_b[256 * 512];                // weights fp16 [N,K]

// ---------------- CSR build ----------------
__global__ void zero_kernel(int* p, int n) {
    int i = blockIdx.x * blockDim.x + threadIdx.x;
    if (i < n) p[i] = 0;
}
__global__ void hist_kernel(const int* __restrict__ rows, int* __restrict__ counts, int nnz) {
    int i = blockIdx.x * blockDim.x + threadIdx.x;
    if (i < nnz) atomicAdd(&counts[rows[i]], 1);
}
// level A: per-block inclusive scan of counts; local incl -> rowptr[i+1], block total -> bsum
__global__ void scanA_kernel(const int* __restrict__ counts, int* __restrict__ rowptr,
                             int* __restrict__ bsum, int n) {
    __shared__ int ws[8];
    int i = blockIdx.x * 256 + threadIdx.x;
    int lane = threadIdx.x & 31, w = threadIdx.x >> 5;
    int v = (i < n) ? counts[i] : 0;
    int x = v;
    #pragma unroll
    for (int d = 1; d < 32; d <<= 1) {
        int y = __shfl_up_sync(0xffffffffu, x, d);
        if (lane >= d) x += y;
    }
    if (lane == 31) ws[w] = x;
    __syncthreads();
    if (w == 0) {
        int t = (lane < 8) ? ws[lane] : 0;
        #pragma unroll
        for (int d = 1; d < 8; d <<= 1) {
            int y = __shfl_up_sync(0xffffffffu, t, d);
            if (lane >= d) t += y;
        }
        if (lane < 8) ws[lane] = t;
    }
    __syncthreads();
    int incl = x + (w > 0 ? ws[w - 1] : 0);
    if (i < n) rowptr[i + 1] = incl;
    if (threadIdx.x == 255) bsum[blockIdx.x] = incl;
}
// level B: single block exclusive-scans block sums in place (nb <= 512)
__global__ void scanB_kernel(int* __restrict__ bsum, int nb) {
    __shared__ int ws[16];
    int i = threadIdx.x, lane = i & 31, w = i >> 5;
    int v = (i < nb) ? bsum[i] : 0;
    int x = v;
    #pragma unroll
    for (int d = 1; d < 32; d <<= 1) {
        int y = __shfl_up_sync(0xffffffffu, x, d);
        if (lane >= d) x += y;
    }
    if (lane == 31) ws[w] = x;
    __syncthreads();
    if (w == 0) {
        int t = (lane < 16) ? ws[lane] : 0;
        #pragma unroll
        for (int d = 1; d < 16; d <<= 1) {
            int y = __shfl_up_sync(0xffffffffu, t, d);
            if (lane >= d) t += y;
        }
        if (lane < 16) ws[lane] = t;
    }
    __syncthreads();
    int incl = x + (w > 0 ? ws[w - 1] : 0);
    if (i < nb) bsum[i] = incl - v;      // exclusive block offset
}
// level C: add offsets; finalize rowptr and cursor
__global__ void scanC_kernel(const int* __restrict__ counts, const int* __restrict__ bsum,
                             int* __restrict__ rowptr, int* __restrict__ cursor, int n) {
    int i = blockIdx.x * 256 + threadIdx.x;
    if (i < n) {
        int incl = rowptr[i + 1] + bsum[blockIdx.x];
        rowptr[i + 1] = incl;
        cursor[i] = incl - counts[i];
    }
    if (i == 0) rowptr[0] = 0;
}
__global__ void scatter_kernel(const int* __restrict__ rows, const int* __restrict__ cols,
                               const float* __restrict__ vals, int* __restrict__ cursor,
                               uint2* __restrict__ scv, int nnz) {
    int i = blockIdx.x * blockDim.x + threadIdx.x;
    if (i < nnz) {
        int r = rows[i];
        int pos = atomicAdd(&cursor[r], 1);
        scv[pos] = make_uint2((unsigned)cols[i], __float_as_uint(vals[i]));
    }
}

// W[K,N] -> B[n,k] fp16 (transpose)
__global__ void wsplit_single(const float* __restrict__ W, __half* __restrict__ bp,
                              int K, int N) {
    int idx = blockIdx.x * blockDim.x + threadIdx.x;
    if (idx >= K * N) return;
    int k = idx / N, n = idx % N;
    bp[(size_t)n * K + k] = __float2half_rn(W[idx]);
}

// ---------------- layer-1 fused GEMM: C = fp16(x) @ Wh^T -------------------
// x fp32 [M,512] loaded straight to registers, converted, STS'd as fp16.
// BM=64, BN=128, chunk=64 cols, B 2-stage cp.async, 256 threads, warp 32x32.
__global__ __launch_bounds__(256, 2) void gemm1_fused(const float* __restrict__ X,
                                                      const __half* __restrict__ B,
                                                      __half* __restrict__ C, int M) {
    extern __shared__ char smem[];
    constexpr int OFF_HI = 0;                 // 64 x 128B = 8192
    constexpr int OFF_B  = 8192;
    constexpr int BST    = 128 * 128;         // 16384 per stage
    // total = 8192 + 2*16384 = 40960

    uint32_t sbase;
    asm("{ .reg .u64 t; cvta.to.shared.u64 t, %1; cvt.u32.u64 %0, t; }" : "=r"(sbase) : "l"(smem));

    int tid = threadIdx.x;
    int wid = tid >> 5, lane = tid & 31;
    int wm = wid & 1, wn = wid >> 1;          // 2 x 4 warp grid, warp tile 32x32
    int m0 = blockIdx.y * 64, n0 = blockIdx.x * 128;

    float d[2][4][4];
    #pragma unroll
    for (int mi = 0; mi < 2; mi++)
        #pragma unroll
        for (int nj = 0; nj < 4; nj++)
            #pragma unroll
            for (int q = 0; q < 4; q++) d[mi][nj][q] = 0.f;

    const float*  Xbase = X + (size_t)m0 * 512;
    const __half* Bbase = B + (size_t)n0 * 512;

    // X register staging: thread covers row (tid>>2), fp32 cols [q*16, q*16+16)
    const int xr_row = tid >> 2, xr_q = tid & 3;
    const float* xsrc_row = (m0 + xr_row < M) ? (Xbase + (size_t)xr_row * 512) : Xbase;
    float4 xr[4];

#define LOAD_XREG(ch) do {                                                          \
        const float4* _s = (const float4*)(xsrc_row + (ch) * 64 + xr_q * 16);       \
        xr[0] = __ldg(_s); xr[1] = __ldg(_s + 1);                                   \
        xr[2] = __ldg(_s + 2); xr[3] = __ldg(_s + 3);                               \
    } while (0)
#define STS_HI() do {                                                               \
        __half2 _h[8];                                                              \
        _h[0] = __floats2half2_rn(xr[0].x, xr[0].y);                                \
        _h[1] = __floats2half2_rn(xr[0].z, xr[0].w);                                \
        _h[2] = __floats2half2_rn(xr[1].x, xr[1].y);                                \
        _h[3] = __floats2half2_rn(xr[1].z, xr[1].w);                                \
        _h[4] = __floats2half2_rn(xr[2].x, xr[2].y);                                \
        _h[5] = __floats2half2_rn(xr[2].z, xr[2].w);                                \
        _h[6] = __floats2half2_rn(xr[3].x, xr[3].y);                                \
        _h[7] = __floats2half2_rn(xr[3].z, xr[3].w);                                \
        uint32_t _o0 = (uint32_t)(xr_row * 128 + xr_q * 32);                        \
        uint32_t _o1 = _o0 + 16;                                                    \
        _o0 ^= ((_o0 >> 3) & 0x70); _o1 ^= ((_o1 >> 3) & 0x70);                     \
        *(uint4*)(smem + OFF_HI + _o0) = *(uint4*)&_h[0];                           \
        *(uint4*)(smem + OFF_HI + _o1) = *(uint4*)&_h[4];                           \
    } while (0)
#define LOAD_B(st, ch) do {                                                         \
        uint32_t _db = sbase + OFF_B + (st) * BST;                                  \
        _Pragma("unroll")                                                           \
        for (int _i = 0; _i < 4; _i++) {                                            \
            int _u = tid + _i * 256;                                                \
            int _r = _u >> 3, _c = _u & 7;                                          \
            uint32_t _off = (uint32_t)(_r * 128 + _c * 16);                         \
            _off ^= ((_off >> 3) & 0x70);                                           \
            const __half* _src = Bbase + (size_t)_r * 512 + (ch) * 64 + _c * 8;     \
            asm volatile("cp.async.cg.shared.global [%0], [%1], 16;"                \
                :: "r"(_db + _off), "l"(_src));                                     \
        }                                                                           \
    } while (0)

    LOAD_XREG(0);
    LOAD_B(0, 0);
    asm volatile("cp.async.commit_group;");
    LOAD_B(1, 1);
    asm volatile("cp.async.commit_group;");

    for (int c = 0; c < 8; c++) {
        STS_HI();                                  // hi(c) from regs
        asm volatile("cp.async.wait_group 1;");    // B(c) arrived
        __syncthreads();
        if (c + 1 < 8) LOAD_XREG(c + 1);           // hide LDG behind MMA

        uint32_t da = sbase + OFF_HI;
        uint32_t db = sbase + OFF_B + (c & 1) * BST;
        #pragma unroll
        for (int kk = 0; kk < 4; kk++) {
            int k16 = kk * 16;
            uint32_t a[2][4];
            #pragma unroll
            for (int mi = 0; mi < 2; mi++) {
                int row = wm * 32 + mi * 16 + (lane & 15);
                int colB = (k16 + ((lane >> 4) << 3)) * 2;
                uint32_t off = (uint32_t)(row * 128 + colB);
                off ^= ((off >> 3) & 0x70);
                asm volatile("ldmatrix.sync.aligned.m8n8.x4.shared.b16 {%0,%1,%2,%3}, [%4];"
                    : "=r"(a[mi][0]), "=r"(a[mi][1]), "=r"(a[mi][2]), "=r"(a[mi][3])
                    : "r"(da + off));
            }
            uint32_t b[4][2];
            #pragma unroll
            for (int nj = 0; nj < 2; nj++) {
                int nrow = wn * 32 + nj * 16 + (lane & 7) + ((lane >> 4) << 3);
                int colB = (k16 + (((lane >> 3) & 1) << 3)) * 2;
                uint32_t off = (uint32_t)(nrow * 128 + colB);
                off ^= ((off >> 3) & 0x70);
                uint32_t r0, r1, r2, r3;
                asm volatile("ldmatrix.sync.aligned.m8n8.x4.shared.b16 {%0,%1,%2,%3}, [%4];"
                    : "=r"(r0), "=r"(r1), "=r"(r2), "=r"(r3) : "r"(db + off));
                b[nj * 2][0] = r0; b[nj * 2][1] = r1;
                b[nj * 2 + 1][0] = r2; b[nj * 2 + 1][1] = r3;
            }
            #pragma unroll
            for (int mi = 0; mi < 2; mi++)
                #pragma unroll
                for (int nj = 0; nj < 4; nj++)
                    asm volatile("mma.sync.aligned.m16n8k16.row.col.f32.f16.f16.f32 "
                        "{%0,%1,%2,%3}, {%4,%5,%6,%7}, {%8,%9}, {%0,%1,%2,%3};"
                        : "+f"(d[mi][nj][0]), "+f"(d[mi][nj][1]),
                          "+f"(d[mi][nj][2]), "+f"(d[mi][nj][3])
                        : "r"(a[mi][0]), "r"(a[mi][1]), "r"(a[mi][2]), "r"(a[mi][3]),
                          "r"(b[nj][0]), "r"(b[nj][1]));
        }
        __syncthreads();                           // all reads of hi/B(c) done
        if (c + 2 < 8) LOAD_B(c & 1, c + 2);
        asm volatile("cp.async.commit_group;");
    }
#undef LOAD_XREG
#undef STS_HI
#undef LOAD_B

    #pragma unroll
    for (int mi = 0; mi < 2; mi++) {
        int r0 = m0 + wm * 32 + mi * 16 + (lane >> 2);
        #pragma unroll
        for (int nj = 0; nj < 4; nj++) {
            int col = n0 + wn * 32 + nj * 8 + 2 * (lane & 3);
            if (r0 < M)
                *(__half2*)(C + (size_t)r0 * 256 + col) =
                    __floats2half2_rn(d[mi][nj][0], d[mi][nj][1]);
            if (r0 + 8 < M)
                *(__half2*)(C + (size_t)(r0 + 8) * 256 + col) =
                    __floats2half2_rn(d[mi][nj][2], d[mi][nj][3]);
        }
    }
}

// ---------------- fp16 GEMM via mma.sync, cp.async (layers 2/3) ------------
__global__ __launch_bounds__(256) void gemm_mma(const __half* __restrict__ A,
                                                const __half* __restrict__ B,
                                                __half* __restrict__ C,
                                                int M, int N, int K) {
    extern __shared__ char smem[];
    constexpr int STAGES = 3;
    constexpr int ABYTES = 128 * 64 * 2;
    constexpr int BBYTES = 128 * 64 * 2;
    uint32_t sa_base;
    asm("{ .reg .u64 t; cvta.to.shared.u64 t, %1; cvt.u32.u64 %0, t; }" : "=r"(sa_base) : "l"(smem));
    uint32_t sb_base = sa_base + STAGES * ABYTES;

    int tid = threadIdx.x;
    int wid = tid >> 5, lane = tid & 31;
    int wm = wid & 3, wn = wid >> 2;
    int m0 = blockIdx.y * 128, n0 = blockIdx.x * 128;
    int NC = K / 64;

    float d[2][8][4];
    #pragma unroll
    for (int mi = 0; mi < 2; mi++)
        #pragma unroll
        for (int nj = 0; nj < 8; nj++)
            #pragma unroll
            for (int q = 0; q < 4; q++) d[mi][nj][q] = 0.f;

    const __half* Abase = A + (size_t)m0 * K;
    const __half* Bbase = B + (size_t)n0 * K;

#define LOAD_STAGE(st, ch) do {                                                   \
        uint32_t _da = sa_base + (st) * ABYTES;                                   \
        uint32_t _db = sb_base + (st) * BBYTES;                                   \
        int _k0 = (ch) * 64;                                                      \
        _Pragma("unroll")                                                         \
        for (int _i = 0; _i < 4; _i++) {                                          \
            int _u = tid + _i * 256;                                              \
            int _r = _u >> 3, _c = _u & 7;                                        \
            uint32_t _off = (uint32_t)(_r * 128 + _c * 16);                       \
            _off ^= ((_off >> 3) & 0x70);                                         \
            const __half* _src = Abase + (size_t)_r * K + _k0 + _c * 8;           \
            uint32_t _sz = (m0 + _r < M) ? 16u : 0u;                              \
            if (m0 + _r >= M) _src = Abase + _k0;                                 \
            asm volatile("cp.async.cg.shared.global [%0], [%1], 16, %2;"          \
                :: "r"(_da + _off), "l"(_src), "r"(_sz));                         \
        }                                                                         \
        _Pragma("unroll")                                                         \
        for (int _i = 0; _i < 4; _i++) {                                          \
            int _u = tid + _i * 256;                                              \
            int _r = _u >> 3, _c = _u & 7;                                        \
            uint32_t _off = (uint32_t)(_r * 128 + _c * 16);                       \
            _off ^= ((_off >> 3) & 0x70);                                         \
            const __half* _src = Bbase + (size_t)_r * K + _k0 + _c * 8;           \
            asm volatile("cp.async.cg.shared.global [%0], [%1], 16;"              \
                :: "r"(_db + _off), "l"(_src));                                   \
        }                                                                         \
    } while (0)

    LOAD_STAGE(0, 0);
    asm volatile("cp.async.commit_group;");
    if (NC > 1) LOAD_STAGE(1, 1);
    asm volatile("cp.async.commit_group;");

    for (int c = 0; c < NC; c++) {
        asm volatile("cp.async.wait_group 1;");
        __syncthreads();
        if (c + 2 < NC) LOAD_STAGE((c + 2) % STAGES, c + 2);
        asm volatile("cp.async.commit_group;");

        uint32_t da = sa_base + (c % STAGES) * ABYTES;
        uint32_t db = sb_base + (c % STAGES) * BBYTES;
        #pragma unroll
        for (int kk = 0; kk < 4; kk++) {
            int k16 = kk * 16;
            uint32_t a[2][4];
            #pragma unroll
            for (int mi = 0; mi < 2; mi++) {
                int row = wm * 32 + mi * 16 + (lane & 15);
                int colB = (k16 + ((lane >> 4) << 3)) * 2;
                uint32_t off = (uint32_t)(row * 128 + colB);
                off ^= ((off >> 3) & 0x70);
                asm volatile("ldmatrix.sync.aligned.m8n8.x4.shared.b16 {%0,%1,%2,%3}, [%4];"
                    : "=r"(a[mi][0]), "=r"(a[mi][1]), "=r"(a[mi][2]), "=r"(a[mi][3])
                    : "r"(da + off));
            }
            uint32_t b[8][2];
            #pragma unroll
            for (int nj = 0; nj < 4; nj++) {
                int nrow = wn * 64 + nj * 16 + (lane & 7) + ((lane >> 4) << 3);
                int colB = (k16 + (((lane >> 3) & 1) << 3)) * 2;
                uint32_t off = (uint32_t)(nrow * 128 + colB);
                off ^= ((off >> 3) & 0x70);
                uint32_t r0, r1, r2, r3;
                asm volatile("ldmatrix.sync.aligned.m8n8.x4.shared.b16 {%0,%1,%2,%3}, [%4];"
                    : "=r"(r0), "=r"(r1), "=r"(r2), "=r"(r3) : "r"(db + off));
                b[nj * 2][0] = r0; b[nj * 2][1] = r1;
                b[nj * 2 + 1][0] = r2; b[nj * 2 + 1][1] = r3;
            }
            #pragma unroll
            for (int mi = 0; mi < 2; mi++)
                #pragma unroll
                for (int nj = 0; nj < 8; nj++)
                    asm volatile("mma.sync.aligned.m16n8k16.row.col.f32.f16.f16.f32 "
                        "{%0,%1,%2,%3}, {%4,%5,%6,%7}, {%8,%9}, {%0,%1,%2,%3};"
                        : "+f"(d[mi][nj][0]), "+f"(d[mi][nj][1]),
                          "+f"(d[mi][nj][2]), "+f"(d[mi][nj][3])
                        : "r"(a[mi][0]), "r"(a[mi][1]), "r"(a[mi][2]), "r"(a[mi][3]),
                          "r"(b[nj][0]), "r"(b[nj][1]));
        }
        __syncthreads();
    }
#undef LOAD_STAGE

    #pragma unroll
    for (int mi = 0; mi < 2; mi++) {
        int r0 = m0 + wm * 32 + mi * 16 + (lane >> 2);
        #pragma unroll
        for (int nj = 0; nj < 8; nj++) {
            int col = n0 + wn * 64 + nj * 8 + 2 * (lane & 3);
            if (r0 < M)
                *(__half2*)(C + (size_t)r0 * N + col) =
                    __floats2half2_rn(d[mi][nj][0], d[mi][nj][1]);
            if (r0 + 8 < M)
                *(__half2*)(C + (size_t)(r0 + 8) * N + col) =
                    __floats2half2_rn(d[mi][nj][2], d[mi][nj][3]);
        }
    }
}

// ---------------- SpMM (fp16 gather, packed edges) + bias + leaky ----------
template <int D, bool HALF_OUT>
__global__ __launch_bounds__(256) void spmm_kernel(const __half* __restrict__ sup,
                                                   const uint2* __restrict__ scv,
                                                   const int* __restrict__ rowptr,
                                                   const float* __restrict__ bias,
                                                   float* __restrict__ outf,
                                                   __half* __restrict__ outa,
                                                   int n) {
    int warp = (blockIdx.x * blockDim.x + threadIdx.x) >> 5;
    int lane = threadIdx.x & 31;
    if (warp >= n) return;
    int s = rowptr[warp];
    int e = rowptr[warp + 1];
    constexpr int VEC = D / 32;
    float acc[VEC];
    #pragma unroll
    for (int q = 0; q < VEC; q++) acc[q] = 0.f;

    const int lanecol = lane * VEC;

#define GATHER(cc, vv) do {                                                        \
        const __half* _b = sup + (size_t)(cc) * D + lanecol;                       \
        if (VEC == 8) {                                                            \
            uint4 _r = __ldg((const uint4*)_b);                                    \
            const __half2* _h = (const __half2*)&_r;                               \
            _Pragma("unroll")                                                      \
            for (int _q = 0; _q < 4; _q++) {                                       \
                float2 _f = __half22float2(_h[_q]);                                \
                acc[2 * _q]     += (vv) * _f.x;                                    \
                acc[2 * _q + 1] += (vv) * _f.y;                                    \
            }                                                                      \
        } else {                                                                   \
            uint2 _r = __ldg((const uint2*)_b);                                    \
            const __half2* _h = (const __half2*)&_r;                               \
            _Pragma("unroll")                                                      \
            for (int _q = 0; _q < 2; _q++) {                                       \
                float2 _f = __half22float2(_h[_q]);                                \
                acc[2 * _q]     += (vv) * _f.x;                                    \
                acc[2 * _q + 1] += (vv) * _f.y;                                    \
            }                                                                      \
        }                                                                          \
    } while (0)

    int p = s;
    for (; p + 3 < e; p += 4) {
        uint2 e0 = __ldg(&scv[p]),     e1 = __ldg(&scv[p + 1]);
        uint2 e2 = __ldg(&scv[p + 2]), e3 = __ldg(&scv[p + 3]);
        GATHER(e0.x, __uint_as_float(e0.y));
        GATHER(e1.x, __uint_as_float(e1.y));
        GATHER(e2.x, __uint_as_float(e2.y));
        GATHER(e3.x, __uint_as_float(e3.y));
    }
    for (; p < e; p++) {
        uint2 ee = __ldg(&scv[p]);
        GATHER(ee.x, __uint_as_float(ee.y));
    }
#undef GATHER

    float r[VEC];
    #pragma unroll
    for (int q = 0; q < VEC; q += 4) {
        float4 b = __ldg((const float4*)(bias + lanecol + q));
        r[q]     = acc[q]     + b.x;
        r[q + 1] = acc[q + 1] + b.y;
        r[q + 2] = acc[q + 2] + b.z;
        r[q + 3] = acc[q + 3] + b.w;
    }
    #pragma unroll
    for (int q = 0; q < VEC; q++) r[q] = (r[q] > 0.f) ? r[q] : GCN_SLOPE * r[q];

    if (HALF_OUT) {
        __half* rp = outa + (size_t)warp * D;
        #pragma unroll
        for (int q = 0; q < VEC; q += 2)
            *(__half2*)(rp + lanecol + q) = __floats2half2_rn(r[q], r[q + 1]);
    } else {
        float* o = outf + (size_t)warp * D + lanecol;
        #pragma unroll
        for (int q = 0; q < VEC; q += 4)
            *(float4*)(o + q) = make_float4(r[q], r[q + 1], r[q + 2], r[q + 3]);
    }
}

// ---------------- launch ----------------
extern "C" void kernel_launch(void* const* d_in, const int* in_sizes, int n_in,
                              void* d_out, int out_size) {
    const float* x    = (const float*)d_in[0];
    const int*   rows = (const int*)  d_in[1];
    const int*   cols = (const int*)  d_in[2];
    const float* vals = (const float*)d_in[3];
    const float* W1   = (const float*)d_in[4];
    const float* b1   = (const float*)d_in[5];
    const float* W2   = (const float*)d_in[6];
    const float* b2   = (const float*)d_in[7];
    const float* W3   = (const float*)d_in[8];
    const float* b3   = (const float*)d_in[9];
    float* out = (float*)d_out;

    const int N = GCN_N;
    const int NNZ = GCN_NNZ;
    const int NBLK = (N + 255) / 256;   // 391

    int *rowptr, *cursor, *cnt, *bsum;
    uint2* scv;
    __half *sup, *ap, *bp;
    cudaGetSymbolAddress((void**)&rowptr, g_rowptr);
    cudaGetSymbolAddress((void**)&cursor, g_cursor);
    cudaGetSymbolAddress((void**)&cnt,    g_cnt);
    cudaGetSymbolAddress((void**)&bsum,   g_bsum);
    cudaGetSymbolAddress((void**)&scv,    g_scv);
    cudaGetSymbolAddress((void**)&sup,    g_sup);
    cudaGetSymbolAddress((void**)&ap,     g_a);
    cudaGetSymbolAddress((void**)&bp,     g_b);

    const int SMEM_GEMM  = 3 * (128 * 64 * 2) * 2;   // 96KB (gemm_mma)
    const int SMEM_FUSED = 40960;                    // gemm1_fused
    cudaFuncSetAttribute(gemm_mma,    cudaFuncAttributeMaxDynamicSharedMemorySize, SMEM_GEMM);
    cudaFuncSetAttribute(gemm1_fused, cudaFuncAttributeMaxDynamicSharedMemorySize, SMEM_FUSED);

    const int MT128 = (N + 127) / 128;   // 782
    const int MT64  = (N + 63) / 64;     // 1563
    int spmm_grid = (N + 7) / 8;

    // launches 1-3 (gemm1_fused must be 4th for the ncu capture slot)
    wsplit_single<<<(512 * 256 + 255) / 256, 256>>>(W1, bp, 512, 256);
    zero_kernel<<<NBLK, 256>>>(cnt, N);
    hist_kernel<<<(NNZ + 255) / 256, 256>>>(rows, cnt, NNZ);

    // launch 4: fused layer-1 GEMM  <- ncu capture slot
    gemm1_fused<<<dim3(2, MT64), 256, SMEM_FUSED>>>(x, bp, sup, N);

    // CSR finish: 3-level scan + scatter
    scanA_kernel<<<NBLK, 256>>>(cnt, rowptr, bsum, N);
    scanB_kernel<<<1, 512>>>(bsum, NBLK);
    scanC_kernel<<<NBLK, 256>>>(cnt, bsum, rowptr, cursor, N);
    scatter_kernel<<<(NNZ + 255) / 256, 256>>>(rows, cols, vals, cursor, scv, NNZ);

    // layer 1 SpMM -> h1 (fp16)
    spmm_kernel<256, true><<<spmm_grid, 256>>>(sup, scv, rowptr, b1, nullptr, ap, N);

    // layer 2: K=256, N=256
    wsplit_single<<<(256 * 256 + 255) / 256, 256>>>(W2, bp, 256, 256);
    gemm_mma<<<dim3(2, MT128), 256, SMEM_GEMM>>>(ap, bp, sup, N, 256, 256);
    spmm_kernel<256, true><<<spmm_grid, 256>>>(sup, scv, rowptr, b2, nullptr, ap, N);

    // layer 3: K=256, N=128 -> out (fp32)
    wsplit_single<<<(256 * 128 + 255) / 256, 256>>>(W3, bp, 256, 128);
    gemm_mma<<<dim3(1, MT128), 256, SMEM_GEMM>>>(ap, bp, sup, N, 128, 256);
    spmm_kernel<128, false><<<spmm_grid, 256>>>(sup, scv, rowptr, b3, out, nullptr, N);
}

// round 10
// speedup vs baseline: 3.4565x; 1.0261x over previous
#include <cuda_runtime.h>
#include <cuda_fp16.h>
#include <cstdint>

#define GCN_N     100000
#define GCN_NNZ   3200000
#define GCN_SLOPE 0.25f

// ---------------- device scratch (static, allocation-free) ----------------
__device__ __align__(16) int    g_rowptr[GCN_N + 1];
__device__ __align__(16) int    g_cursor[GCN_N];
__device__ __align__(16) int    g_cnt[GCN_N];
__device__ __align__(16) int    g_bsum[512];
__device__ __align__(16) uint2  g_scv[GCN_NNZ];                // packed (col, val)
__device__ __align__(16) __half g_sup [(size_t)GCN_N * 256];   // GEMM output fp16
__device__ __align__(16) __half g_a[(size_t)GCN_N * 512];      // activations fp16 (xh / h)
__device__ __align__(16) __half g_b[256 * 512];                // weights fp16 [N,K]

// ---------------- CSR build ----------------
__global__ void zero_kernel(int* p, int n) {
    int i = blockIdx.x * blockDim.x + threadIdx.x;
    if (i < n) p[i] = 0;
}
__global__ void hist_kernel(const int* __restrict__ rows, int* __restrict__ counts, int nnz) {
    int i = blockIdx.x * blockDim.x + threadIdx.x;
    if (i < nnz) atomicAdd(&counts[rows[i]], 1);
}
// level A: per-block inclusive scan of counts
__global__ void scanA_kernel(const int* __restrict__ counts, int* __restrict__ rowptr,
                             int* __restrict__ bsum, int n) {
    __shared__ int ws[8];
    int i = blockIdx.x * 256 + threadIdx.x;
    int lane = threadIdx.x & 31, w = threadIdx.x >> 5;
    int v = (i < n) ? counts[i] : 0;
    int x = v;
    #pragma unroll
    for (int d = 1; d < 32; d <<= 1) {
        int y = __shfl_up_sync(0xffffffffu, x, d);
        if (lane >= d) x += y;
    }
    if (lane == 31) ws[w] = x;
    __syncthreads();
    if (w == 0) {
        int t = (lane < 8) ? ws[lane] : 0;
        #pragma unroll
        for (int d = 1; d < 8; d <<= 1) {
            int y = __shfl_up_sync(0xffffffffu, t, d);
            if (lane >= d) t += y;
        }
        if (lane < 8) ws[lane] = t;
    }
    __syncthreads();
    int incl = x + (w > 0 ? ws[w - 1] : 0);
    if (i < n) rowptr[i + 1] = incl;
    if (threadIdx.x == 255) bsum[blockIdx.x] = incl;
}
__global__ void scanB_kernel(int* __restrict__ bsum, int nb) {
    __shared__ int ws[16];
    int i = threadIdx.x, lane = i & 31, w = i >> 5;
    int v = (i < nb) ? bsum[i] : 0;
    int x = v;
    #pragma unroll
    for (int d = 1; d < 32; d <<= 1) {
        int y = __shfl_up_sync(0xffffffffu, x, d);
        if (lane >= d) x += y;
    }
    if (lane == 31) ws[w] = x;
    __syncthreads();
    if (w == 0) {
        int t = (lane < 16) ? ws[lane] : 0;
        #pragma unroll
        for (int d = 1; d < 16; d <<= 1) {
            int y = __shfl_up_sync(0xffffffffu, t, d);
            if (lane >= d) t += y;
        }
        if (lane < 16) ws[lane] = t;
    }
    __syncthreads();
    int incl = x + (w > 0 ? ws[w - 1] : 0);
    if (i < nb) bsum[i] = incl - v;
}
__global__ void scanC_kernel(const int* __restrict__ counts, const int* __restrict__ bsum,
                             int* __restrict__ rowptr, int* __restrict__ cursor, int n) {
    int i = blockIdx.x * 256 + threadIdx.x;
    if (i < n) {
        int incl = rowptr[i + 1] + bsum[blockIdx.x];
        rowptr[i + 1] = incl;
        cursor[i] = incl - counts[i];
    }
    if (i == 0) rowptr[0] = 0;
}
__global__ void scatter_kernel(const int* __restrict__ rows, const int* __restrict__ cols,
                               const float* __restrict__ vals, int* __restrict__ cursor,
                               uint2* __restrict__ scv, int nnz) {
    int i = blockIdx.x * blockDim.x + threadIdx.x;
    if (i < nnz) {
        int r = rows[i];
        int pos = atomicAdd(&cursor[r], 1);
        scv[pos] = make_uint2((unsigned)cols[i], __float_as_uint(vals[i]));
    }
}

// x fp32 -> fp16 (plain cast, vectorized)
__global__ void convert_x(const float* __restrict__ in, __half* __restrict__ outh, int n4) {
    int i = blockIdx.x * blockDim.x + threadIdx.x;
    if (i >= n4) return;
    float4 v = __ldg((const float4*)in + i);
    __half2 h0 = __floats2half2_rn(v.x, v.y);
    __half2 h1 = __floats2half2_rn(v.z, v.w);
    ((__half2*)outh)[2 * i]     = h0;
    ((__half2*)outh)[2 * i + 1] = h1;
}

// W[K,N] -> B[n,k] fp16 (transpose)
__global__ void wsplit_single(const float* __restrict__ W, __half* __restrict__ bp,
                              int K, int N) {
    int idx = blockIdx.x * blockDim.x + threadIdx.x;
    if (idx >= K * N) return;
    int k = idx / N, n = idx % N;
    bp[(size_t)n * K + k] = __float2half_rn(W[idx]);
}

// ---------------- fp16 GEMM via mma.sync, cp.async -------------------------
// C[M,N] = A[M,K] @ B[N,K]^T ; fp16 out. BM=128, BN=128, BK=64, 3 stages.
__global__ __launch_bounds__(256) void gemm_mma(const __half* __restrict__ A,
                                                const __half* __restrict__ B,
                                                __half* __restrict__ C,
                                                int M, int N, int K) {
    extern __shared__ char smem[];
    constexpr int STAGES = 3;
    constexpr int ABYTES = 128 * 64 * 2;
    constexpr int BBYTES = 128 * 64 * 2;
    uint32_t sa_base;
    asm("{ .reg .u64 t; cvta.to.shared.u64 t, %1; cvt.u32.u64 %0, t; }" : "=r"(sa_base) : "l"(smem));
    uint32_t sb_base = sa_base + STAGES * ABYTES;

    int tid = threadIdx.x;
    int wid = tid >> 5, lane = tid & 31;
    int wm = wid & 3, wn = wid >> 2;
    int m0 = blockIdx.y * 128, n0 = blockIdx.x * 128;
    int NC = K / 64;

    float d[2][8][4];
    #pragma unroll
    for (int mi = 0; mi < 2; mi++)
        #pragma unroll
        for (int nj = 0; nj < 8; nj++)
            #pragma unroll
            for (int q = 0; q < 4; q++) d[mi][nj][q] = 0.f;

    const __half* Abase = A + (size_t)m0 * K;
    const __half* Bbase = B + (size_t)n0 * K;

#define LOAD_STAGE(st, ch) do {                                                   \
        uint32_t _da = sa_base + (st) * ABYTES;                                   \
        uint32_t _db = sb_base + (st) * BBYTES;                                   \
        int _k0 = (ch) * 64;                                                      \
        _Pragma("unroll")                                                         \
        for (int _i = 0; _i < 4; _i++) {                                          \
            int _u = tid + _i * 256;                                              \
            int _r = _u >> 3, _c = _u & 7;                                        \
            uint32_t _off = (uint32_t)(_r * 128 + _c * 16);                       \
            _off ^= ((_off >> 3) & 0x70);                                         \
            const __half* _src = Abase + (size_t)_r * K + _k0 + _c * 8;           \
            uint32_t _sz = (m0 + _r < M) ? 16u : 0u;                              \
            if (m0 + _r >= M) _src = Abase + _k0;                                 \
            asm volatile("cp.async.cg.shared.global [%0], [%1], 16, %2;"          \
                :: "r"(_da + _off), "l"(_src), "r"(_sz));                         \
        }                                                                         \
        _Pragma("unroll")                                                         \
        for (int _i = 0; _i < 4; _i++) {                                          \
            int _u = tid + _i * 256;                                              \
            int _r = _u >> 3, _c = _u & 7;                                        \
            uint32_t _off = (uint32_t)(_r * 128 + _c * 16);                       \
            _off ^= ((_off >> 3) & 0x70);                                         \
            const __half* _src = Bbase + (size_t)_r * K + _k0 + _c * 8;           \
            asm volatile("cp.async.cg.shared.global [%0], [%1], 16;"              \
                :: "r"(_db + _off), "l"(_src));                                   \
        }                                                                         \
    } while (0)

    LOAD_STAGE(0, 0);
    asm volatile("cp.async.commit_group;");
    if (NC > 1) LOAD_STAGE(1, 1);
    asm volatile("cp.async.commit_group;");

    for (int c = 0; c < NC; c++) {
        asm volatile("cp.async.wait_group 1;");
        __syncthreads();
        if (c + 2 < NC) LOAD_STAGE((c + 2) % STAGES, c + 2);
        asm volatile("cp.async.commit_group;");

        uint32_t da = sa_base + (c % STAGES) * ABYTES;
        uint32_t db = sb_base + (c % STAGES) * BBYTES;
        #pragma unroll
        for (int kk = 0; kk < 4; kk++) {
            int k16 = kk * 16;
            uint32_t a[2][4];
            #pragma unroll
            for (int mi = 0; mi < 2; mi++) {
                int row = wm * 32 + mi * 16 + (lane & 15);
                int colB = (k16 + ((lane >> 4) << 3)) * 2;
                uint32_t off = (uint32_t)(row * 128 + colB);
                off ^= ((off >> 3) & 0x70);
                asm volatile("ldmatrix.sync.aligned.m8n8.x4.shared.b16 {%0,%1,%2,%3}, [%4];"
                    : "=r"(a[mi][0]), "=r"(a[mi][1]), "=r"(a[mi][2]), "=r"(a[mi][3])
                    : "r"(da + off));
            }
            uint32_t b[8][2];
            #pragma unroll
            for (int nj = 0; nj < 4; nj++) {
                int nrow = wn * 64 + nj * 16 + (lane & 7) + ((lane >> 4) << 3);
                int colB = (k16 + (((lane >> 3) & 1) << 3)) * 2;
                uint32_t off = (uint32_t)(nrow * 128 + colB);
                off ^= ((off >> 3) & 0x70);
                uint32_t r0, r1, r2, r3;
                asm volatile("ldmatrix.sync.aligned.m8n8.x4.shared.b16 {%0,%1,%2,%3}, [%4];"
                    : "=r"(r0), "=r"(r1), "=r"(r2), "=r"(r3) : "r"(db + off));
                b[nj * 2][0] = r0; b[nj * 2][1] = r1;
                b[nj * 2 + 1][0] = r2; b[nj * 2 + 1][1] = r3;
            }
            #pragma unroll
            for (int mi = 0; mi < 2; mi++)
                #pragma unroll
                for (int nj = 0; nj < 8; nj++)
                    asm volatile("mma.sync.aligned.m16n8k16.row.col.f32.f16.f16.f32 "
                        "{%0,%1,%2,%3}, {%4,%5,%6,%7}, {%8,%9}, {%0,%1,%2,%3};"
                        : "+f"(d[mi][nj][0]), "+f"(d[mi][nj][1]),
                          "+f"(d[mi][nj][2]), "+f"(d[mi][nj][3])
                        : "r"(a[mi][0]), "r"(a[mi][1]), "r"(a[mi][2]), "r"(a[mi][3]),
                          "r"(b[nj][0]), "r"(b[nj][1]));
        }
        __syncthreads();
    }
#undef LOAD_STAGE

    #pragma unroll
    for (int mi = 0; mi < 2; mi++) {
        int r0 = m0 + wm * 32 + mi * 16 + (lane >> 2);
        #pragma unroll
        for (int nj = 0; nj < 8; nj++) {
            int col = n0 + wn * 64 + nj * 8 + 2 * (lane & 3);
            if (r0 < M)
                *(__half2*)(C + (size_t)r0 * N + col) =
                    __floats2half2_rn(d[mi][nj][0], d[mi][nj][1]);
            if (r0 + 8 < M)
                *(__half2*)(C + (size_t)(r0 + 8) * N + col) =
                    __floats2half2_rn(d[mi][nj][2], d[mi][nj][3]);
        }
    }
}

// ---------------- SpMM (fp16 gather, packed edges) + bias + leaky ----------
template <int D, bool HALF_OUT>
__global__ __launch_bounds__(256) void spmm_kernel(const __half* __restrict__ sup,
                                                   const uint2* __restrict__ scv,
                                                   const int* __restrict__ rowptr,
                                                   const float* __restrict__ bias,
                                                   float* __restrict__ outf,
                                                   __half* __restrict__ outa,
                                                   int n) {
    int warp = (blockIdx.x * blockDim.x + threadIdx.x) >> 5;
    int lane = threadIdx.x & 31;
    if (warp >= n) return;
    int s = rowptr[warp];
    int e = rowptr[warp + 1];
    constexpr int VEC = D / 32;
    float acc[VEC];
    #pragma unroll
    for (int q = 0; q < VEC; q++) acc[q] = 0.f;

    const int lanecol = lane * VEC;

#define GATHER(cc, vv) do {                                                        \
        const __half* _b = sup + (size_t)(cc) * D + lanecol;                       \
        if (VEC == 8) {                                                            \
            uint4 _r = __ldg((const uint4*)_b);                                    \
            const __half2* _h = (const __half2*)&_r;                               \
            _Pragma("unroll")                                                      \
            for (int _q = 0; _q < 4; _q++) {                                       \
                float2 _f = __half22float2(_h[_q]);                                \
                acc[2 * _q]     += (vv) * _f.x;                                    \
                acc[2 * _q + 1] += (vv) * _f.y;                                    \
            }                                                                      \
        } else {                                                                   \
            uint2 _r = __ldg((const uint2*)_b);                                    \
            const __half2* _h = (const __half2*)&_r;                               \
            _Pragma("unroll")                                                      \
            for (int _q = 0; _q < 2; _q++) {                                       \
                float2 _f = __half22float2(_h[_q]);                                \
                acc[2 * _q]     += (vv) * _f.x;                                    \
                acc[2 * _q + 1] += (vv) * _f.y;                                    \
            }                                                                      \
        }                                                                          \
    } while (0)

    int p = s;
    for (; p + 3 < e; p += 4) {
        uint2 e0 = __ldg(&scv[p]),     e1 = __ldg(&scv[p + 1]);
        uint2 e2 = __ldg(&scv[p + 2]), e3 = __ldg(&scv[p + 3]);
        GATHER(e0.x, __uint_as_float(e0.y));
        GATHER(e1.x, __uint_as_float(e1.y));
        GATHER(e2.x, __uint_as_float(e2.y));
        GATHER(e3.x, __uint_as_float(e3.y));
    }
    for (; p < e; p++) {
        uint2 ee = __ldg(&scv[p]);
        GATHER(ee.x, __uint_as_float(ee.y));
    }
#undef GATHER

    float r[VEC];
    #pragma unroll
    for (int q = 0; q < VEC; q += 4) {
        float4 b = __ldg((const float4*)(bias + lanecol + q));
        r[q]     = acc[q]     + b.x;
        r[q + 1] = acc[q + 1] + b.y;
        r[q + 2] = acc[q + 2] + b.z;
        r[q + 3] = acc[q + 3] + b.w;
    }
    #pragma unroll
    for (int q = 0; q < VEC; q++) r[q] = (r[q] > 0.f) ? r[q] : GCN_SLOPE * r[q];

    if (HALF_OUT) {
        __half* rp = outa + (size_t)warp * D;
        #pragma unroll
        for (int q = 0; q < VEC; q += 2)
            *(__half2*)(rp + lanecol + q) = __floats2half2_rn(r[q], r[q + 1]);
    } else {
        float* o = outf + (size_t)warp * D + lanecol;
        #pragma unroll
        for (int q = 0; q < VEC; q += 4)
            *(float4*)(o + q) = make_float4(r[q], r[q + 1], r[q + 2], r[q + 3]);
    }
}

// ---------------- launch ----------------
extern "C" void kernel_launch(void* const* d_in, const int* in_sizes, int n_in,
                              void* d_out, int out_size) {
    const float* x    = (const float*)d_in[0];
    const int*   rows = (const int*)  d_in[1];
    const int*   cols = (const int*)  d_in[2];
    const float* vals = (const float*)d_in[3];
    const float* W1   = (const float*)d_in[4];
    const float* b1   = (const float*)d_in[5];
    const float* W2   = (const float*)d_in[6];
    const float* b2   = (const float*)d_in[7];
    const float* W3   = (const float*)d_in[8];
    const float* b3   = (const float*)d_in[9];
    float* out = (float*)d_out;

    const int N = GCN_N;
    const int NNZ = GCN_NNZ;
    const int NBLK = (N + 255) / 256;   // 391

    int *rowptr, *cursor, *cnt, *bsum;
    uint2* scv;
    __half *sup, *ap, *bp;
    cudaGetSymbolAddress((void**)&rowptr, g_rowptr);
    cudaGetSymbolAddress((void**)&cursor, g_cursor);
    cudaGetSymbolAddress((void**)&cnt,    g_cnt);
    cudaGetSymbolAddress((void**)&bsum,   g_bsum);
    cudaGetSymbolAddress((void**)&scv,    g_scv);
    cudaGetSymbolAddress((void**)&sup,    g_sup);
    cudaGetSymbolAddress((void**)&ap,     g_a);
    cudaGetSymbolAddress((void**)&bp,     g_b);

    const int SMEM_GEMM = 3 * (128 * 64 * 2) * 2;   // 96KB
    cudaFuncSetAttribute(gemm_mma, cudaFuncAttributeMaxDynamicSharedMemorySize, SMEM_GEMM);

    const int MT128 = (N + 127) / 128;   // 782
    int spmm_grid = (N + 7) / 8;

    // launches 1-3 (gemm1 must be 4th for the ncu capture slot)
    wsplit_single<<<(512 * 256 + 255) / 256, 256>>>(W1, bp, 512, 256);
    convert_x<<<(N * 512 / 4 + 255) / 256, 256>>>(x, ap, N * 512 / 4);
    zero_kernel<<<NBLK, 256>>>(cnt, N);

    // launch 4: layer-1 GEMM (fp16 xh, K=512)  <- ncu capture slot
    gemm_mma<<<dim3(2, MT128), 256, SMEM_GEMM>>>(ap, bp, sup, N, 256, 512);

    // CSR build
    hist_kernel<<<(NNZ + 255) / 256, 256>>>(rows, cnt, NNZ);
    scanA_kernel<<<NBLK, 256>>>(cnt, rowptr, bsum, N);
    scanB_kernel<<<1, 512>>>(bsum, NBLK);
    scanC_kernel<<<NBLK, 256>>>(cnt, bsum, rowptr, cursor, N);
    scatter_kernel<<<(NNZ + 255) / 256, 256>>>(rows, cols, vals, cursor, scv, NNZ);

    // layer 1 SpMM -> h1 (fp16)
    spmm_kernel<256, true><<<spmm_grid, 256>>>(sup, scv, rowptr, b1, nullptr, ap, N);

    // layer 2: K=256, N=256
    wsplit_single<<<(256 * 256 + 255) / 256, 256>>>(W2, bp, 256, 256);
    gemm_mma<<<dim3(2, MT128), 256, SMEM_GEMM>>>(ap, bp, sup, N, 256, 256);
    spmm_kernel<256, true><<<spmm_grid, 256>>>(sup, scv, rowptr, b2, nullptr, ap, N);

    // layer 3: K=256, N=128 -> out (fp32)
    wsplit_single<<<(256 * 128 + 255) / 256, 256>>>(W3, bp, 256, 128);
    gemm_mma<<<dim3(1, MT128), 256, SMEM_GEMM>>>(ap, bp, sup, N, 128, 256);
    spmm_kernel<128, false><<<spmm_grid, 256>>>(sup, scv, rowptr, b3, out, nullptr, N);
}

// round 11
// speedup vs baseline: 3.5007x; 1.0128x over previous
#include <cuda_runtime.h>
#include <cuda_fp16.h>
#include <cstdint>

#define GCN_N     100000
#define GCN_NNZ   3200000
#define GCN_SLOPE 0.25f

// ---------------- device scratch (static, allocation-free) ----------------
__device__ __align__(16) int    g_rowptr[GCN_N + 1];
__device__ __align__(16) int    g_cursor[GCN_N];
__device__ __align__(16) int    g_cnt[GCN_N];
__device__ __align__(16) int    g_bsum[512];
__device__ __align__(16) uint2  g_scv[GCN_NNZ];                // packed (col, val)
__device__ __align__(16) __half g_sup [(size_t)GCN_N * 256];   // GEMM output fp16
__device__ __align__(16) __half g_a[(size_t)GCN_N * 512];      // activations fp16
__device__ __align__(16) __half g_b1[256 * 512];               // W1^T fp16
__device__ __align__(16) __half g_b2[256 * 256];               // W2^T fp16
__device__ __align__(16) __half g_b3[128 * 256];               // W3^T fp16

// ---------------- CSR build ----------------
__global__ void zero_kernel(int* p, int n) {
    int i = blockIdx.x * blockDim.x + threadIdx.x;
    if (i < n) p[i] = 0;
}
__global__ void hist_kernel(const int* __restrict__ rows, int* __restrict__ counts, int nnz) {
    int i = blockIdx.x * blockDim.x + threadIdx.x;
    if (i < nnz) atomicAdd(&counts[rows[i]], 1);
}
__global__ void scanA_kernel(const int* __restrict__ counts, int* __restrict__ rowptr,
                             int* __restrict__ bsum, int n) {
    __shared__ int ws[8];
    int i = blockIdx.x * 256 + threadIdx.x;
    int lane = threadIdx.x & 31, w = threadIdx.x >> 5;
    int v = (i < n) ? counts[i] : 0;
    int x = v;
    #pragma unroll
    for (int d = 1; d < 32; d <<= 1) {
        int y = __shfl_up_sync(0xffffffffu, x, d);
        if (lane >= d) x += y;
    }
    if (lane == 31) ws[w] = x;
    __syncthreads();
    if (w == 0) {
        int t = (lane < 8) ? ws[lane] : 0;
        #pragma unroll
        for (int d = 1; d < 8; d <<= 1) {
            int y = __shfl_up_sync(0xffffffffu, t, d);
            if (lane >= d) t += y;
        }
        if (lane < 8) ws[lane] = t;
    }
    __syncthreads();
    int incl = x + (w > 0 ? ws[w - 1] : 0);
    if (i < n) rowptr[i + 1] = incl;
    if (threadIdx.x == 255) bsum[blockIdx.x] = incl;
}
__global__ void scanB_kernel(int* __restrict__ bsum, int nb) {
    __shared__ int ws[16];
    int i = threadIdx.x, lane = i & 31, w = i >> 5;
    int v = (i < nb) ? bsum[i] : 0;
    int x = v;
    #pragma unroll
    for (int d = 1; d < 32; d <<= 1) {
        int y = __shfl_up_sync(0xffffffffu, x, d);
        if (lane >= d) x += y;
    }
    if (lane == 31) ws[w] = x;
    __syncthreads();
    if (w == 0) {
        int t = (lane < 16) ? ws[lane] : 0;
        #pragma unroll
        for (int d = 1; d < 16; d <<= 1) {
            int y = __shfl_up_sync(0xffffffffu, t, d);
            if (lane >= d) t += y;
        }
        if (lane < 16) ws[lane] = t;
    }
    __syncthreads();
    int incl = x + (w > 0 ? ws[w - 1] : 0);
    if (i < nb) bsum[i] = incl - v;
}
__global__ void scanC_kernel(const int* __restrict__ counts, const int* __restrict__ bsum,
                             int* __restrict__ rowptr, int* __restrict__ cursor, int n) {
    int i = blockIdx.x * 256 + threadIdx.x;
    if (i < n) {
        int incl = rowptr[i + 1] + bsum[blockIdx.x];
        rowptr[i + 1] = incl;
        cursor[i] = incl - counts[i];
    }
    if (i == 0) rowptr[0] = 0;
}
__global__ void scatter_kernel(const int* __restrict__ rows, const int* __restrict__ cols,
                               const float* __restrict__ vals, int* __restrict__ cursor,
                               uint2* __restrict__ scv, int nnz) {
    int i = blockIdx.x * blockDim.x + threadIdx.x;
    if (i < nnz) {
        int r = rows[i];
        int pos = atomicAdd(&cursor[r], 1);
        scv[pos] = make_uint2((unsigned)cols[i], __float_as_uint(vals[i]));
    }
}

// x fp32 -> fp16
__global__ void convert_x(const float* __restrict__ in, __half* __restrict__ outh, int n4) {
    int i = blockIdx.x * blockDim.x + threadIdx.x;
    if (i >= n4) return;
    float4 v = __ldg((const float4*)in + i);
    ((__half2*)outh)[2 * i]     = __floats2half2_rn(v.x, v.y);
    ((__half2*)outh)[2 * i + 1] = __floats2half2_rn(v.z, v.w);
}

// W[K,N] -> B[n,k] fp16 (transpose)
__global__ void wsplit_single(const float* __restrict__ W, __half* __restrict__ bp,
                              int K, int N) {
    int idx = blockIdx.x * blockDim.x + threadIdx.x;
    if (idx >= K * N) return;
    int k = idx / N, n = idx % N;
    bp[(size_t)n * K + k] = __float2half_rn(W[idx]);
}

// ---------------- fp16 GEMM via mma.sync, cp.async -------------------------
__global__ __launch_bounds__(256) void gemm_mma(const __half* __restrict__ A,
                                                const __half* __restrict__ B,
                                                __half* __restrict__ C,
                                                int M, int N, int K) {
    extern __shared__ char smem[];
    constexpr int STAGES = 3;
    constexpr int ABYTES = 128 * 64 * 2;
    constexpr int BBYTES = 128 * 64 * 2;
    uint32_t sa_base;
    asm("{ .reg .u64 t; cvta.to.shared.u64 t, %1; cvt.u32.u64 %0, t; }" : "=r"(sa_base) : "l"(smem));
    uint32_t sb_base = sa_base + STAGES * ABYTES;

    int tid = threadIdx.x;
    int wid = tid >> 5, lane = tid & 31;
    int wm = wid & 3, wn = wid >> 2;
    int m0 = blockIdx.y * 128, n0 = blockIdx.x * 128;
    int NC = K / 64;

    float d[2][8][4];
    #pragma unroll
    for (int mi = 0; mi < 2; mi++)
        #pragma unroll
        for (int nj = 0; nj < 8; nj++)
            #pragma unroll
            for (int q = 0; q < 4; q++) d[mi][nj][q] = 0.f;

    const __half* Abase = A + (size_t)m0 * K;
    const __half* Bbase = B + (size_t)n0 * K;

#define LOAD_STAGE(st, ch) do {                                                   \
        uint32_t _da = sa_base + (st) * ABYTES;                                   \
        uint32_t _db = sb_base + (st) * BBYTES;                                   \
        int _k0 = (ch) * 64;                                                      \
        _Pragma("unroll")                                                         \
        for (int _i = 0; _i < 4; _i++) {                                          \
            int _u = tid + _i * 256;                                              \
            int _r = _u >> 3, _c = _u & 7;                                        \
            uint32_t _off = (uint32_t)(_r * 128 + _c * 16);                       \
            _off ^= ((_off >> 3) & 0x70);                                         \
            const __half* _src = Abase + (size_t)_r * K + _k0 + _c * 8;           \
            uint32_t _sz = (m0 + _r < M) ? 16u : 0u;                              \
            if (m0 + _r >= M) _src = Abase + _k0;                                 \
            asm volatile("cp.async.cg.shared.global [%0], [%1], 16, %2;"          \
                :: "r"(_da + _off), "l"(_src), "r"(_sz));                         \
        }                                                                         \
        _Pragma("unroll")                                                         \
        for (int _i = 0; _i < 4; _i++) {                                          \
            int _u = tid + _i * 256;                                              \
            int _r = _u >> 3, _c = _u & 7;                                        \
            uint32_t _off = (uint32_t)(_r * 128 + _c * 16);                       \
            _off ^= ((_off >> 3) & 0x70);                                         \
            const __half* _src = Bbase + (size_t)_r * K + _k0 + _c * 8;           \
            asm volatile("cp.async.cg.shared.global [%0], [%1], 16;"              \
                :: "r"(_db + _off), "l"(_src));                                   \
        }                                                                         \
    } while (0)

    LOAD_STAGE(0, 0);
    asm volatile("cp.async.commit_group;");
    if (NC > 1) LOAD_STAGE(1, 1);
    asm volatile("cp.async.commit_group;");

    for (int c = 0; c < NC; c++) {
        asm volatile("cp.async.wait_group 1;");
        __syncthreads();
        if (c + 2 < NC) LOAD_STAGE((c + 2) % STAGES, c + 2);
        asm volatile("cp.async.commit_group;");

        uint32_t da = sa_base + (c % STAGES) * ABYTES;
        uint32_t db = sb_base + (c % STAGES) * BBYTES;
        #pragma unroll
        for (int kk = 0; kk < 4; kk++) {
            int k16 = kk * 16;
            uint32_t a[2][4];
            #pragma unroll
            for (int mi = 0; mi < 2; mi++) {
                int row = wm * 32 + mi * 16 + (lane & 15);
                int colB = (k16 + ((lane >> 4) << 3)) * 2;
                uint32_t off = (uint32_t)(row * 128 + colB);
                off ^= ((off >> 3) & 0x70);
                asm volatile("ldmatrix.sync.aligned.m8n8.x4.shared.b16 {%0,%1,%2,%3}, [%4];"
                    : "=r"(a[mi][0]), "=r"(a[mi][1]), "=r"(a[mi][2]), "=r"(a[mi][3])
                    : "r"(da + off));
            }
            uint32_t b[8][2];
            #pragma unroll
            for (int nj = 0; nj < 4; nj++) {
                int nrow = wn * 64 + nj * 16 + (lane & 7) + ((lane >> 4) << 3);
                int colB = (k16 + (((lane >> 3) & 1) << 3)) * 2;
                uint32_t off = (uint32_t)(nrow * 128 + colB);
                off ^= ((off >> 3) & 0x70);
                uint32_t r0, r1, r2, r3;
                asm volatile("ldmatrix.sync.aligned.m8n8.x4.shared.b16 {%0,%1,%2,%3}, [%4];"
                    : "=r"(r0), "=r"(r1), "=r"(r2), "=r"(r3) : "r"(db + off));
                b[nj * 2][0] = r0; b[nj * 2][1] = r1;
                b[nj * 2 + 1][0] = r2; b[nj * 2 + 1][1] = r3;
            }
            #pragma unroll
            for (int mi = 0; mi < 2; mi++)
                #pragma unroll
                for (int nj = 0; nj < 8; nj++)
                    asm volatile("mma.sync.aligned.m16n8k16.row.col.f32.f16.f16.f32 "
                        "{%0,%1,%2,%3}, {%4,%5,%6,%7}, {%8,%9}, {%0,%1,%2,%3};"
                        : "+f"(d[mi][nj][0]), "+f"(d[mi][nj][1]),
                          "+f"(d[mi][nj][2]), "+f"(d[mi][nj][3])
                        : "r"(a[mi][0]), "r"(a[mi][1]), "r"(a[mi][2]), "r"(a[mi][3]),
                          "r"(b[nj][0]), "r"(b[nj][1]));
        }
        __syncthreads();
    }
#undef LOAD_STAGE

    #pragma unroll
    for (int mi = 0; mi < 2; mi++) {
        int r0 = m0 + wm * 32 + mi * 16 + (lane >> 2);
        #pragma unroll
        for (int nj = 0; nj < 8; nj++) {
            int col = n0 + wn * 64 + nj * 8 + 2 * (lane & 3);
            if (r0 < M)
                *(__half2*)(C + (size_t)r0 * N + col) =
                    __floats2half2_rn(d[mi][nj][0], d[mi][nj][1]);
            if (r0 + 8 < M)
                *(__half2*)(C + (size_t)(r0 + 8) * N + col) =
                    __floats2half2_rn(d[mi][nj][2], d[mi][nj][3]);
        }
    }
}

// ---------------- SpMM (fp16 gather, packed edges) + bias + leaky ----------
template <int D, bool HALF_OUT>
__global__ __launch_bounds__(256) void spmm_kernel(const __half* __restrict__ sup,
                                                   const uint2* __restrict__ scv,
                                                   const int* __restrict__ rowptr,
                                                   const float* __restrict__ bias,
                                                   float* __restrict__ outf,
                                                   __half* __restrict__ outa,
                                                   int n) {
    int warp = (blockIdx.x * blockDim.x + threadIdx.x) >> 5;
    int lane = threadIdx.x & 31;
    if (warp >= n) return;
    int s = rowptr[warp];
    int e = rowptr[warp + 1];
    constexpr int VEC = D / 32;
    float acc[VEC];
    #pragma unroll
    for (int q = 0; q < VEC; q++) acc[q] = 0.f;

    const int lanecol = lane * VEC;

#define GATHER(cc, vv) do {                                                        \
        const __half* _b = sup + (size_t)(cc) * D + lanecol;                       \
        if (VEC == 8) {                                                            \
            uint4 _r = __ldg((const uint4*)_b);                                    \
            const __half2* _h = (const __half2*)&_r;                               \
            _Pragma("unroll")                                                      \
            for (int _q = 0; _q < 4; _q++) {                                       \
                float2 _f = __half22float2(_h[_q]);                                \
                acc[2 * _q]     += (vv) * _f.x;                                    \
                acc[2 * _q + 1] += (vv) * _f.y;                                    \
            }                                                                      \
        } else {                                                                   \
            uint2 _r = __ldg((const uint2*)_b);                                    \
            const __half2* _h = (const __half2*)&_r;                               \
            _Pragma("unroll")                                                      \
            for (int _q = 0; _q < 2; _q++) {                                       \
                float2 _f = __half22float2(_h[_q]);                                \
                acc[2 * _q]     += (vv) * _f.x;                                    \
                acc[2 * _q + 1] += (vv) * _f.y;                                    \
            }                                                                      \
        }                                                                          \
    } while (0)

    int p = s;
    for (; p + 3 < e; p += 4) {
        uint2 e0 = __ldg(&scv[p]),     e1 = __ldg(&scv[p + 1]);
        uint2 e2 = __ldg(&scv[p + 2]), e3 = __ldg(&scv[p + 3]);
        GATHER(e0.x, __uint_as_float(e0.y));
        GATHER(e1.x, __uint_as_float(e1.y));
        GATHER(e2.x, __uint_as_float(e2.y));
        GATHER(e3.x, __uint_as_float(e3.y));
    }
    for (; p < e; p++) {
        uint2 ee = __ldg(&scv[p]);
        GATHER(ee.x, __uint_as_float(ee.y));
    }
#undef GATHER

    float r[VEC];
    #pragma unroll
    for (int q = 0; q < VEC; q += 4) {
        float4 b = __ldg((const float4*)(bias + lanecol + q));
        r[q]     = acc[q]     + b.x;
        r[q + 1] = acc[q + 1] + b.y;
        r[q + 2] = acc[q + 2] + b.z;
        r[q + 3] = acc[q + 3] + b.w;
    }
    #pragma unroll
    for (int q = 0; q < VEC; q++) r[q] = (r[q] > 0.f) ? r[q] : GCN_SLOPE * r[q];

    if (HALF_OUT) {
        __half* rp = outa + (size_t)warp * D;
        #pragma unroll
        for (int q = 0; q < VEC; q += 2)
            *(__half2*)(rp + lanecol + q) = __floats2half2_rn(r[q], r[q + 1]);
    } else {
        float* o = outf + (size_t)warp * D + lanecol;
        #pragma unroll
        for (int q = 0; q < VEC; q += 4)
            *(float4*)(o + q) = make_float4(r[q], r[q + 1], r[q + 2], r[q + 3]);
    }
}

// ---------------- launch ----------------
extern "C" void kernel_launch(void* const* d_in, const int* in_sizes, int n_in,
                              void* d_out, int out_size) {
    const float* x    = (const float*)d_in[0];
    const int*   rows = (const int*)  d_in[1];
    const int*   cols = (const int*)  d_in[2];
    const float* vals = (const float*)d_in[3];
    const float* W1   = (const float*)d_in[4];
    const float* b1   = (const float*)d_in[5];
    const float* W2   = (const float*)d_in[6];
    const float* b2   = (const float*)d_in[7];
    const float* W3   = (const float*)d_in[8];
    const float* b3   = (const float*)d_in[9];
    float* out = (float*)d_out;

    const int N = GCN_N;
    const int NNZ = GCN_NNZ;
    const int NBLK = (N + 255) / 256;   // 391

    int *rowptr, *cursor, *cnt, *bsum;
    uint2* scv;
    __half *sup, *ap, *bp1, *bp2, *bp3;
    cudaGetSymbolAddress((void**)&rowptr, g_rowptr);
    cudaGetSymbolAddress((void**)&cursor, g_cursor);
    cudaGetSymbolAddress((void**)&cnt,    g_cnt);
    cudaGetSymbolAddress((void**)&bsum,   g_bsum);
    cudaGetSymbolAddress((void**)&scv,    g_scv);
    cudaGetSymbolAddress((void**)&sup,    g_sup);
    cudaGetSymbolAddress((void**)&ap,     g_a);
    cudaGetSymbolAddress((void**)&bp1,    g_b1);
    cudaGetSymbolAddress((void**)&bp2,    g_b2);
    cudaGetSymbolAddress((void**)&bp3,    g_b3);

    const int SMEM_GEMM = 3 * (128 * 64 * 2) * 2;   // 96KB
    cudaFuncSetAttribute(gemm_mma, cudaFuncAttributeMaxDynamicSharedMemorySize, SMEM_GEMM);

    // one-time host resources (identical captured work every call)
    static cudaStream_t s2 = nullptr;
    static cudaEvent_t e_fork = nullptr, e_csr = nullptr;
    if (s2 == nullptr) {
        cudaStreamCreateWithFlags(&s2, cudaStreamNonBlocking);
        cudaEventCreateWithFlags(&e_fork, cudaEventDisableTiming);
        cudaEventCreateWithFlags(&e_csr, cudaEventDisableTiming);
    }

    const int MT128 = (N + 127) / 128;   // 782
    int spmm_grid = (N + 7) / 8;

    // fork: CSR chain on side stream, GEMM path on main stream
    cudaEventRecord(e_fork, 0);
    cudaStreamWaitEvent(s2, e_fork, 0);

    // ---- side stream: CSR build ----
    zero_kernel<<<NBLK, 256, 0, s2>>>(cnt, N);
    hist_kernel<<<(NNZ + 255) / 256, 256, 0, s2>>>(rows, cnt, NNZ);
    scanA_kernel<<<NBLK, 256, 0, s2>>>(cnt, rowptr, bsum, N);
    scanB_kernel<<<1, 512, 0, s2>>>(bsum, NBLK);
    scanC_kernel<<<NBLK, 256, 0, s2>>>(cnt, bsum, rowptr, cursor, N);
    scatter_kernel<<<(NNZ + 255) / 256, 256, 0, s2>>>(rows, cols, vals, cursor, scv, NNZ);
    cudaEventRecord(e_csr, s2);

    // ---- main stream: conversions + layer-1 GEMM ----
    wsplit_single<<<(512 * 256 + 255) / 256, 256>>>(W1, bp1, 512, 256);
    convert_x<<<(N * 512 / 4 + 255) / 256, 256>>>(x, ap, N * 512 / 4);
    wsplit_single<<<(256 * 256 + 255) / 256, 256>>>(W2, bp2, 256, 256);
    wsplit_single<<<(256 * 128 + 255) / 256, 256>>>(W3, bp3, 256, 128);
    gemm_mma<<<dim3(2, MT128), 256, SMEM_GEMM>>>(ap, bp1, sup, N, 256, 512);

    // join: spmm1 needs CSR + gemm1
    cudaStreamWaitEvent(0, e_csr, 0);

    spmm_kernel<256, true><<<spmm_grid, 256>>>(sup, scv, rowptr, b1, nullptr, ap, N);

    gemm_mma<<<dim3(2, MT128), 256, SMEM_GEMM>>>(ap, bp2, sup, N, 256, 256);
    spmm_kernel<256, true><<<spmm_grid, 256>>>(sup, scv, rowptr, b2, nullptr, ap, N);

    gemm_mma<<<dim3(1, MT128), 256, SMEM_GEMM>>>(ap, bp3, sup, N, 128, 256);
    spmm_kernel<128, false><<<spmm_grid, 256>>>(sup, scv, rowptr, b3, out, nullptr, N);
}